// round 9
// baseline (speedup 1.0000x reference)
#include <cuda_runtime.h>
#include <cuda_bf16.h>
#include <cuda_fp16.h>
#include <cstdint>
#include <math.h>
#include <stddef.h>

// Problem constants
#define Bq 2
#define Tt 1024
#define Dd 768
#define Hh 12
#define Ll 6
#define Vv 50257
#define VP 50304
#define HS 64
#define Mm (Bq*Tt)
#define DFF (4*Dd)
#define NQKV (3*Dd)

// bf16x3 GEMM tiling
#define TM 128
#define TN 128
#define BK 32
#define SA_STRIDE 40
#define SB_STRIDE 136
#define OFF_AH 0
#define OFF_AL 10240
#define OFF_BH 20480
#define OFF_BL 29184
#define STAGE_BYTES 37888
#define GEMM_SMEM (2*STAGE_BYTES)

// lm_head GEMM tiling (fp16 single-pass, TM=256, 512 threads)
#define LM_TM 256
#define LM_TN 128
#define LM_OFF_A 0          // 256 rows x 80 B
#define LM_OFF_B 20480      // 32 rows x 272 B
#define LM_STAGE 29184
#define LM_SMEM 69632       // epilogue needs 256*68*4

// Flash attention tiling
#define FBM 64
#define FBN 64
#define FST_KH 0
#define FST_KL 9216
#define FST_VH 18432
#define FST_VL 27648
#define FSTAGE 36864
#define FLASH_SMEM (2*FSTAGE)

// ---------------- scratch --------------------------------------------------
__device__ float g_x  [Mm*Dd];
__device__ float g_tmp[Mm*Dd];

__device__ __nv_bfloat16 x_h [Mm*Dd],  x_l [Mm*Dd];
__device__ __half        x16 [Mm*Dd];
__device__ __nv_bfloat16 o_h [Mm*Dd],  o_l [Mm*Dd];
__device__ __nv_bfloat16 h1_h[(size_t)Mm*DFF], h1_l[(size_t)Mm*DFF];
__device__ __nv_bfloat16 qkvp_h[(size_t)Mm*NQKV], qkvp_l[(size_t)Mm*NQKV];

__device__ __nv_bfloat16 wqkv_h[(size_t)Ll*Dd*NQKV], wqkv_l[(size_t)Ll*Dd*NQKV];
__device__ __nv_bfloat16 wpr_h [(size_t)Ll*Dd*Dd],   wpr_l [(size_t)Ll*Dd*Dd];
__device__ __nv_bfloat16 w1b_h [(size_t)Ll*Dd*DFF],  w1b_l [(size_t)Ll*Dd*DFF];
__device__ __nv_bfloat16 w2b_h [(size_t)Ll*DFF*Dd],  w2b_l [(size_t)Ll*DFF*Dd];
__device__ __half        lmw16_h[(size_t)Dd*VP];

// ---------------- helpers --------------------------------------------------
__device__ __forceinline__ uint32_t s2u(const void* p) {
    uint32_t a;
    asm("{ .reg .u64 t; cvta.to.shared.u64 t, %1; cvt.u32.u64 %0, t; }" : "=r"(a) : "l"(p));
    return a;
}
__device__ __forceinline__ void cpa16(uint32_t dst, const void* src) {
    asm volatile("cp.async.cg.shared.global [%0], [%1], 16;" :: "r"(dst), "l"(src));
}
__device__ __forceinline__ void ldmx4(uint32_t* r, uint32_t addr) {
    asm volatile("ldmatrix.sync.aligned.m8n8.x4.shared.b16 {%0,%1,%2,%3},[%4];"
                 : "=r"(r[0]), "=r"(r[1]), "=r"(r[2]), "=r"(r[3]) : "r"(addr));
}
__device__ __forceinline__ void ldmx4t(uint32_t* r, uint32_t addr) {
    asm volatile("ldmatrix.sync.aligned.m8n8.x4.trans.shared.b16 {%0,%1,%2,%3},[%4];"
                 : "=r"(r[0]), "=r"(r[1]), "=r"(r[2]), "=r"(r[3]) : "r"(addr));
}
__device__ __forceinline__ void mma_bf16(float* c, const uint32_t* a,
                                         uint32_t b0, uint32_t b1) {
    asm volatile(
        "mma.sync.aligned.m16n8k16.row.col.f32.bf16.bf16.f32 "
        "{%0,%1,%2,%3},{%4,%5,%6,%7},{%8,%9},{%0,%1,%2,%3};"
        : "+f"(c[0]), "+f"(c[1]), "+f"(c[2]), "+f"(c[3])
        : "r"(a[0]), "r"(a[1]), "r"(a[2]), "r"(a[3]), "r"(b0), "r"(b1));
}
__device__ __forceinline__ void mma_f16(float* c, const uint32_t* a,
                                        uint32_t b0, uint32_t b1) {
    asm volatile(
        "mma.sync.aligned.m16n8k16.row.col.f32.f16.f16.f32 "
        "{%0,%1,%2,%3},{%4,%5,%6,%7},{%8,%9},{%0,%1,%2,%3};"
        : "+f"(c[0]), "+f"(c[1]), "+f"(c[2]), "+f"(c[3])
        : "r"(a[0]), "r"(a[1]), "r"(a[2]), "r"(a[3]), "r"(b0), "r"(b1));
}
__device__ __forceinline__ void splitv(float v, __nv_bfloat16& h, __nv_bfloat16& l) {
    h = __float2bfloat16_rn(v);
    l = __float2bfloat16_rn(v - __bfloat162float(h));
}
__device__ __forceinline__ uint32_t pk(__nv_bfloat16 a, __nv_bfloat16 b) {
    return ((uint32_t)__bfloat16_as_ushort(b) << 16) | __bfloat16_as_ushort(a);
}
__device__ __forceinline__ uint32_t pkh(__half a, __half b) {
    return ((uint32_t)__half_as_ushort(b) << 16) | __half_as_ushort(a);
}
__device__ __forceinline__ void split4(float4 v, uint2& h, uint2& l) {
    __nv_bfloat16 h0, h1, h2, h3, l0, l1, l2, l3;
    splitv(v.x, h0, l0); splitv(v.y, h1, l1);
    splitv(v.z, h2, l2); splitv(v.w, h3, l3);
    h = make_uint2(pk(h0, h1), pk(h2, h3));
    l = make_uint2(pk(l0, l1), pk(l2, l3));
}

// ---------------- weight conversion ----------------------------------------
__global__ void split_flat(const float4* __restrict__ src,
                           uint2* __restrict__ h,
                           uint2* __restrict__ l, unsigned n4) {
    unsigned stride = gridDim.x * blockDim.x;
    for (unsigned i = blockIdx.x * blockDim.x + threadIdx.x; i < n4; i += 2 * stride) {
        unsigned j = i + stride;
        float4 a = src[i];
        float4 b;
        bool has2 = (j < n4);
        if (has2) b = src[j];
        uint2 ha, la;
        split4(a, ha, la);
        h[i] = ha; l[i] = la;
        if (has2) {
            uint2 hb, lb;
            split4(b, hb, lb);
            h[j] = hb; l[j] = lb;
        }
    }
}

__device__ __forceinline__ void qkv_one(const float* __restrict__ wq,
                                        const float* __restrict__ wk,
                                        const float* __restrict__ wv,
                                        unsigned i4) {
    unsigned e = i4 * 4u;
    unsigned l = e / (unsigned)(Dd * NQKV);
    unsigned r = e - l * (unsigned)(Dd * NQKV);
    unsigned k = r / (unsigned)NQKV;
    unsigned n = r - k * (unsigned)NQKV;
    unsigned wsel = n / (unsigned)Dd;
    unsigned r2 = n - wsel * (unsigned)Dd;
    unsigned hh = r2 >> 6, s = r2 & 63;
    const float* base = (wsel == 0) ? wq : ((wsel == 1) ? wk : wv);
    float4 v = *(const float4*)(base + ((size_t)(l * Hh + hh) * Dd + k) * HS + s);
    uint2 hp, lp;
    split4(v, hp, lp);
    ((uint2*)wqkv_h)[i4] = hp;
    ((uint2*)wqkv_l)[i4] = lp;
}
__global__ void conv_qkv(const float* __restrict__ wq,
                         const float* __restrict__ wk,
                         const float* __restrict__ wv) {
    const unsigned total4 = (unsigned)Ll * Dd * NQKV / 4u;
    unsigned stride = gridDim.x * blockDim.x;
    for (unsigned i = blockIdx.x * blockDim.x + threadIdx.x; i < total4; i += 2 * stride) {
        qkv_one(wq, wk, wv, i);
        if (i + stride < total4) qkv_one(wq, wk, wv, i + stride);
    }
}

__device__ __forceinline__ void lm_one(const float* __restrict__ lm_w, unsigned i4) {
    unsigned e = i4 * 4u;
    unsigned k = e / (unsigned)VP;
    unsigned n = e - k * (unsigned)VP;
    const float* row = lm_w + (size_t)k * Vv;
    float4 v;
    v.x = (n     < Vv) ? row[n]     : 0.f;
    v.y = (n + 1 < Vv) ? row[n + 1] : 0.f;
    v.z = (n + 2 < Vv) ? row[n + 2] : 0.f;
    v.w = (n + 3 < Vv) ? row[n + 3] : 0.f;
    uint2 hp;
    hp.x = pkh(__float2half_rn(v.x), __float2half_rn(v.y));
    hp.y = pkh(__float2half_rn(v.z), __float2half_rn(v.w));
    ((uint2*)lmw16_h)[i4] = hp;
}
__global__ void conv_lm(const float* __restrict__ lm_w) {
    const unsigned total4 = (unsigned)Dd * VP / 4u;
    unsigned stride = gridDim.x * blockDim.x;
    for (unsigned i = blockIdx.x * blockDim.x + threadIdx.x; i < total4; i += 2 * stride) {
        lm_one(lm_w, i);
        if (i + stride < total4) lm_one(lm_w, i + stride);
    }
}

// x (fp32) -> fp16 copy for lm_head A operand
__global__ void conv_x16() {
    unsigned i4 = blockIdx.x * blockDim.x + threadIdx.x;
    if (i4 < (unsigned)(Mm * Dd / 4)) {
        float4 v = ((const float4*)g_x)[i4];
        uint2 h;
        h.x = pkh(__float2half_rn(v.x), __float2half_rn(v.y));
        h.y = pkh(__float2half_rn(v.z), __float2half_rn(v.w));
        ((uint2*)x16)[i4] = h;
    }
}

// ---------------- bf16x3 tensor-core GEMM (cp.async double-buffered) -------
__global__ __launch_bounds__(256, 2) void gemm_bf3(
    const __nv_bfloat16* __restrict__ Ah_g, const __nv_bfloat16* __restrict__ Al_g,
    int lda,
    const __nv_bfloat16* __restrict__ Bh_g, const __nv_bfloat16* __restrict__ Bl_g,
    int ldb,
    const float* __restrict__ bias,
    float* __restrict__ Cf,
    __nv_bfloat16* __restrict__ Ch, __nv_bfloat16* __restrict__ Cl,
    int ldc, int N, int K, int relu, int outmode)
{
    extern __shared__ char smem[];
    const uint32_t sb = s2u(smem);
    const int tid = threadIdx.x;
    const int wid = tid >> 5, lane = tid & 31;
    const int m0 = blockIdx.x * TM;
    const int n0 = blockIdx.y * TN;
    const int mw = (wid & 3) * 32;
    const int nw = (wid >> 2) * 64;

    float acc[2][8][4];
    #pragma unroll
    for (int a = 0; a < 2; a++)
        #pragma unroll
        for (int b = 0; b < 8; b++)
            #pragma unroll
            for (int c = 0; c < 4; c++) acc[a][b][c] = 0.f;

    auto load_stage = [&](int kc, int st) {
        uint32_t base = sb + st * STAGE_BYTES;
        #pragma unroll
        for (int i = 0; i < 2; i++) {
            int c = tid + i * 256;
            int row = c >> 2, q = c & 3;
            uint32_t d = base + OFF_AH + row * 80 + q * 16;
            cpa16(d, Ah_g + (size_t)(m0 + row) * lda + kc + q * 8);
            cpa16(d + (OFF_AL - OFF_AH), Al_g + (size_t)(m0 + row) * lda + kc + q * 8);
        }
        #pragma unroll
        for (int i = 0; i < 2; i++) {
            int c = tid + i * 256;
            int row = c >> 4, q = c & 15;
            uint32_t d = base + OFF_BH + row * 272 + q * 16;
            cpa16(d, Bh_g + (size_t)(kc + row) * ldb + n0 + q * 8);
            cpa16(d + (OFF_BL - OFF_BH), Bl_g + (size_t)(kc + row) * ldb + n0 + q * 8);
        }
        asm volatile("cp.async.commit_group;" ::: "memory");
    };

    const int niter = K / BK;
    load_stage(0, 0);

    for (int it = 0; it < niter; it++) {
        if (it + 1 < niter) {
            load_stage((it + 1) * BK, (it + 1) & 1);
            asm volatile("cp.async.wait_group 1;" ::: "memory");
        } else {
            asm volatile("cp.async.wait_group 0;" ::: "memory");
        }
        __syncthreads();

        const uint32_t sbase = sb + (it & 1) * STAGE_BYTES;
        #pragma unroll
        for (int kk = 0; kk < BK; kk += 16) {
            uint32_t ah[2][4], al[2][4];
            int arow = mw + (lane & 15);
            int acol = kk + (lane >> 4) * 8;
            #pragma unroll
            for (int mi = 0; mi < 2; mi++) {
                uint32_t off = (uint32_t)(arow + mi * 16) * (SA_STRIDE * 2) + acol * 2;
                ldmx4(ah[mi], sbase + OFF_AH + off);
                ldmx4(al[mi], sbase + OFF_AL + off);
            }
            int brow = kk + (lane & 15);
            int bcol = nw + (lane >> 4) * 8;
            #pragma unroll
            for (int ni = 0; ni < 4; ni++) {
                uint32_t off = (uint32_t)brow * (SB_STRIDE * 2) + (bcol + ni * 16) * 2;
                uint32_t bh[4], bl[4];
                ldmx4t(bh, sbase + OFF_BH + off);
                ldmx4t(bl, sbase + OFF_BL + off);
                #pragma unroll
                for (int mi = 0; mi < 2; mi++) {
                    mma_bf16(acc[mi][2 * ni],     ah[mi], bh[0], bh[1]);
                    mma_bf16(acc[mi][2 * ni],     ah[mi], bl[0], bl[1]);
                    mma_bf16(acc[mi][2 * ni],     al[mi], bh[0], bh[1]);
                    mma_bf16(acc[mi][2 * ni + 1], ah[mi], bh[2], bh[3]);
                    mma_bf16(acc[mi][2 * ni + 1], ah[mi], bl[2], bl[3]);
                    mma_bf16(acc[mi][2 * ni + 1], al[mi], bh[2], bh[3]);
                }
            }
        }
        __syncthreads();
    }

    float* sC = (float*)smem;
    const int r0 = mw + (lane >> 2);
    const int c0 = 2 * (lane & 3);
    #pragma unroll 1
    for (int hf = 0; hf < 2; hf++) {
        if ((wid >> 2) == hf) {
            #pragma unroll
            for (int mi = 0; mi < 2; mi++)
                #pragma unroll
                for (int ni = 0; ni < 8; ni++) {
                    int rr = (r0 + mi * 16) * 68 + ni * 8 + c0;
                    sC[rr]              = acc[mi][ni][0];
                    sC[rr + 1]          = acc[mi][ni][1];
                    sC[rr + 8 * 68]     = acc[mi][ni][2];
                    sC[rr + 8 * 68 + 1] = acc[mi][ni][3];
                }
        }
        __syncthreads();
        #pragma unroll 4
        for (int it = 0; it < 32; it++) {
            int idx = tid + it * 256;
            int r = idx >> 6, c = idx & 63;
            int col = n0 + hf * 64 + c;
            if (col < N) {
                float v = sC[r * 68 + c];
                if (bias) v += bias[col];
                if (relu) v = fmaxf(v, 0.f);
                if (outmode == 0) {
                    Cf[(size_t)(m0 + r) * ldc + col] = v;
                } else {
                    __nv_bfloat16 hh, ll;
                    splitv(v, hh, ll);
                    Ch[(size_t)(m0 + r) * ldc + col] = hh;
                    Cl[(size_t)(m0 + r) * ldc + col] = ll;
                }
            }
        }
        __syncthreads();
    }
}

// ---------------- lm_head GEMM: fp16 single-pass, TM=256, 512 threads ------
__global__ __launch_bounds__(512, 1) void gemm_lm(
    const __half* __restrict__ A_g, int lda,
    const __half* __restrict__ B_g, int ldb,
    const float* __restrict__ bias,
    float* __restrict__ C, int ldc, int N, int K)
{
    extern __shared__ char smem[];
    const uint32_t sb = s2u(smem);
    const int tid = threadIdx.x;
    const int wid = tid >> 5, lane = tid & 31;
    const int m0 = blockIdx.x * LM_TM;
    const int n0 = blockIdx.y * LM_TN;
    const int mw = (wid & 3) * 64;      // 4 m-warps
    const int nw = (wid >> 2) * 32;     // 4 n-warps

    float acc[4][4][4];
    #pragma unroll
    for (int a = 0; a < 4; a++)
        #pragma unroll
        for (int b = 0; b < 4; b++)
            #pragma unroll
            for (int c = 0; c < 4; c++) acc[a][b][c] = 0.f;

    auto load_stage = [&](int kc, int st) {
        uint32_t base = sb + st * LM_STAGE;
        // A: 256 rows x 4 16B-chunks = 1024, 2 per thread
        #pragma unroll
        for (int i = 0; i < 2; i++) {
            int c = tid + i * 512;
            int row = c >> 2, q = c & 3;
            cpa16(base + LM_OFF_A + row * 80 + q * 16,
                  A_g + (size_t)(m0 + row) * lda + kc + q * 8);
        }
        // B: 32 rows x 16 chunks = 512, 1 per thread
        {
            int row = tid >> 4, q = tid & 15;
            cpa16(base + LM_OFF_B + row * 272 + q * 16,
                  B_g + (size_t)(kc + row) * ldb + n0 + q * 8);
        }
        asm volatile("cp.async.commit_group;" ::: "memory");
    };

    const int niter = K / BK;
    load_stage(0, 0);

    for (int it = 0; it < niter; it++) {
        if (it + 1 < niter) {
            load_stage((it + 1) * BK, (it + 1) & 1);
            asm volatile("cp.async.wait_group 1;" ::: "memory");
        } else {
            asm volatile("cp.async.wait_group 0;" ::: "memory");
        }
        __syncthreads();

        const uint32_t sbase = sb + (it & 1) * LM_STAGE;
        #pragma unroll
        for (int kk = 0; kk < BK; kk += 16) {
            uint32_t af[4][4];
            int arow = mw + (lane & 15);
            int acol = kk + (lane >> 4) * 8;
            #pragma unroll
            for (int mi = 0; mi < 4; mi++)
                ldmx4(af[mi], sbase + LM_OFF_A +
                              (uint32_t)(arow + mi * 16) * 80 + acol * 2);
            int brow = kk + (lane & 15);
            int bcol = nw + (lane >> 4) * 8;
            #pragma unroll
            for (int j = 0; j < 2; j++) {
                uint32_t bh[4];
                ldmx4t(bh, sbase + LM_OFF_B +
                           (uint32_t)brow * 272 + (bcol + j * 16) * 2);
                #pragma unroll
                for (int mi = 0; mi < 4; mi++) {
                    mma_f16(acc[mi][2 * j],     af[mi], bh[0], bh[1]);
                    mma_f16(acc[mi][2 * j + 1], af[mi], bh[2], bh[3]);
                }
            }
        }
        __syncthreads();
    }

    // epilogue: smem transpose by n-half, coalesced fp32 stores
    float* sC = (float*)smem;
    const int r0 = mw + (lane >> 2);
    const int c0 = 2 * (lane & 3);
    const int cl0 = ((wid >> 2) & 1) * 32;
    #pragma unroll 1
    for (int hf = 0; hf < 2; hf++) {
        if ((wid >> 3) == hf) {
            #pragma unroll
            for (int mi = 0; mi < 4; mi++)
                #pragma unroll
                for (int nb = 0; nb < 4; nb++) {
                    int rr = (r0 + mi * 16) * 68 + cl0 + nb * 8 + c0;
                    sC[rr]              = acc[mi][nb][0];
                    sC[rr + 1]          = acc[mi][nb][1];
                    sC[rr + 8 * 68]     = acc[mi][nb][2];
                    sC[rr + 8 * 68 + 1] = acc[mi][nb][3];
                }
        }
        __syncthreads();
        #pragma unroll 4
        for (int it = 0; it < 32; it++) {
            int idx = tid + it * 512;            // 16384 = 256 x 64
            int r = idx >> 6, c = idx & 63;
            int col = n0 + hf * 64 + c;
            if (col < N)
                C[(size_t)(m0 + r) * ldc + col] = sC[r * 68 + c] + bias[col];
        }
        __syncthreads();
    }
}

// ---------------- flash attention (bf16x3, causal, online softmax) ---------
__global__ __launch_bounds__(128) void flash_kernel() {
    extern __shared__ char smem[];
    const uint32_t sb = s2u(smem);
    const int tid = threadIdx.x, wid = tid >> 5, lane = tid & 31;
    const int bh = blockIdx.y;
    const int b = bh / Hh, h = bh % Hh;
    const int t0 = (int)(gridDim.x - 1 - blockIdx.x) * FBM;
    const int mw = wid * 16;

    const size_t rowbase = (size_t)(b * Tt) * NQKV + h * HS;

    #pragma unroll
    for (int i = 0; i < 4; i++) {
        int c = tid + i * 128;
        int row = c >> 3, q = c & 7;
        size_t g = rowbase + (size_t)(t0 + row) * NQKV + q * 8;
        cpa16(sb + row * 144 + q * 16, qkvp_h + g);
        cpa16(sb + 9216 + row * 144 + q * 16, qkvp_l + g);
    }
    asm volatile("cp.async.commit_group;" ::: "memory");
    asm volatile("cp.async.wait_group 0;" ::: "memory");
    __syncthreads();

    uint32_t qfh[4][4], qfl[4][4];
    {
        int arow = mw + (lane & 15);
        #pragma unroll
        for (int kk = 0; kk < 4; kk++) {
            int acol = kk * 16 + (lane >> 4) * 8;
            uint32_t off = (uint32_t)arow * 144 + acol * 2;
            ldmx4(qfh[kk], sb + off);
            ldmx4(qfl[kk], sb + 9216 + off);
        }
    }
    __syncthreads();

    auto kv_issue = [&](int u0, int st) {
        uint32_t base = sb + st * FSTAGE;
        #pragma unroll
        for (int i = 0; i < 4; i++) {
            int c = tid + i * 128;
            int row = c >> 3, q = c & 7;
            size_t g = rowbase + (size_t)(u0 + row) * NQKV + q * 8;
            uint32_t d = base + row * 144 + q * 16;
            cpa16(d + FST_KH, qkvp_h + g + Dd);
            cpa16(d + FST_KL, qkvp_l + g + Dd);
            cpa16(d + FST_VH, qkvp_h + g + 2 * Dd);
            cpa16(d + FST_VL, qkvp_l + g + 2 * Dd);
        }
        asm volatile("cp.async.commit_group;" ::: "memory");
    };

    float o[8][4];
    #pragma unroll
    for (int i = 0; i < 8; i++)
        #pragma unroll
        for (int j = 0; j < 4; j++) o[i][j] = 0.f;
    float mA = -1e30f, mB = -1e30f, lA = 0.f, lB = 0.f;

    const int nt = t0 / FBN + 1;
    kv_issue(0, 1);

    for (int it = 0; it < nt; it++) {
        const int u0 = it * FBN;
        if (it + 1 < nt) {
            kv_issue((it + 1) * FBN, it & 1);
            asm volatile("cp.async.wait_group 1;" ::: "memory");
        } else {
            asm volatile("cp.async.wait_group 0;" ::: "memory");
        }
        __syncthreads();
        const uint32_t kb = sb + ((it + 1) & 1) * FSTAGE;

        float s[8][4];
        #pragma unroll
        for (int i = 0; i < 8; i++)
            #pragma unroll
            for (int j = 0; j < 4; j++) s[i][j] = 0.f;

        const int bn = ((lane >> 4) << 3) + (lane & 7);
        const int bk = ((lane >> 3) & 1) * 8;
        #pragma unroll
        for (int kk = 0; kk < 4; kk++) {
            #pragma unroll
            for (int j = 0; j < 4; j++) {
                uint32_t addr = kb + (uint32_t)(j * 16 + bn) * 144 + (kk * 16 + bk) * 2;
                uint32_t kh4[4], kl4[4];
                ldmx4(kh4, addr + FST_KH);
                ldmx4(kl4, addr + FST_KL);
                mma_bf16(s[2 * j],     qfh[kk], kh4[0], kh4[1]);
                mma_bf16(s[2 * j],     qfh[kk], kl4[0], kl4[1]);
                mma_bf16(s[2 * j],     qfl[kk], kh4[0], kh4[1]);
                mma_bf16(s[2 * j + 1], qfh[kk], kh4[2], kh4[3]);
                mma_bf16(s[2 * j + 1], qfh[kk], kl4[2], kl4[3]);
                mma_bf16(s[2 * j + 1], qfl[kk], kh4[2], kh4[3]);
            }
        }

        const int rA = lane >> 2;
        const int tA = t0 + mw + rA, tB = tA + 8;
        #pragma unroll
        for (int nb = 0; nb < 8; nb++)
            #pragma unroll
            for (int j = 0; j < 4; j++) s[nb][j] *= 0.125f;
        if (u0 + FBN - 1 > t0 + mw) {
            #pragma unroll
            for (int nb = 0; nb < 8; nb++) {
                int u_lo = u0 + nb * 8 + (lane & 3) * 2;
                if (u_lo     > tA) s[nb][0] = -1e30f;
                if (u_lo + 1 > tA) s[nb][1] = -1e30f;
                if (u_lo     > tB) s[nb][2] = -1e30f;
                if (u_lo + 1 > tB) s[nb][3] = -1e30f;
            }
        }

        float rmA = -1e30f, rmB = -1e30f;
        #pragma unroll
        for (int nb = 0; nb < 8; nb++) {
            rmA = fmaxf(rmA, fmaxf(s[nb][0], s[nb][1]));
            rmB = fmaxf(rmB, fmaxf(s[nb][2], s[nb][3]));
        }
        rmA = fmaxf(rmA, __shfl_xor_sync(0xffffffffu, rmA, 1));
        rmA = fmaxf(rmA, __shfl_xor_sync(0xffffffffu, rmA, 2));
        rmB = fmaxf(rmB, __shfl_xor_sync(0xffffffffu, rmB, 1));
        rmB = fmaxf(rmB, __shfl_xor_sync(0xffffffffu, rmB, 2));
        float mAn = fmaxf(mA, rmA), mBn = fmaxf(mB, rmB);
        float scA = __expf(mA - mAn), scB = __expf(mB - mBn);
        mA = mAn; mB = mBn;

        float rsA = 0.f, rsB = 0.f;
        #pragma unroll
        for (int nb = 0; nb < 8; nb++) {
            s[nb][0] = __expf(s[nb][0] - mA); rsA += s[nb][0];
            s[nb][1] = __expf(s[nb][1] - mA); rsA += s[nb][1];
            s[nb][2] = __expf(s[nb][2] - mB); rsB += s[nb][2];
            s[nb][3] = __expf(s[nb][3] - mB); rsB += s[nb][3];
        }
        rsA += __shfl_xor_sync(0xffffffffu, rsA, 1);
        rsA += __shfl_xor_sync(0xffffffffu, rsA, 2);
        rsB += __shfl_xor_sync(0xffffffffu, rsB, 1);
        rsB += __shfl_xor_sync(0xffffffffu, rsB, 2);
        lA = lA * scA + rsA;
        lB = lB * scB + rsB;
        #pragma unroll
        for (int nb = 0; nb < 8; nb++) {
            o[nb][0] *= scA; o[nb][1] *= scA;
            o[nb][2] *= scB; o[nb][3] *= scB;
        }

        #pragma unroll
        for (int g = 0; g < 4; g++) {
            uint32_t pha[4], pla[4];
            {
                __nv_bfloat16 h0, h1, l0, l1;
                splitv(s[2 * g][0], h0, l0); splitv(s[2 * g][1], h1, l1);
                pha[0] = pk(h0, h1); pla[0] = pk(l0, l1);
                splitv(s[2 * g][2], h0, l0); splitv(s[2 * g][3], h1, l1);
                pha[1] = pk(h0, h1); pla[1] = pk(l0, l1);
                splitv(s[2 * g + 1][0], h0, l0); splitv(s[2 * g + 1][1], h1, l1);
                pha[2] = pk(h0, h1); pla[2] = pk(l0, l1);
                splitv(s[2 * g + 1][2], h0, l0); splitv(s[2 * g + 1][3], h1, l1);
                pha[3] = pk(h0, h1); pla[3] = pk(l0, l1);
            }
            const int vrow = g * 16 + (lane & 15);
            #pragma unroll
            for (int j = 0; j < 4; j++) {
                uint32_t addr = kb + (uint32_t)vrow * 144 +
                                (uint32_t)(j * 16 + (lane >> 4) * 8) * 2;
                uint32_t vh4[4], vl4[4];
                ldmx4t(vh4, addr + FST_VH);
                ldmx4t(vl4, addr + FST_VL);
                mma_bf16(o[2 * j],     pha, vh4[0], vh4[1]);
                mma_bf16(o[2 * j],     pha, vl4[0], vl4[1]);
                mma_bf16(o[2 * j],     pla, vh4[0], vh4[1]);
                mma_bf16(o[2 * j + 1], pha, vh4[2], vh4[3]);
                mma_bf16(o[2 * j + 1], pha, vl4[2], vl4[3]);
                mma_bf16(o[2 * j + 1], pla, vh4[2], vh4[3]);
            }
        }
        __syncthreads();
    }

    const float invA = 1.f / lA, invB = 1.f / lB;
    const int rA = lane >> 2;
    const int tA = t0 + mw + rA, tB = tA + 8;
    const int cbase = h * HS + (lane & 3) * 2;
    size_t baseA = (size_t)(b * Tt + tA) * Dd + cbase;
    size_t baseB = (size_t)(b * Tt + tB) * Dd + cbase;
    #pragma unroll
    for (int nb = 0; nb < 8; nb++) {
        splitv(o[nb][0] * invA, o_h[baseA + nb * 8],     o_l[baseA + nb * 8]);
        splitv(o[nb][1] * invA, o_h[baseA + nb * 8 + 1], o_l[baseA + nb * 8 + 1]);
        splitv(o[nb][2] * invB, o_h[baseB + nb * 8],     o_l[baseB + nb * 8]);
        splitv(o[nb][3] * invB, o_h[baseB + nb * 8 + 1], o_l[baseB + nb * 8 + 1]);
    }
}

// ---------------- embedding -------------------------------------------------
__global__ void embed_kernel(const int* __restrict__ idx,
                             const float* __restrict__ tok_emb,
                             const float* __restrict__ pos_emb) {
    int m = blockIdx.x;
    int t = m % Tt;
    int tok = idx[m];
    const float* te = tok_emb + (size_t)tok * Dd;
    const float* pe = pos_emb + (size_t)t * Dd;
    float* x = g_x + (size_t)m * Dd;
    for (int c = threadIdx.x; c < Dd; c += blockDim.x) {
        float v = te[c] + pe[c];
        x[c] = v;
        splitv(v, x_h[(size_t)m * Dd + c], x_l[(size_t)m * Dd + c]);
    }
}

// ---------------- fused residual add + LayerNorm (warp per row) ------------
__global__ void addln_kernel(const float* __restrict__ add,
                             const float* __restrict__ gamma,
                             const float* __restrict__ beta) {
    int row = blockIdx.x * (blockDim.x >> 5) + (threadIdx.x >> 5);
    int lane = threadIdx.x & 31;
    float* x = g_x + (size_t)row * Dd;
    const float* a = add + (size_t)row * Dd;

    float v[24];
    float s = 0.f;
    #pragma unroll
    for (int i = 0; i < 24; i++) {
        int c = lane + i * 32;
        v[i] = x[c] + a[c];
        s += v[i];
    }
    #pragma unroll
    for (int o = 16; o > 0; o >>= 1) s += __shfl_xor_sync(0xffffffffu, s, o);
    float mean = s * (1.f / Dd);

    float q = 0.f;
    #pragma unroll
    for (int i = 0; i < 24; i++) {
        float d = v[i] - mean;
        q += d * d;
    }
    #pragma unroll
    for (int o = 16; o > 0; o >>= 1) q += __shfl_xor_sync(0xffffffffu, q, o);
    float rstd = rsqrtf(q * (1.f / Dd) + 1e-5f);

    #pragma unroll
    for (int i = 0; i < 24; i++) {
        int c = lane + i * 32;
        float ov = (v[i] - mean) * rstd * gamma[c] + beta[c];
        x[c] = ov;
        splitv(ov, x_h[(size_t)row * Dd + c], x_l[(size_t)row * Dd + c]);
    }
}

// ---------------- host orchestration ----------------------------------------
extern "C" void kernel_launch(void* const* d_in, const int* in_sizes, int n_in,
                              void* d_out, int out_size) {
    const int*   idx     = (const int*)  d_in[0];
    const float* tok_emb = (const float*)d_in[1];
    const float* pos_emb = (const float*)d_in[2];
    const float* wq      = (const float*)d_in[3];
    const float* wk      = (const float*)d_in[4];
    const float* wv      = (const float*)d_in[5];
    const float* wproj   = (const float*)d_in[6];
    const float* bproj   = (const float*)d_in[7];
    const float* w1      = (const float*)d_in[8];
    const float* b1      = (const float*)d_in[9];
    const float* w2      = (const float*)d_in[10];
    const float* b2      = (const float*)d_in[11];
    const float* ln1_g   = (const float*)d_in[12];
    const float* ln1_b   = (const float*)d_in[13];
    const float* ln2_g   = (const float*)d_in[14];
    const float* ln2_b   = (const float*)d_in[15];
    const float* lm_w    = (const float*)d_in[16];
    const float* lm_b    = (const float*)d_in[17];
    float* out = (float*)d_out;

    cudaFuncSetAttribute(gemm_bf3, cudaFuncAttributeMaxDynamicSharedMemorySize, GEMM_SMEM);
    cudaFuncSetAttribute(gemm_lm, cudaFuncAttributeMaxDynamicSharedMemorySize, LM_SMEM);
    cudaFuncSetAttribute(flash_kernel, cudaFuncAttributeMaxDynamicSharedMemorySize, FLASH_SMEM);

    float *p_x, *p_tmp;
    cudaGetSymbolAddress((void**)&p_x,   g_x);
    cudaGetSymbolAddress((void**)&p_tmp, g_tmp);
    __nv_bfloat16 *pxh, *pxl, *poh, *pol, *ph1h, *ph1l, *pqh, *pql;
    cudaGetSymbolAddress((void**)&pxh, x_h);   cudaGetSymbolAddress((void**)&pxl, x_l);
    cudaGetSymbolAddress((void**)&poh, o_h);   cudaGetSymbolAddress((void**)&pol, o_l);
    cudaGetSymbolAddress((void**)&ph1h, h1_h); cudaGetSymbolAddress((void**)&ph1l, h1_l);
    cudaGetSymbolAddress((void**)&pqh, qkvp_h); cudaGetSymbolAddress((void**)&pql, qkvp_l);
    __nv_bfloat16 *pwqh, *pwql, *pwph, *pwpl, *pw1h, *pw1l, *pw2h, *pw2l;
    cudaGetSymbolAddress((void**)&pwqh, wqkv_h); cudaGetSymbolAddress((void**)&pwql, wqkv_l);
    cudaGetSymbolAddress((void**)&pwph, wpr_h);  cudaGetSymbolAddress((void**)&pwpl, wpr_l);
    cudaGetSymbolAddress((void**)&pw1h, w1b_h);  cudaGetSymbolAddress((void**)&pw1l, w1b_l);
    cudaGetSymbolAddress((void**)&pw2h, w2b_h);  cudaGetSymbolAddress((void**)&pw2l, w2b_l);
    __half *plmh, *px16;
    cudaGetSymbolAddress((void**)&plmh, lmw16_h);
    cudaGetSymbolAddress((void**)&px16, x16);

    conv_qkv<<<1024, 256>>>(wq, wk, wv);
    split_flat<<<512, 256>>>((const float4*)wproj, (uint2*)pwph, (uint2*)pwpl,
                             (unsigned)(Ll * Dd * Dd / 4));
    split_flat<<<1024, 256>>>((const float4*)w1, (uint2*)pw1h, (uint2*)pw1l,
                              (unsigned)(Ll * Dd * DFF / 4));
    split_flat<<<1024, 256>>>((const float4*)w2, (uint2*)pw2h, (uint2*)pw2l,
                              (unsigned)(Ll * DFF * Dd / 4));
    conv_lm<<<2048, 256>>>(lm_w);

    embed_kernel<<<Mm, 256>>>(idx, tok_emb, pos_emb);

    for (int l = 0; l < Ll; l++) {
        gemm_bf3<<<dim3(Mm / TM, NQKV / TN), 256, GEMM_SMEM>>>(
            pxh, pxl, Dd,
            pwqh + (size_t)l * Dd * NQKV, pwql + (size_t)l * Dd * NQKV, NQKV,
            nullptr, nullptr, pqh, pql, NQKV, NQKV, Dd, 0, 1);
        flash_kernel<<<dim3(Tt / FBM, Bq * Hh), 128, FLASH_SMEM>>>();
        gemm_bf3<<<dim3(Mm / TM, Dd / TN), 256, GEMM_SMEM>>>(
            poh, pol, Dd,
            pwph + (size_t)l * Dd * Dd, pwpl + (size_t)l * Dd * Dd, Dd,
            bproj + (size_t)l * Dd, p_tmp, nullptr, nullptr, Dd, Dd, Dd, 0, 0);
        addln_kernel<<<Mm / 8, 256>>>(p_tmp, ln1_g + (size_t)l * Dd, ln1_b + (size_t)l * Dd);
        gemm_bf3<<<dim3(Mm / TM, DFF / TN), 256, GEMM_SMEM>>>(
            pxh, pxl, Dd,
            pw1h + (size_t)l * Dd * DFF, pw1l + (size_t)l * Dd * DFF, DFF,
            b1 + (size_t)l * DFF, nullptr, ph1h, ph1l, DFF, DFF, Dd, 1, 1);
        gemm_bf3<<<dim3(Mm / TM, Dd / TN), 256, GEMM_SMEM>>>(
            ph1h, ph1l, DFF,
            pw2h + (size_t)l * DFF * Dd, pw2l + (size_t)l * DFF * Dd, Dd,
            b2 + (size_t)l * Dd, p_tmp, nullptr, nullptr, Dd, Dd, DFF, 0, 0);
        addln_kernel<<<Mm / 8, 256>>>(p_tmp, ln2_g + (size_t)l * Dd, ln2_b + (size_t)l * Dd);
    }

    // lm_head: fp16 single-pass, TM=256
    conv_x16<<<(Mm * Dd / 4 + 255) / 256, 256>>>();
    gemm_lm<<<dim3(Mm / LM_TM, VP / LM_TN), 512, LM_SMEM>>>(
        px16, Dd, plmh, VP, lm_b, out, Vv, Vv, Dd);
}

// round 10
// speedup vs baseline: 1.5619x; 1.5619x over previous
#include <cuda_runtime.h>
#include <cuda_bf16.h>
#include <cuda_fp16.h>
#include <cstdint>
#include <math.h>
#include <stddef.h>

// Problem constants
#define Bq 2
#define Tt 1024
#define Dd 768
#define Hh 12
#define Ll 6
#define Vv 50257
#define VP 50304
#define HS 64
#define Mm (Bq*Tt)
#define DFF (4*Dd)
#define NQKV (3*Dd)

// GEMM tiling
#define TM 128
#define TN 128
#define BK 32
#define SA_STRIDE 40
#define SB_STRIDE 136
#define OFF_AH 0
#define OFF_AL 10240
#define OFF_BH 20480
#define OFF_BL 29184
#define STAGE_BYTES 37888
#define GEMM_SMEM (2*STAGE_BYTES)

// Flash attention tiling
#define FBM 64
#define FBN 64
#define FST_KH 0
#define FST_KL 9216
#define FST_VH 18432
#define FST_VL 27648
#define FSTAGE 36864
#define FLASH_SMEM (2*FSTAGE)

// ---------------- scratch --------------------------------------------------
__device__ float g_x  [Mm*Dd];
__device__ float g_tmp[Mm*Dd];

__device__ __nv_bfloat16 x_h [Mm*Dd],  x_l [Mm*Dd];
__device__ __half        x16 [Mm*Dd];
__device__ __nv_bfloat16 o_h [Mm*Dd],  o_l [Mm*Dd];
__device__ __nv_bfloat16 h1_h[(size_t)Mm*DFF], h1_l[(size_t)Mm*DFF];
__device__ __nv_bfloat16 qkvp_h[(size_t)Mm*NQKV], qkvp_l[(size_t)Mm*NQKV];

__device__ __nv_bfloat16 wqkv_h[(size_t)Ll*Dd*NQKV], wqkv_l[(size_t)Ll*Dd*NQKV];
__device__ __nv_bfloat16 wpr_h [(size_t)Ll*Dd*Dd],   wpr_l [(size_t)Ll*Dd*Dd];
__device__ __nv_bfloat16 w1b_h [(size_t)Ll*Dd*DFF],  w1b_l [(size_t)Ll*Dd*DFF];
__device__ __nv_bfloat16 w2b_h [(size_t)Ll*DFF*Dd],  w2b_l [(size_t)Ll*DFF*Dd];
__device__ __half        lmw16_h[(size_t)Dd*VP];

// ---------------- helpers --------------------------------------------------
__device__ __forceinline__ uint32_t s2u(const void* p) {
    uint32_t a;
    asm("{ .reg .u64 t; cvta.to.shared.u64 t, %1; cvt.u32.u64 %0, t; }" : "=r"(a) : "l"(p));
    return a;
}
__device__ __forceinline__ void cpa16(uint32_t dst, const void* src) {
    asm volatile("cp.async.cg.shared.global [%0], [%1], 16;" :: "r"(dst), "l"(src));
}
__device__ __forceinline__ void ldmx4(uint32_t* r, uint32_t addr) {
    asm volatile("ldmatrix.sync.aligned.m8n8.x4.shared.b16 {%0,%1,%2,%3},[%4];"
                 : "=r"(r[0]), "=r"(r[1]), "=r"(r[2]), "=r"(r[3]) : "r"(addr));
}
__device__ __forceinline__ void ldmx4t(uint32_t* r, uint32_t addr) {
    asm volatile("ldmatrix.sync.aligned.m8n8.x4.trans.shared.b16 {%0,%1,%2,%3},[%4];"
                 : "=r"(r[0]), "=r"(r[1]), "=r"(r[2]), "=r"(r[3]) : "r"(addr));
}
__device__ __forceinline__ void mma_bf16(float* c, const uint32_t* a,
                                         uint32_t b0, uint32_t b1) {
    asm volatile(
        "mma.sync.aligned.m16n8k16.row.col.f32.bf16.bf16.f32 "
        "{%0,%1,%2,%3},{%4,%5,%6,%7},{%8,%9},{%0,%1,%2,%3};"
        : "+f"(c[0]), "+f"(c[1]), "+f"(c[2]), "+f"(c[3])
        : "r"(a[0]), "r"(a[1]), "r"(a[2]), "r"(a[3]), "r"(b0), "r"(b1));
}
__device__ __forceinline__ void mma_f16(float* c, const uint32_t* a,
                                        uint32_t b0, uint32_t b1) {
    asm volatile(
        "mma.sync.aligned.m16n8k16.row.col.f32.f16.f16.f32 "
        "{%0,%1,%2,%3},{%4,%5,%6,%7},{%8,%9},{%0,%1,%2,%3};"
        : "+f"(c[0]), "+f"(c[1]), "+f"(c[2]), "+f"(c[3])
        : "r"(a[0]), "r"(a[1]), "r"(a[2]), "r"(a[3]), "r"(b0), "r"(b1));
}
__device__ __forceinline__ void splitv(float v, __nv_bfloat16& h, __nv_bfloat16& l) {
    h = __float2bfloat16_rn(v);
    l = __float2bfloat16_rn(v - __bfloat162float(h));
}
__device__ __forceinline__ uint32_t pk(__nv_bfloat16 a, __nv_bfloat16 b) {
    return ((uint32_t)__bfloat16_as_ushort(b) << 16) | __bfloat16_as_ushort(a);
}
__device__ __forceinline__ uint32_t pkh(__half a, __half b) {
    return ((uint32_t)__half_as_ushort(b) << 16) | __half_as_ushort(a);
}
__device__ __forceinline__ void split4(float4 v, uint2& h, uint2& l) {
    __nv_bfloat16 h0, h1, h2, h3, l0, l1, l2, l3;
    splitv(v.x, h0, l0); splitv(v.y, h1, l1);
    splitv(v.z, h2, l2); splitv(v.w, h3, l3);
    h = make_uint2(pk(h0, h1), pk(h2, h3));
    l = make_uint2(pk(l0, l1), pk(l2, l3));
}

// ---------------- weight conversion ----------------------------------------
__global__ void split_flat(const float4* __restrict__ src,
                           uint2* __restrict__ h,
                           uint2* __restrict__ l, unsigned n4) {
    unsigned stride = gridDim.x * blockDim.x;
    for (unsigned i = blockIdx.x * blockDim.x + threadIdx.x; i < n4; i += 2 * stride) {
        unsigned j = i + stride;
        float4 a = src[i];
        float4 b;
        bool has2 = (j < n4);
        if (has2) b = src[j];
        uint2 ha, la;
        split4(a, ha, la);
        h[i] = ha; l[i] = la;
        if (has2) {
            uint2 hb, lb;
            split4(b, hb, lb);
            h[j] = hb; l[j] = lb;
        }
    }
}

__device__ __forceinline__ void qkv_one(const float* __restrict__ wq,
                                        const float* __restrict__ wk,
                                        const float* __restrict__ wv,
                                        unsigned i4) {
    unsigned e = i4 * 4u;
    unsigned l = e / (unsigned)(Dd * NQKV);
    unsigned r = e - l * (unsigned)(Dd * NQKV);
    unsigned k = r / (unsigned)NQKV;
    unsigned n = r - k * (unsigned)NQKV;
    unsigned wsel = n / (unsigned)Dd;
    unsigned r2 = n - wsel * (unsigned)Dd;
    unsigned hh = r2 >> 6, s = r2 & 63;
    const float* base = (wsel == 0) ? wq : ((wsel == 1) ? wk : wv);
    float4 v = *(const float4*)(base + ((size_t)(l * Hh + hh) * Dd + k) * HS + s);
    uint2 hp, lp;
    split4(v, hp, lp);
    ((uint2*)wqkv_h)[i4] = hp;
    ((uint2*)wqkv_l)[i4] = lp;
}
__global__ void conv_qkv(const float* __restrict__ wq,
                         const float* __restrict__ wk,
                         const float* __restrict__ wv) {
    const unsigned total4 = (unsigned)Ll * Dd * NQKV / 4u;
    unsigned stride = gridDim.x * blockDim.x;
    for (unsigned i = blockIdx.x * blockDim.x + threadIdx.x; i < total4; i += 2 * stride) {
        qkv_one(wq, wk, wv, i);
        if (i + stride < total4) qkv_one(wq, wk, wv, i + stride);
    }
}

__device__ __forceinline__ void lm_one(const float* __restrict__ lm_w, unsigned i4) {
    unsigned e = i4 * 4u;
    unsigned k = e / (unsigned)VP;
    unsigned n = e - k * (unsigned)VP;
    const float* row = lm_w + (size_t)k * Vv;
    float4 v;
    v.x = (n     < Vv) ? row[n]     : 0.f;
    v.y = (n + 1 < Vv) ? row[n + 1] : 0.f;
    v.z = (n + 2 < Vv) ? row[n + 2] : 0.f;
    v.w = (n + 3 < Vv) ? row[n + 3] : 0.f;
    uint2 hp;
    hp.x = pkh(__float2half_rn(v.x), __float2half_rn(v.y));
    hp.y = pkh(__float2half_rn(v.z), __float2half_rn(v.w));
    ((uint2*)lmw16_h)[i4] = hp;
}
__global__ void conv_lm(const float* __restrict__ lm_w) {
    const unsigned total4 = (unsigned)Dd * VP / 4u;
    unsigned stride = gridDim.x * blockDim.x;
    for (unsigned i = blockIdx.x * blockDim.x + threadIdx.x; i < total4; i += 2 * stride) {
        lm_one(lm_w, i);
        if (i + stride < total4) lm_one(lm_w, i + stride);
    }
}

// x (fp32) -> fp16 copy for lm_head A operand
__global__ void conv_x16() {
    unsigned i4 = blockIdx.x * blockDim.x + threadIdx.x;
    if (i4 < (unsigned)(Mm * Dd / 4)) {
        float4 v = ((const float4*)g_x)[i4];
        uint2 h;
        h.x = pkh(__float2half_rn(v.x), __float2half_rn(v.y));
        h.y = pkh(__float2half_rn(v.z), __float2half_rn(v.w));
        ((uint2*)x16)[i4] = h;
    }
}

// ---------------- templated tensor-core GEMM (cp.async double-buffered) ----
// MODE 0: bf16 3-pass (AhBh + AhBl + AlBh).
// MODE 2: fp16 single-pass (AhBh only; Al/Bl never touched).
template<int MODE>
__global__ __launch_bounds__(256, 2) void gemm_mp(
    const __nv_bfloat16* __restrict__ Ah_g, const __nv_bfloat16* __restrict__ Al_g,
    int lda,
    const __nv_bfloat16* __restrict__ Bh_g, const __nv_bfloat16* __restrict__ Bl_g,
    int ldb,
    const float* __restrict__ bias,
    float* __restrict__ Cf,
    __nv_bfloat16* __restrict__ Ch, __nv_bfloat16* __restrict__ Cl,
    int ldc, int N, int K, int relu, int outmode)
{
    extern __shared__ char smem[];
    const uint32_t sb = s2u(smem);
    const int tid = threadIdx.x;
    const int wid = tid >> 5, lane = tid & 31;
    const int m0 = blockIdx.x * TM;
    const int n0 = blockIdx.y * TN;
    const int mw = (wid & 3) * 32;
    const int nw = (wid >> 2) * 64;

    float acc[2][8][4];
    #pragma unroll
    for (int a = 0; a < 2; a++)
        #pragma unroll
        for (int b = 0; b < 8; b++)
            #pragma unroll
            for (int c = 0; c < 4; c++) acc[a][b][c] = 0.f;

    auto load_stage = [&](int kc, int st) {
        uint32_t base = sb + st * STAGE_BYTES;
        #pragma unroll
        for (int i = 0; i < 2; i++) {
            int c = tid + i * 256;
            int row = c >> 2, q = c & 3;
            uint32_t d = base + OFF_AH + row * 80 + q * 16;
            cpa16(d, Ah_g + (size_t)(m0 + row) * lda + kc + q * 8);
            if (MODE == 0)
                cpa16(d + (OFF_AL - OFF_AH), Al_g + (size_t)(m0 + row) * lda + kc + q * 8);
        }
        #pragma unroll
        for (int i = 0; i < 2; i++) {
            int c = tid + i * 256;
            int row = c >> 4, q = c & 15;
            uint32_t d = base + OFF_BH + row * 272 + q * 16;
            cpa16(d, Bh_g + (size_t)(kc + row) * ldb + n0 + q * 8);
            if (MODE == 0)
                cpa16(d + (OFF_BL - OFF_BH), Bl_g + (size_t)(kc + row) * ldb + n0 + q * 8);
        }
        asm volatile("cp.async.commit_group;" ::: "memory");
    };

    const int niter = K / BK;
    load_stage(0, 0);

    for (int it = 0; it < niter; it++) {
        if (it + 1 < niter) {
            load_stage((it + 1) * BK, (it + 1) & 1);
            asm volatile("cp.async.wait_group 1;" ::: "memory");
        } else {
            asm volatile("cp.async.wait_group 0;" ::: "memory");
        }
        __syncthreads();

        const uint32_t sbase = sb + (it & 1) * STAGE_BYTES;
        #pragma unroll
        for (int kk = 0; kk < BK; kk += 16) {
            uint32_t ah[2][4], al[2][4];
            int arow = mw + (lane & 15);
            int acol = kk + (lane >> 4) * 8;
            #pragma unroll
            for (int mi = 0; mi < 2; mi++) {
                uint32_t off = (uint32_t)(arow + mi * 16) * (SA_STRIDE * 2) + acol * 2;
                ldmx4(ah[mi], sbase + OFF_AH + off);
                if (MODE == 0) ldmx4(al[mi], sbase + OFF_AL + off);
            }
            int brow = kk + (lane & 15);
            int bcol = nw + (lane >> 4) * 8;
            #pragma unroll
            for (int ni = 0; ni < 4; ni++) {
                uint32_t off = (uint32_t)brow * (SB_STRIDE * 2) + (bcol + ni * 16) * 2;
                uint32_t bh[4], bl[4];
                ldmx4t(bh, sbase + OFF_BH + off);
                if (MODE == 0) ldmx4t(bl, sbase + OFF_BL + off);
                #pragma unroll
                for (int mi = 0; mi < 2; mi++) {
                    if (MODE == 0) {
                        mma_bf16(acc[mi][2 * ni],     ah[mi], bh[0], bh[1]);
                        mma_bf16(acc[mi][2 * ni],     ah[mi], bl[0], bl[1]);
                        mma_bf16(acc[mi][2 * ni],     al[mi], bh[0], bh[1]);
                        mma_bf16(acc[mi][2 * ni + 1], ah[mi], bh[2], bh[3]);
                        mma_bf16(acc[mi][2 * ni + 1], ah[mi], bl[2], bl[3]);
                        mma_bf16(acc[mi][2 * ni + 1], al[mi], bh[2], bh[3]);
                    } else {
                        mma_f16(acc[mi][2 * ni],     ah[mi], bh[0], bh[1]);
                        mma_f16(acc[mi][2 * ni + 1], ah[mi], bh[2], bh[3]);
                    }
                }
            }
        }
        __syncthreads();
    }

    float* sC = (float*)smem;
    const int r0 = mw + (lane >> 2);
    const int c0 = 2 * (lane & 3);
    #pragma unroll 1
    for (int hf = 0; hf < 2; hf++) {
        if ((wid >> 2) == hf) {
            #pragma unroll
            for (int mi = 0; mi < 2; mi++)
                #pragma unroll
                for (int ni = 0; ni < 8; ni++) {
                    int rr = (r0 + mi * 16) * 68 + ni * 8 + c0;
                    sC[rr]              = acc[mi][ni][0];
                    sC[rr + 1]          = acc[mi][ni][1];
                    sC[rr + 8 * 68]     = acc[mi][ni][2];
                    sC[rr + 8 * 68 + 1] = acc[mi][ni][3];
                }
        }
        __syncthreads();
        #pragma unroll 4
        for (int it = 0; it < 32; it++) {
            int idx = tid + it * 256;
            int r = idx >> 6, c = idx & 63;
            int col = n0 + hf * 64 + c;
            if (col < N) {
                float v = sC[r * 68 + c];
                if (bias) v += bias[col];
                if (relu) v = fmaxf(v, 0.f);
                if (outmode == 0) {
                    Cf[(size_t)(m0 + r) * ldc + col] = v;
                } else {
                    __nv_bfloat16 hh, ll;
                    splitv(v, hh, ll);
                    Ch[(size_t)(m0 + r) * ldc + col] = hh;
                    Cl[(size_t)(m0 + r) * ldc + col] = ll;
                }
            }
        }
        __syncthreads();
    }
}

// ---------------- flash attention (bf16x3, causal, online softmax) ---------
__global__ __launch_bounds__(128) void flash_kernel() {
    extern __shared__ char smem[];
    const uint32_t sb = s2u(smem);
    const int tid = threadIdx.x, wid = tid >> 5, lane = tid & 31;
    const int bh = blockIdx.y;
    const int b = bh / Hh, h = bh % Hh;
    const int t0 = (int)(gridDim.x - 1 - blockIdx.x) * FBM;
    const int mw = wid * 16;

    const size_t rowbase = (size_t)(b * Tt) * NQKV + h * HS;

    #pragma unroll
    for (int i = 0; i < 4; i++) {
        int c = tid + i * 128;
        int row = c >> 3, q = c & 7;
        size_t g = rowbase + (size_t)(t0 + row) * NQKV + q * 8;
        cpa16(sb + row * 144 + q * 16, qkvp_h + g);
        cpa16(sb + 9216 + row * 144 + q * 16, qkvp_l + g);
    }
    asm volatile("cp.async.commit_group;" ::: "memory");
    asm volatile("cp.async.wait_group 0;" ::: "memory");
    __syncthreads();

    uint32_t qfh[4][4], qfl[4][4];
    {
        int arow = mw + (lane & 15);
        #pragma unroll
        for (int kk = 0; kk < 4; kk++) {
            int acol = kk * 16 + (lane >> 4) * 8;
            uint32_t off = (uint32_t)arow * 144 + acol * 2;
            ldmx4(qfh[kk], sb + off);
            ldmx4(qfl[kk], sb + 9216 + off);
        }
    }
    __syncthreads();

    auto kv_issue = [&](int u0, int st) {
        uint32_t base = sb + st * FSTAGE;
        #pragma unroll
        for (int i = 0; i < 4; i++) {
            int c = tid + i * 128;
            int row = c >> 3, q = c & 7;
            size_t g = rowbase + (size_t)(u0 + row) * NQKV + q * 8;
            uint32_t d = base + row * 144 + q * 16;
            cpa16(d + FST_KH, qkvp_h + g + Dd);
            cpa16(d + FST_KL, qkvp_l + g + Dd);
            cpa16(d + FST_VH, qkvp_h + g + 2 * Dd);
            cpa16(d + FST_VL, qkvp_l + g + 2 * Dd);
        }
        asm volatile("cp.async.commit_group;" ::: "memory");
    };

    float o[8][4];
    #pragma unroll
    for (int i = 0; i < 8; i++)
        #pragma unroll
        for (int j = 0; j < 4; j++) o[i][j] = 0.f;
    float mA = -1e30f, mB = -1e30f, lA = 0.f, lB = 0.f;

    const int nt = t0 / FBN + 1;
    kv_issue(0, 1);

    for (int it = 0; it < nt; it++) {
        const int u0 = it * FBN;
        if (it + 1 < nt) {
            kv_issue((it + 1) * FBN, it & 1);
            asm volatile("cp.async.wait_group 1;" ::: "memory");
        } else {
            asm volatile("cp.async.wait_group 0;" ::: "memory");
        }
        __syncthreads();
        const uint32_t kb = sb + ((it + 1) & 1) * FSTAGE;

        float s[8][4];
        #pragma unroll
        for (int i = 0; i < 8; i++)
            #pragma unroll
            for (int j = 0; j < 4; j++) s[i][j] = 0.f;

        const int bn = ((lane >> 4) << 3) + (lane & 7);
        const int bk = ((lane >> 3) & 1) * 8;
        #pragma unroll
        for (int kk = 0; kk < 4; kk++) {
            #pragma unroll
            for (int j = 0; j < 4; j++) {
                uint32_t addr = kb + (uint32_t)(j * 16 + bn) * 144 + (kk * 16 + bk) * 2;
                uint32_t kh4[4], kl4[4];
                ldmx4(kh4, addr + FST_KH);
                ldmx4(kl4, addr + FST_KL);
                mma_bf16(s[2 * j],     qfh[kk], kh4[0], kh4[1]);
                mma_bf16(s[2 * j],     qfh[kk], kl4[0], kl4[1]);
                mma_bf16(s[2 * j],     qfl[kk], kh4[0], kh4[1]);
                mma_bf16(s[2 * j + 1], qfh[kk], kh4[2], kh4[3]);
                mma_bf16(s[2 * j + 1], qfh[kk], kl4[2], kl4[3]);
                mma_bf16(s[2 * j + 1], qfl[kk], kh4[2], kh4[3]);
            }
        }

        const int rA = lane >> 2;
        const int tA = t0 + mw + rA, tB = tA + 8;
        #pragma unroll
        for (int nb = 0; nb < 8; nb++)
            #pragma unroll
            for (int j = 0; j < 4; j++) s[nb][j] *= 0.125f;
        if (u0 + FBN - 1 > t0 + mw) {
            #pragma unroll
            for (int nb = 0; nb < 8; nb++) {
                int u_lo = u0 + nb * 8 + (lane & 3) * 2;
                if (u_lo     > tA) s[nb][0] = -1e30f;
                if (u_lo + 1 > tA) s[nb][1] = -1e30f;
                if (u_lo     > tB) s[nb][2] = -1e30f;
                if (u_lo + 1 > tB) s[nb][3] = -1e30f;
            }
        }

        float rmA = -1e30f, rmB = -1e30f;
        #pragma unroll
        for (int nb = 0; nb < 8; nb++) {
            rmA = fmaxf(rmA, fmaxf(s[nb][0], s[nb][1]));
            rmB = fmaxf(rmB, fmaxf(s[nb][2], s[nb][3]));
        }
        rmA = fmaxf(rmA, __shfl_xor_sync(0xffffffffu, rmA, 1));
        rmA = fmaxf(rmA, __shfl_xor_sync(0xffffffffu, rmA, 2));
        rmB = fmaxf(rmB, __shfl_xor_sync(0xffffffffu, rmB, 1));
        rmB = fmaxf(rmB, __shfl_xor_sync(0xffffffffu, rmB, 2));
        float mAn = fmaxf(mA, rmA), mBn = fmaxf(mB, rmB);
        float scA = __expf(mA - mAn), scB = __expf(mB - mBn);
        mA = mAn; mB = mBn;

        float rsA = 0.f, rsB = 0.f;
        #pragma unroll
        for (int nb = 0; nb < 8; nb++) {
            s[nb][0] = __expf(s[nb][0] - mA); rsA += s[nb][0];
            s[nb][1] = __expf(s[nb][1] - mA); rsA += s[nb][1];
            s[nb][2] = __expf(s[nb][2] - mB); rsB += s[nb][2];
            s[nb][3] = __expf(s[nb][3] - mB); rsB += s[nb][3];
        }
        rsA += __shfl_xor_sync(0xffffffffu, rsA, 1);
        rsA += __shfl_xor_sync(0xffffffffu, rsA, 2);
        rsB += __shfl_xor_sync(0xffffffffu, rsB, 1);
        rsB += __shfl_xor_sync(0xffffffffu, rsB, 2);
        lA = lA * scA + rsA;
        lB = lB * scB + rsB;
        #pragma unroll
        for (int nb = 0; nb < 8; nb++) {
            o[nb][0] *= scA; o[nb][1] *= scA;
            o[nb][2] *= scB; o[nb][3] *= scB;
        }

        #pragma unroll
        for (int g = 0; g < 4; g++) {
            uint32_t pha[4], pla[4];
            {
                __nv_bfloat16 h0, h1, l0, l1;
                splitv(s[2 * g][0], h0, l0); splitv(s[2 * g][1], h1, l1);
                pha[0] = pk(h0, h1); pla[0] = pk(l0, l1);
                splitv(s[2 * g][2], h0, l0); splitv(s[2 * g][3], h1, l1);
                pha[1] = pk(h0, h1); pla[1] = pk(l0, l1);
                splitv(s[2 * g + 1][0], h0, l0); splitv(s[2 * g + 1][1], h1, l1);
                pha[2] = pk(h0, h1); pla[2] = pk(l0, l1);
                splitv(s[2 * g + 1][2], h0, l0); splitv(s[2 * g + 1][3], h1, l1);
                pha[3] = pk(h0, h1); pla[3] = pk(l0, l1);
            }
            const int vrow = g * 16 + (lane & 15);
            #pragma unroll
            for (int j = 0; j < 4; j++) {
                uint32_t addr = kb + (uint32_t)vrow * 144 +
                                (uint32_t)(j * 16 + (lane >> 4) * 8) * 2;
                uint32_t vh4[4], vl4[4];
                ldmx4t(vh4, addr + FST_VH);
                ldmx4t(vl4, addr + FST_VL);
                mma_bf16(o[2 * j],     pha, vh4[0], vh4[1]);
                mma_bf16(o[2 * j],     pha, vl4[0], vl4[1]);
                mma_bf16(o[2 * j],     pla, vh4[0], vh4[1]);
                mma_bf16(o[2 * j + 1], pha, vh4[2], vh4[3]);
                mma_bf16(o[2 * j + 1], pha, vl4[2], vl4[3]);
                mma_bf16(o[2 * j + 1], pla, vh4[2], vh4[3]);
            }
        }
        __syncthreads();
    }

    const float invA = 1.f / lA, invB = 1.f / lB;
    const int rA = lane >> 2;
    const int tA = t0 + mw + rA, tB = tA + 8;
    const int cbase = h * HS + (lane & 3) * 2;
    size_t baseA = (size_t)(b * Tt + tA) * Dd + cbase;
    size_t baseB = (size_t)(b * Tt + tB) * Dd + cbase;
    #pragma unroll
    for (int nb = 0; nb < 8; nb++) {
        splitv(o[nb][0] * invA, o_h[baseA + nb * 8],     o_l[baseA + nb * 8]);
        splitv(o[nb][1] * invA, o_h[baseA + nb * 8 + 1], o_l[baseA + nb * 8 + 1]);
        splitv(o[nb][2] * invB, o_h[baseB + nb * 8],     o_l[baseB + nb * 8]);
        splitv(o[nb][3] * invB, o_h[baseB + nb * 8 + 1], o_l[baseB + nb * 8 + 1]);
    }
}

// ---------------- embedding -------------------------------------------------
__global__ void embed_kernel(const int* __restrict__ idx,
                             const float* __restrict__ tok_emb,
                             const float* __restrict__ pos_emb) {
    int m = blockIdx.x;
    int t = m % Tt;
    int tok = idx[m];
    const float* te = tok_emb + (size_t)tok * Dd;
    const float* pe = pos_emb + (size_t)t * Dd;
    float* x = g_x + (size_t)m * Dd;
    for (int c = threadIdx.x; c < Dd; c += blockDim.x) {
        float v = te[c] + pe[c];
        x[c] = v;
        splitv(v, x_h[(size_t)m * Dd + c], x_l[(size_t)m * Dd + c]);
    }
}

// ---------------- fused residual add + LayerNorm (warp per row) ------------
__global__ void addln_kernel(const float* __restrict__ add,
                             const float* __restrict__ gamma,
                             const float* __restrict__ beta) {
    int row = blockIdx.x * (blockDim.x >> 5) + (threadIdx.x >> 5);
    int lane = threadIdx.x & 31;
    float* x = g_x + (size_t)row * Dd;
    const float* a = add + (size_t)row * Dd;

    float v[24];
    float s = 0.f;
    #pragma unroll
    for (int i = 0; i < 24; i++) {
        int c = lane + i * 32;
        v[i] = x[c] + a[c];
        s += v[i];
    }
    #pragma unroll
    for (int o = 16; o > 0; o >>= 1) s += __shfl_xor_sync(0xffffffffu, s, o);
    float mean = s * (1.f / Dd);

    float q = 0.f;
    #pragma unroll
    for (int i = 0; i < 24; i++) {
        float d = v[i] - mean;
        q += d * d;
    }
    #pragma unroll
    for (int o = 16; o > 0; o >>= 1) q += __shfl_xor_sync(0xffffffffu, q, o);
    float rstd = rsqrtf(q * (1.f / Dd) + 1e-5f);

    #pragma unroll
    for (int i = 0; i < 24; i++) {
        int c = lane + i * 32;
        float ov = (v[i] - mean) * rstd * gamma[c] + beta[c];
        x[c] = ov;
        splitv(ov, x_h[(size_t)row * Dd + c], x_l[(size_t)row * Dd + c]);
    }
}

// ---------------- host orchestration ----------------------------------------
extern "C" void kernel_launch(void* const* d_in, const int* in_sizes, int n_in,
                              void* d_out, int out_size) {
    const int*   idx     = (const int*)  d_in[0];
    const float* tok_emb = (const float*)d_in[1];
    const float* pos_emb = (const float*)d_in[2];
    const float* wq      = (const float*)d_in[3];
    const float* wk      = (const float*)d_in[4];
    const float* wv      = (const float*)d_in[5];
    const float* wproj   = (const float*)d_in[6];
    const float* bproj   = (const float*)d_in[7];
    const float* w1      = (const float*)d_in[8];
    const float* b1      = (const float*)d_in[9];
    const float* w2      = (const float*)d_in[10];
    const float* b2      = (const float*)d_in[11];
    const float* ln1_g   = (const float*)d_in[12];
    const float* ln1_b   = (const float*)d_in[13];
    const float* ln2_g   = (const float*)d_in[14];
    const float* ln2_b   = (const float*)d_in[15];
    const float* lm_w    = (const float*)d_in[16];
    const float* lm_b    = (const float*)d_in[17];
    float* out = (float*)d_out;

    cudaFuncSetAttribute(gemm_mp<0>, cudaFuncAttributeMaxDynamicSharedMemorySize, GEMM_SMEM);
    cudaFuncSetAttribute(gemm_mp<2>, cudaFuncAttributeMaxDynamicSharedMemorySize, GEMM_SMEM);
    cudaFuncSetAttribute(flash_kernel, cudaFuncAttributeMaxDynamicSharedMemorySize, FLASH_SMEM);

    float *p_x, *p_tmp;
    cudaGetSymbolAddress((void**)&p_x,   g_x);
    cudaGetSymbolAddress((void**)&p_tmp, g_tmp);
    __nv_bfloat16 *pxh, *pxl, *poh, *pol, *ph1h, *ph1l, *pqh, *pql;
    cudaGetSymbolAddress((void**)&pxh, x_h);   cudaGetSymbolAddress((void**)&pxl, x_l);
    cudaGetSymbolAddress((void**)&poh, o_h);   cudaGetSymbolAddress((void**)&pol, o_l);
    cudaGetSymbolAddress((void**)&ph1h, h1_h); cudaGetSymbolAddress((void**)&ph1l, h1_l);
    cudaGetSymbolAddress((void**)&pqh, qkvp_h); cudaGetSymbolAddress((void**)&pql, qkvp_l);
    __nv_bfloat16 *pwqh, *pwql, *pwph, *pwpl, *pw1h, *pw1l, *pw2h, *pw2l;
    cudaGetSymbolAddress((void**)&pwqh, wqkv_h); cudaGetSymbolAddress((void**)&pwql, wqkv_l);
    cudaGetSymbolAddress((void**)&pwph, wpr_h);  cudaGetSymbolAddress((void**)&pwpl, wpr_l);
    cudaGetSymbolAddress((void**)&pw1h, w1b_h);  cudaGetSymbolAddress((void**)&pw1l, w1b_l);
    cudaGetSymbolAddress((void**)&pw2h, w2b_h);  cudaGetSymbolAddress((void**)&pw2l, w2b_l);
    __half *plmh, *px16;
    cudaGetSymbolAddress((void**)&plmh, lmw16_h);
    cudaGetSymbolAddress((void**)&px16, x16);

    conv_qkv<<<1024, 256>>>(wq, wk, wv);
    split_flat<<<512, 256>>>((const float4*)wproj, (uint2*)pwph, (uint2*)pwpl,
                             (unsigned)(Ll * Dd * Dd / 4));
    split_flat<<<1024, 256>>>((const float4*)w1, (uint2*)pw1h, (uint2*)pw1l,
                              (unsigned)(Ll * Dd * DFF / 4));
    split_flat<<<1024, 256>>>((const float4*)w2, (uint2*)pw2h, (uint2*)pw2l,
                              (unsigned)(Ll * DFF * Dd / 4));
    conv_lm<<<2048, 256>>>(lm_w);

    embed_kernel<<<Mm, 256>>>(idx, tok_emb, pos_emb);

    for (int l = 0; l < Ll; l++) {
        gemm_mp<0><<<dim3(Mm / TM, NQKV / TN), 256, GEMM_SMEM>>>(
            pxh, pxl, Dd,
            pwqh + (size_t)l * Dd * NQKV, pwql + (size_t)l * Dd * NQKV, NQKV,
            nullptr, nullptr, pqh, pql, NQKV, NQKV, Dd, 0, 1);
        flash_kernel<<<dim3(Tt / FBM, Bq * Hh), 128, FLASH_SMEM>>>();
        gemm_mp<0><<<dim3(Mm / TM, Dd / TN), 256, GEMM_SMEM>>>(
            poh, pol, Dd,
            pwph + (size_t)l * Dd * Dd, pwpl + (size_t)l * Dd * Dd, Dd,
            bproj + (size_t)l * Dd, p_tmp, nullptr, nullptr, Dd, Dd, Dd, 0, 0);
        addln_kernel<<<Mm / 8, 256>>>(p_tmp, ln1_g + (size_t)l * Dd, ln1_b + (size_t)l * Dd);
        gemm_mp<0><<<dim3(Mm / TM, DFF / TN), 256, GEMM_SMEM>>>(
            pxh, pxl, Dd,
            pw1h + (size_t)l * Dd * DFF, pw1l + (size_t)l * Dd * DFF, DFF,
            b1 + (size_t)l * DFF, nullptr, ph1h, ph1l, DFF, DFF, Dd, 1, 1);
        gemm_mp<0><<<dim3(Mm / TM, Dd / TN), 256, GEMM_SMEM>>>(
            ph1h, ph1l, DFF,
            pw2h + (size_t)l * DFF * Dd, pw2l + (size_t)l * DFF * Dd, Dd,
            b2 + (size_t)l * Dd, p_tmp, nullptr, nullptr, Dd, Dd, DFF, 0, 0);
        addln_kernel<<<Mm / 8, 256>>>(p_tmp, ln2_g + (size_t)l * Dd, ln2_b + (size_t)l * Dd);
    }

    // lm_head: fp16 single-pass in the proven 256-thread TM=128 skeleton
    conv_x16<<<(Mm * Dd / 4 + 255) / 256, 256>>>();
    gemm_mp<2><<<dim3(Mm / TM, VP / TN), 256, GEMM_SMEM>>>(
        (const __nv_bfloat16*)px16, nullptr, Dd,
        (const __nv_bfloat16*)plmh, nullptr, VP,
        lm_b, out, nullptr, nullptr, Vv, Vv, Dd, 0, 0);
}

// round 11
// speedup vs baseline: 1.7544x; 1.1232x over previous
#include <cuda_runtime.h>
#include <cuda_bf16.h>
#include <cuda_fp16.h>
#include <cstdint>
#include <math.h>
#include <stddef.h>

// Problem constants
#define Bq 2
#define Tt 1024
#define Dd 768
#define Hh 12
#define Ll 6
#define Vv 50257
#define VP 50304
#define HS 64
#define Mm (Bq*Tt)
#define DFF (4*Dd)
#define NQKV (3*Dd)

// GEMM tiling
#define TM 128
#define TN 128
#define BK 32
#define SA_STRIDE 40
#define SB_STRIDE 136
#define OFF_AH 0
#define OFF_AL 10240
#define OFF_BH 20480
#define OFF_BL 29184
#define STAGE_BYTES 37888
#define GEMM_SMEM (2*STAGE_BYTES)

// Flash attention tiling
#define FBM 64
#define FBN 64
#define FST_KH 0
#define FST_KL 9216
#define FST_VH 18432
#define FST_VL 27648
#define FSTAGE 36864
#define FLASH_SMEM (2*FSTAGE)

// ---------------- scratch --------------------------------------------------
__device__ float g_x  [Mm*Dd];
__device__ float g_tmp[(size_t)3*Mm*Dd];     // up to 3 split-K partials

__device__ __nv_bfloat16 x_h [Mm*Dd],  x_l [Mm*Dd];
__device__ __half        x16 [Mm*Dd];
__device__ __nv_bfloat16 o_h [Mm*Dd],  o_l [Mm*Dd];
__device__ __nv_bfloat16 h1_h[(size_t)Mm*DFF], h1_l[(size_t)Mm*DFF];
__device__ __nv_bfloat16 qkvp_h[(size_t)Mm*NQKV], qkvp_l[(size_t)Mm*NQKV];

__device__ __nv_bfloat16 wqkv_h[(size_t)Ll*Dd*NQKV], wqkv_l[(size_t)Ll*Dd*NQKV];
__device__ __nv_bfloat16 wpr_h [(size_t)Ll*Dd*Dd],   wpr_l [(size_t)Ll*Dd*Dd];
__device__ __nv_bfloat16 w1b_h [(size_t)Ll*Dd*DFF],  w1b_l [(size_t)Ll*Dd*DFF];
__device__ __nv_bfloat16 w2b_h [(size_t)Ll*DFF*Dd],  w2b_l [(size_t)Ll*DFF*Dd];
__device__ __half        lmw16_h[(size_t)Dd*VP];

// ---------------- helpers --------------------------------------------------
__device__ __forceinline__ uint32_t s2u(const void* p) {
    uint32_t a;
    asm("{ .reg .u64 t; cvta.to.shared.u64 t, %1; cvt.u32.u64 %0, t; }" : "=r"(a) : "l"(p));
    return a;
}
__device__ __forceinline__ void cpa16(uint32_t dst, const void* src) {
    asm volatile("cp.async.cg.shared.global [%0], [%1], 16;" :: "r"(dst), "l"(src));
}
__device__ __forceinline__ void ldmx4(uint32_t* r, uint32_t addr) {
    asm volatile("ldmatrix.sync.aligned.m8n8.x4.shared.b16 {%0,%1,%2,%3},[%4];"
                 : "=r"(r[0]), "=r"(r[1]), "=r"(r[2]), "=r"(r[3]) : "r"(addr));
}
__device__ __forceinline__ void ldmx4t(uint32_t* r, uint32_t addr) {
    asm volatile("ldmatrix.sync.aligned.m8n8.x4.trans.shared.b16 {%0,%1,%2,%3},[%4];"
                 : "=r"(r[0]), "=r"(r[1]), "=r"(r[2]), "=r"(r[3]) : "r"(addr));
}
__device__ __forceinline__ void mma_bf16(float* c, const uint32_t* a,
                                         uint32_t b0, uint32_t b1) {
    asm volatile(
        "mma.sync.aligned.m16n8k16.row.col.f32.bf16.bf16.f32 "
        "{%0,%1,%2,%3},{%4,%5,%6,%7},{%8,%9},{%0,%1,%2,%3};"
        : "+f"(c[0]), "+f"(c[1]), "+f"(c[2]), "+f"(c[3])
        : "r"(a[0]), "r"(a[1]), "r"(a[2]), "r"(a[3]), "r"(b0), "r"(b1));
}
__device__ __forceinline__ void mma_f16(float* c, const uint32_t* a,
                                        uint32_t b0, uint32_t b1) {
    asm volatile(
        "mma.sync.aligned.m16n8k16.row.col.f32.f16.f16.f32 "
        "{%0,%1,%2,%3},{%4,%5,%6,%7},{%8,%9},{%0,%1,%2,%3};"
        : "+f"(c[0]), "+f"(c[1]), "+f"(c[2]), "+f"(c[3])
        : "r"(a[0]), "r"(a[1]), "r"(a[2]), "r"(a[3]), "r"(b0), "r"(b1));
}
__device__ __forceinline__ void splitv(float v, __nv_bfloat16& h, __nv_bfloat16& l) {
    h = __float2bfloat16_rn(v);
    l = __float2bfloat16_rn(v - __bfloat162float(h));
}
__device__ __forceinline__ uint32_t pk(__nv_bfloat16 a, __nv_bfloat16 b) {
    return ((uint32_t)__bfloat16_as_ushort(b) << 16) | __bfloat16_as_ushort(a);
}
__device__ __forceinline__ uint32_t pkh(__half a, __half b) {
    return ((uint32_t)__half_as_ushort(b) << 16) | __half_as_ushort(a);
}
__device__ __forceinline__ void split4(float4 v, uint2& h, uint2& l) {
    __nv_bfloat16 h0, h1, h2, h3, l0, l1, l2, l3;
    splitv(v.x, h0, l0); splitv(v.y, h1, l1);
    splitv(v.z, h2, l2); splitv(v.w, h3, l3);
    h = make_uint2(pk(h0, h1), pk(h2, h3));
    l = make_uint2(pk(l0, l1), pk(l2, l3));
}

// ---------------- weight conversion ----------------------------------------
__global__ void split_flat(const float4* __restrict__ src,
                           uint2* __restrict__ h,
                           uint2* __restrict__ l, unsigned n4) {
    unsigned stride = gridDim.x * blockDim.x;
    for (unsigned i = blockIdx.x * blockDim.x + threadIdx.x; i < n4; i += 2 * stride) {
        unsigned j = i + stride;
        float4 a = src[i];
        float4 b;
        bool has2 = (j < n4);
        if (has2) b = src[j];
        uint2 ha, la;
        split4(a, ha, la);
        h[i] = ha; l[i] = la;
        if (has2) {
            uint2 hb, lb;
            split4(b, hb, lb);
            h[j] = hb; l[j] = lb;
        }
    }
}

__device__ __forceinline__ void qkv_one(const float* __restrict__ wq,
                                        const float* __restrict__ wk,
                                        const float* __restrict__ wv,
                                        unsigned i4) {
    unsigned e = i4 * 4u;
    unsigned l = e / (unsigned)(Dd * NQKV);
    unsigned r = e - l * (unsigned)(Dd * NQKV);
    unsigned k = r / (unsigned)NQKV;
    unsigned n = r - k * (unsigned)NQKV;
    unsigned wsel = n / (unsigned)Dd;
    unsigned r2 = n - wsel * (unsigned)Dd;
    unsigned hh = r2 >> 6, s = r2 & 63;
    const float* base = (wsel == 0) ? wq : ((wsel == 1) ? wk : wv);
    float4 v = *(const float4*)(base + ((size_t)(l * Hh + hh) * Dd + k) * HS + s);
    uint2 hp, lp;
    split4(v, hp, lp);
    ((uint2*)wqkv_h)[i4] = hp;
    ((uint2*)wqkv_l)[i4] = lp;
}
__global__ void conv_qkv(const float* __restrict__ wq,
                         const float* __restrict__ wk,
                         const float* __restrict__ wv) {
    const unsigned total4 = (unsigned)Ll * Dd * NQKV / 4u;
    unsigned stride = gridDim.x * blockDim.x;
    for (unsigned i = blockIdx.x * blockDim.x + threadIdx.x; i < total4; i += 2 * stride) {
        qkv_one(wq, wk, wv, i);
        if (i + stride < total4) qkv_one(wq, wk, wv, i + stride);
    }
}

__device__ __forceinline__ void lm_one(const float* __restrict__ lm_w, unsigned i4) {
    unsigned e = i4 * 4u;
    unsigned k = e / (unsigned)VP;
    unsigned n = e - k * (unsigned)VP;
    const float* row = lm_w + (size_t)k * Vv;
    float4 v;
    v.x = (n     < Vv) ? row[n]     : 0.f;
    v.y = (n + 1 < Vv) ? row[n + 1] : 0.f;
    v.z = (n + 2 < Vv) ? row[n + 2] : 0.f;
    v.w = (n + 3 < Vv) ? row[n + 3] : 0.f;
    uint2 hp;
    hp.x = pkh(__float2half_rn(v.x), __float2half_rn(v.y));
    hp.y = pkh(__float2half_rn(v.z), __float2half_rn(v.w));
    ((uint2*)lmw16_h)[i4] = hp;
}
__global__ void conv_lm(const float* __restrict__ lm_w) {
    const unsigned total4 = (unsigned)Dd * VP / 4u;
    unsigned stride = gridDim.x * blockDim.x;
    for (unsigned i = blockIdx.x * blockDim.x + threadIdx.x; i < total4; i += 2 * stride) {
        lm_one(lm_w, i);
        if (i + stride < total4) lm_one(lm_w, i + stride);
    }
}

// ---------------- templated tensor-core GEMM (cp.async double-buffered) ----
// MODE 0: bf16 3-pass (AhBh + AhBl + AlBh).
// MODE 2: fp16 single-pass (AhBh only).
// Split-K: blockIdx.z = K-chunk index; chunk z reads A+z*K, B+z*K*ldb and
// writes Cf + z*Mm*ldc (fp32 partials); bias applied only by chunk 0.
template<int MODE>
__global__ __launch_bounds__(256, 2) void gemm_mp(
    const __nv_bfloat16* __restrict__ Ah_g, const __nv_bfloat16* __restrict__ Al_g,
    int lda,
    const __nv_bfloat16* __restrict__ Bh_g, const __nv_bfloat16* __restrict__ Bl_g,
    int ldb,
    const float* __restrict__ bias,
    float* __restrict__ Cf,
    __nv_bfloat16* __restrict__ Ch, __nv_bfloat16* __restrict__ Cl,
    int ldc, int N, int K, int relu, int outmode)
{
    extern __shared__ char smem[];
    const uint32_t sb = s2u(smem);
    const int tid = threadIdx.x;
    const int wid = tid >> 5, lane = tid & 31;
    const int m0 = blockIdx.x * TM;
    const int n0 = blockIdx.y * TN;
    const int kz = blockIdx.z;
    const int mw = (wid & 3) * 32;
    const int nw = (wid >> 2) * 64;

    // split-K chunk offsets
    Ah_g += (size_t)kz * K;
    if (MODE == 0) Al_g += (size_t)kz * K;
    Bh_g += (size_t)kz * K * ldb;
    if (MODE == 0) Bl_g += (size_t)kz * K * ldb;
    Cf   += (size_t)kz * Mm * ldc;
    const float* biasz = (kz == 0) ? bias : nullptr;

    float acc[2][8][4];
    #pragma unroll
    for (int a = 0; a < 2; a++)
        #pragma unroll
        for (int b = 0; b < 8; b++)
            #pragma unroll
            for (int c = 0; c < 4; c++) acc[a][b][c] = 0.f;

    auto load_stage = [&](int kc, int st) {
        uint32_t base = sb + st * STAGE_BYTES;
        #pragma unroll
        for (int i = 0; i < 2; i++) {
            int c = tid + i * 256;
            int row = c >> 2, q = c & 3;
            uint32_t d = base + OFF_AH + row * 80 + q * 16;
            cpa16(d, Ah_g + (size_t)(m0 + row) * lda + kc + q * 8);
            if (MODE == 0)
                cpa16(d + (OFF_AL - OFF_AH), Al_g + (size_t)(m0 + row) * lda + kc + q * 8);
        }
        #pragma unroll
        for (int i = 0; i < 2; i++) {
            int c = tid + i * 256;
            int row = c >> 4, q = c & 15;
            uint32_t d = base + OFF_BH + row * 272 + q * 16;
            cpa16(d, Bh_g + (size_t)(kc + row) * ldb + n0 + q * 8);
            if (MODE == 0)
                cpa16(d + (OFF_BL - OFF_BH), Bl_g + (size_t)(kc + row) * ldb + n0 + q * 8);
        }
        asm volatile("cp.async.commit_group;" ::: "memory");
    };

    const int niter = K / BK;
    load_stage(0, 0);

    for (int it = 0; it < niter; it++) {
        if (it + 1 < niter) {
            load_stage((it + 1) * BK, (it + 1) & 1);
            asm volatile("cp.async.wait_group 1;" ::: "memory");
        } else {
            asm volatile("cp.async.wait_group 0;" ::: "memory");
        }
        __syncthreads();

        const uint32_t sbase = sb + (it & 1) * STAGE_BYTES;
        #pragma unroll
        for (int kk = 0; kk < BK; kk += 16) {
            uint32_t ah[2][4], al[2][4];
            int arow = mw + (lane & 15);
            int acol = kk + (lane >> 4) * 8;
            #pragma unroll
            for (int mi = 0; mi < 2; mi++) {
                uint32_t off = (uint32_t)(arow + mi * 16) * (SA_STRIDE * 2) + acol * 2;
                ldmx4(ah[mi], sbase + OFF_AH + off);
                if (MODE == 0) ldmx4(al[mi], sbase + OFF_AL + off);
            }
            int brow = kk + (lane & 15);
            int bcol = nw + (lane >> 4) * 8;
            #pragma unroll
            for (int ni = 0; ni < 4; ni++) {
                uint32_t off = (uint32_t)brow * (SB_STRIDE * 2) + (bcol + ni * 16) * 2;
                uint32_t bh[4], bl[4];
                ldmx4t(bh, sbase + OFF_BH + off);
                if (MODE == 0) ldmx4t(bl, sbase + OFF_BL + off);
                #pragma unroll
                for (int mi = 0; mi < 2; mi++) {
                    if (MODE == 0) {
                        mma_bf16(acc[mi][2 * ni],     ah[mi], bh[0], bh[1]);
                        mma_bf16(acc[mi][2 * ni],     ah[mi], bl[0], bl[1]);
                        mma_bf16(acc[mi][2 * ni],     al[mi], bh[0], bh[1]);
                        mma_bf16(acc[mi][2 * ni + 1], ah[mi], bh[2], bh[3]);
                        mma_bf16(acc[mi][2 * ni + 1], ah[mi], bl[2], bl[3]);
                        mma_bf16(acc[mi][2 * ni + 1], al[mi], bh[2], bh[3]);
                    } else {
                        mma_f16(acc[mi][2 * ni],     ah[mi], bh[0], bh[1]);
                        mma_f16(acc[mi][2 * ni + 1], ah[mi], bh[2], bh[3]);
                    }
                }
            }
        }
        __syncthreads();
    }

    float* sC = (float*)smem;
    const int r0 = mw + (lane >> 2);
    const int c0 = 2 * (lane & 3);
    #pragma unroll 1
    for (int hf = 0; hf < 2; hf++) {
        if ((wid >> 2) == hf) {
            #pragma unroll
            for (int mi = 0; mi < 2; mi++)
                #pragma unroll
                for (int ni = 0; ni < 8; ni++) {
                    int rr = (r0 + mi * 16) * 68 + ni * 8 + c0;
                    sC[rr]              = acc[mi][ni][0];
                    sC[rr + 1]          = acc[mi][ni][1];
                    sC[rr + 8 * 68]     = acc[mi][ni][2];
                    sC[rr + 8 * 68 + 1] = acc[mi][ni][3];
                }
        }
        __syncthreads();
        #pragma unroll 4
        for (int it = 0; it < 32; it++) {
            int idx = tid + it * 256;
            int r = idx >> 6, c = idx & 63;
            int col = n0 + hf * 64 + c;
            if (col < N) {
                float v = sC[r * 68 + c];
                if (biasz) v += biasz[col];
                if (relu) v = fmaxf(v, 0.f);
                if (outmode == 0) {
                    Cf[(size_t)(m0 + r) * ldc + col] = v;
                } else {
                    __nv_bfloat16 hh, ll;
                    splitv(v, hh, ll);
                    Ch[(size_t)(m0 + r) * ldc + col] = hh;
                    Cl[(size_t)(m0 + r) * ldc + col] = ll;
                }
            }
        }
        __syncthreads();
    }
}

// ---------------- flash attention (bf16x3, causal, online softmax) ---------
__global__ __launch_bounds__(128) void flash_kernel() {
    extern __shared__ char smem[];
    const uint32_t sb = s2u(smem);
    const int tid = threadIdx.x, wid = tid >> 5, lane = tid & 31;
    const int bh = blockIdx.y;
    const int b = bh / Hh, h = bh % Hh;
    const int t0 = (int)(gridDim.x - 1 - blockIdx.x) * FBM;
    const int mw = wid * 16;

    const size_t rowbase = (size_t)(b * Tt) * NQKV + h * HS;

    #pragma unroll
    for (int i = 0; i < 4; i++) {
        int c = tid + i * 128;
        int row = c >> 3, q = c & 7;
        size_t g = rowbase + (size_t)(t0 + row) * NQKV + q * 8;
        cpa16(sb + row * 144 + q * 16, qkvp_h + g);
        cpa16(sb + 9216 + row * 144 + q * 16, qkvp_l + g);
    }
    asm volatile("cp.async.commit_group;" ::: "memory");
    asm volatile("cp.async.wait_group 0;" ::: "memory");
    __syncthreads();

    uint32_t qfh[4][4], qfl[4][4];
    {
        int arow = mw + (lane & 15);
        #pragma unroll
        for (int kk = 0; kk < 4; kk++) {
            int acol = kk * 16 + (lane >> 4) * 8;
            uint32_t off = (uint32_t)arow * 144 + acol * 2;
            ldmx4(qfh[kk], sb + off);
            ldmx4(qfl[kk], sb + 9216 + off);
        }
    }
    __syncthreads();

    auto kv_issue = [&](int u0, int st) {
        uint32_t base = sb + st * FSTAGE;
        #pragma unroll
        for (int i = 0; i < 4; i++) {
            int c = tid + i * 128;
            int row = c >> 3, q = c & 7;
            size_t g = rowbase + (size_t)(u0 + row) * NQKV + q * 8;
            uint32_t d = base + row * 144 + q * 16;
            cpa16(d + FST_KH, qkvp_h + g + Dd);
            cpa16(d + FST_KL, qkvp_l + g + Dd);
            cpa16(d + FST_VH, qkvp_h + g + 2 * Dd);
            cpa16(d + FST_VL, qkvp_l + g + 2 * Dd);
        }
        asm volatile("cp.async.commit_group;" ::: "memory");
    };

    float o[8][4];
    #pragma unroll
    for (int i = 0; i < 8; i++)
        #pragma unroll
        for (int j = 0; j < 4; j++) o[i][j] = 0.f;
    float mA = -1e30f, mB = -1e30f, lA = 0.f, lB = 0.f;

    const int nt = t0 / FBN + 1;
    kv_issue(0, 1);

    for (int it = 0; it < nt; it++) {
        const int u0 = it * FBN;
        if (it + 1 < nt) {
            kv_issue((it + 1) * FBN, it & 1);
            asm volatile("cp.async.wait_group 1;" ::: "memory");
        } else {
            asm volatile("cp.async.wait_group 0;" ::: "memory");
        }
        __syncthreads();
        const uint32_t kb = sb + ((it + 1) & 1) * FSTAGE;

        float s[8][4];
        #pragma unroll
        for (int i = 0; i < 8; i++)
            #pragma unroll
            for (int j = 0; j < 4; j++) s[i][j] = 0.f;

        const int bn = ((lane >> 4) << 3) + (lane & 7);
        const int bk = ((lane >> 3) & 1) * 8;
        #pragma unroll
        for (int kk = 0; kk < 4; kk++) {
            #pragma unroll
            for (int j = 0; j < 4; j++) {
                uint32_t addr = kb + (uint32_t)(j * 16 + bn) * 144 + (kk * 16 + bk) * 2;
                uint32_t kh4[4], kl4[4];
                ldmx4(kh4, addr + FST_KH);
                ldmx4(kl4, addr + FST_KL);
                mma_bf16(s[2 * j],     qfh[kk], kh4[0], kh4[1]);
                mma_bf16(s[2 * j],     qfh[kk], kl4[0], kl4[1]);
                mma_bf16(s[2 * j],     qfl[kk], kh4[0], kh4[1]);
                mma_bf16(s[2 * j + 1], qfh[kk], kh4[2], kh4[3]);
                mma_bf16(s[2 * j + 1], qfh[kk], kl4[2], kl4[3]);
                mma_bf16(s[2 * j + 1], qfl[kk], kh4[2], kh4[3]);
            }
        }

        const int rA = lane >> 2;
        const int tA = t0 + mw + rA, tB = tA + 8;
        #pragma unroll
        for (int nb = 0; nb < 8; nb++)
            #pragma unroll
            for (int j = 0; j < 4; j++) s[nb][j] *= 0.125f;
        if (u0 + FBN - 1 > t0 + mw) {
            #pragma unroll
            for (int nb = 0; nb < 8; nb++) {
                int u_lo = u0 + nb * 8 + (lane & 3) * 2;
                if (u_lo     > tA) s[nb][0] = -1e30f;
                if (u_lo + 1 > tA) s[nb][1] = -1e30f;
                if (u_lo     > tB) s[nb][2] = -1e30f;
                if (u_lo + 1 > tB) s[nb][3] = -1e30f;
            }
        }

        float rmA = -1e30f, rmB = -1e30f;
        #pragma unroll
        for (int nb = 0; nb < 8; nb++) {
            rmA = fmaxf(rmA, fmaxf(s[nb][0], s[nb][1]));
            rmB = fmaxf(rmB, fmaxf(s[nb][2], s[nb][3]));
        }
        rmA = fmaxf(rmA, __shfl_xor_sync(0xffffffffu, rmA, 1));
        rmA = fmaxf(rmA, __shfl_xor_sync(0xffffffffu, rmA, 2));
        rmB = fmaxf(rmB, __shfl_xor_sync(0xffffffffu, rmB, 1));
        rmB = fmaxf(rmB, __shfl_xor_sync(0xffffffffu, rmB, 2));
        float mAn = fmaxf(mA, rmA), mBn = fmaxf(mB, rmB);
        float scA = __expf(mA - mAn), scB = __expf(mB - mBn);
        mA = mAn; mB = mBn;

        float rsA = 0.f, rsB = 0.f;
        #pragma unroll
        for (int nb = 0; nb < 8; nb++) {
            s[nb][0] = __expf(s[nb][0] - mA); rsA += s[nb][0];
            s[nb][1] = __expf(s[nb][1] - mA); rsA += s[nb][1];
            s[nb][2] = __expf(s[nb][2] - mB); rsB += s[nb][2];
            s[nb][3] = __expf(s[nb][3] - mB); rsB += s[nb][3];
        }
        rsA += __shfl_xor_sync(0xffffffffu, rsA, 1);
        rsA += __shfl_xor_sync(0xffffffffu, rsA, 2);
        rsB += __shfl_xor_sync(0xffffffffu, rsB, 1);
        rsB += __shfl_xor_sync(0xffffffffu, rsB, 2);
        lA = lA * scA + rsA;
        lB = lB * scB + rsB;
        #pragma unroll
        for (int nb = 0; nb < 8; nb++) {
            o[nb][0] *= scA; o[nb][1] *= scA;
            o[nb][2] *= scB; o[nb][3] *= scB;
        }

        #pragma unroll
        for (int g = 0; g < 4; g++) {
            uint32_t pha[4], pla[4];
            {
                __nv_bfloat16 h0, h1, l0, l1;
                splitv(s[2 * g][0], h0, l0); splitv(s[2 * g][1], h1, l1);
                pha[0] = pk(h0, h1); pla[0] = pk(l0, l1);
                splitv(s[2 * g][2], h0, l0); splitv(s[2 * g][3], h1, l1);
                pha[1] = pk(h0, h1); pla[1] = pk(l0, l1);
                splitv(s[2 * g + 1][0], h0, l0); splitv(s[2 * g + 1][1], h1, l1);
                pha[2] = pk(h0, h1); pla[2] = pk(l0, l1);
                splitv(s[2 * g + 1][2], h0, l0); splitv(s[2 * g + 1][3], h1, l1);
                pha[3] = pk(h0, h1); pla[3] = pk(l0, l1);
            }
            const int vrow = g * 16 + (lane & 15);
            #pragma unroll
            for (int j = 0; j < 4; j++) {
                uint32_t addr = kb + (uint32_t)vrow * 144 +
                                (uint32_t)(j * 16 + (lane >> 4) * 8) * 2;
                uint32_t vh4[4], vl4[4];
                ldmx4t(vh4, addr + FST_VH);
                ldmx4t(vl4, addr + FST_VL);
                mma_bf16(o[2 * j],     pha, vh4[0], vh4[1]);
                mma_bf16(o[2 * j],     pha, vl4[0], vl4[1]);
                mma_bf16(o[2 * j],     pla, vh4[0], vh4[1]);
                mma_bf16(o[2 * j + 1], pha, vh4[2], vh4[3]);
                mma_bf16(o[2 * j + 1], pha, vl4[2], vl4[3]);
                mma_bf16(o[2 * j + 1], pla, vh4[2], vh4[3]);
            }
        }
        __syncthreads();
    }

    const float invA = 1.f / lA, invB = 1.f / lB;
    const int rA = lane >> 2;
    const int tA = t0 + mw + rA, tB = tA + 8;
    const int cbase = h * HS + (lane & 3) * 2;
    size_t baseA = (size_t)(b * Tt + tA) * Dd + cbase;
    size_t baseB = (size_t)(b * Tt + tB) * Dd + cbase;
    #pragma unroll
    for (int nb = 0; nb < 8; nb++) {
        splitv(o[nb][0] * invA, o_h[baseA + nb * 8],     o_l[baseA + nb * 8]);
        splitv(o[nb][1] * invA, o_h[baseA + nb * 8 + 1], o_l[baseA + nb * 8 + 1]);
        splitv(o[nb][2] * invB, o_h[baseB + nb * 8],     o_l[baseB + nb * 8]);
        splitv(o[nb][3] * invB, o_h[baseB + nb * 8 + 1], o_l[baseB + nb * 8 + 1]);
    }
}

// ---------------- embedding -------------------------------------------------
__global__ void embed_kernel(const int* __restrict__ idx,
                             const float* __restrict__ tok_emb,
                             const float* __restrict__ pos_emb) {
    int m = blockIdx.x;
    int t = m % Tt;
    int tok = idx[m];
    const float* te = tok_emb + (size_t)tok * Dd;
    const float* pe = pos_emb + (size_t)t * Dd;
    float* x = g_x + (size_t)m * Dd;
    for (int c = threadIdx.x; c < Dd; c += blockDim.x) {
        float v = te[c] + pe[c];
        x[c] = v;
        splitv(v, x_h[(size_t)m * Dd + c], x_l[(size_t)m * Dd + c]);
    }
}

// ---------------- fused residual add + LayerNorm (warp per row) ------------
// Sums nparts split-K partials from tmp; optionally writes x16 (fp16) output.
__global__ void addln_kernel(const float* __restrict__ tmp,
                             const float* __restrict__ gamma,
                             const float* __restrict__ beta,
                             int nparts, int w16) {
    int row = blockIdx.x * (blockDim.x >> 5) + (threadIdx.x >> 5);
    int lane = threadIdx.x & 31;
    float* x = g_x + (size_t)row * Dd;
    const float* a0 = tmp + (size_t)row * Dd;

    float v[24];
    float s = 0.f;
    #pragma unroll
    for (int i = 0; i < 24; i++) {
        int c = lane + i * 32;
        float t = x[c] + a0[c];
        if (nparts > 1) t += a0[(size_t)Mm * Dd + c];
        if (nparts > 2) t += a0[(size_t)2 * Mm * Dd + c];
        v[i] = t;
        s += t;
    }
    #pragma unroll
    for (int o = 16; o > 0; o >>= 1) s += __shfl_xor_sync(0xffffffffu, s, o);
    float mean = s * (1.f / Dd);

    float q = 0.f;
    #pragma unroll
    for (int i = 0; i < 24; i++) {
        float d = v[i] - mean;
        q += d * d;
    }
    #pragma unroll
    for (int o = 16; o > 0; o >>= 1) q += __shfl_xor_sync(0xffffffffu, q, o);
    float rstd = rsqrtf(q * (1.f / Dd) + 1e-5f);

    #pragma unroll
    for (int i = 0; i < 24; i++) {
        int c = lane + i * 32;
        float ov = (v[i] - mean) * rstd * gamma[c] + beta[c];
        x[c] = ov;
        splitv(ov, x_h[(size_t)row * Dd + c], x_l[(size_t)row * Dd + c]);
        if (w16) x16[(size_t)row * Dd + c] = __float2half_rn(ov);
    }
}

// ---------------- host orchestration ----------------------------------------
extern "C" void kernel_launch(void* const* d_in, const int* in_sizes, int n_in,
                              void* d_out, int out_size) {
    const int*   idx     = (const int*)  d_in[0];
    const float* tok_emb = (const float*)d_in[1];
    const float* pos_emb = (const float*)d_in[2];
    const float* wq      = (const float*)d_in[3];
    const float* wk      = (const float*)d_in[4];
    const float* wv      = (const float*)d_in[5];
    const float* wproj   = (const float*)d_in[6];
    const float* bproj   = (const float*)d_in[7];
    const float* w1      = (const float*)d_in[8];
    const float* b1      = (const float*)d_in[9];
    const float* w2      = (const float*)d_in[10];
    const float* b2      = (const float*)d_in[11];
    const float* ln1_g   = (const float*)d_in[12];
    const float* ln1_b   = (const float*)d_in[13];
    const float* ln2_g   = (const float*)d_in[14];
    const float* ln2_b   = (const float*)d_in[15];
    const float* lm_w    = (const float*)d_in[16];
    const float* lm_b    = (const float*)d_in[17];
    float* out = (float*)d_out;

    cudaFuncSetAttribute(gemm_mp<0>, cudaFuncAttributeMaxDynamicSharedMemorySize, GEMM_SMEM);
    cudaFuncSetAttribute(gemm_mp<2>, cudaFuncAttributeMaxDynamicSharedMemorySize, GEMM_SMEM);
    cudaFuncSetAttribute(flash_kernel, cudaFuncAttributeMaxDynamicSharedMemorySize, FLASH_SMEM);

    float *p_x, *p_tmp;
    cudaGetSymbolAddress((void**)&p_x,   g_x);
    cudaGetSymbolAddress((void**)&p_tmp, g_tmp);
    __nv_bfloat16 *pxh, *pxl, *poh, *pol, *ph1h, *ph1l, *pqh, *pql;
    cudaGetSymbolAddress((void**)&pxh, x_h);   cudaGetSymbolAddress((void**)&pxl, x_l);
    cudaGetSymbolAddress((void**)&poh, o_h);   cudaGetSymbolAddress((void**)&pol, o_l);
    cudaGetSymbolAddress((void**)&ph1h, h1_h); cudaGetSymbolAddress((void**)&ph1l, h1_l);
    cudaGetSymbolAddress((void**)&pqh, qkvp_h); cudaGetSymbolAddress((void**)&pql, qkvp_l);
    __nv_bfloat16 *pwqh, *pwql, *pwph, *pwpl, *pw1h, *pw1l, *pw2h, *pw2l;
    cudaGetSymbolAddress((void**)&pwqh, wqkv_h); cudaGetSymbolAddress((void**)&pwql, wqkv_l);
    cudaGetSymbolAddress((void**)&pwph, wpr_h);  cudaGetSymbolAddress((void**)&pwpl, wpr_l);
    cudaGetSymbolAddress((void**)&pw1h, w1b_h);  cudaGetSymbolAddress((void**)&pw1l, w1b_l);
    cudaGetSymbolAddress((void**)&pw2h, w2b_h);  cudaGetSymbolAddress((void**)&pw2l, w2b_l);
    __half *plmh, *px16;
    cudaGetSymbolAddress((void**)&plmh, lmw16_h);
    cudaGetSymbolAddress((void**)&px16, x16);

    conv_qkv<<<1024, 256>>>(wq, wk, wv);
    split_flat<<<512, 256>>>((const float4*)wproj, (uint2*)pwph, (uint2*)pwpl,
                             (unsigned)(Ll * Dd * Dd / 4));
    split_flat<<<1024, 256>>>((const float4*)w1, (uint2*)pw1h, (uint2*)pw1l,
                              (unsigned)(Ll * Dd * DFF / 4));
    split_flat<<<1024, 256>>>((const float4*)w2, (uint2*)pw2h, (uint2*)pw2l,
                              (unsigned)(Ll * DFF * Dd / 4));
    conv_lm<<<2048, 256>>>(lm_w);

    embed_kernel<<<Mm, 256>>>(idx, tok_emb, pos_emb);

    for (int l = 0; l < Ll; l++) {
        // QKV -> bf16 hi/lo pairs (288 CTAs, ~full wave)
        gemm_mp<0><<<dim3(Mm / TM, NQKV / TN, 1), 256, GEMM_SMEM>>>(
            pxh, pxl, Dd,
            pwqh + (size_t)l * Dd * NQKV, pwql + (size_t)l * Dd * NQKV, NQKV,
            nullptr, nullptr, pqh, pql, NQKV, NQKV, Dd, 0, 1);
        flash_kernel<<<dim3(Tt / FBM, Bq * Hh), 128, FLASH_SMEM>>>();
        // proj: split-K=3 (K=256 per chunk) -> 288 CTAs, partials in tmp[0..2]
        gemm_mp<0><<<dim3(Mm / TM, Dd / TN, 3), 256, GEMM_SMEM>>>(
            poh, pol, Dd,
            pwph + (size_t)l * Dd * Dd, pwpl + (size_t)l * Dd * Dd, Dd,
            bproj + (size_t)l * Dd, p_tmp, nullptr, nullptr, Dd, Dd, Dd / 3, 0, 0);
        addln_kernel<<<Mm / 8, 256>>>(p_tmp, ln1_g + (size_t)l * Dd,
                                      ln1_b + (size_t)l * Dd, 3, 0);
        // fc1 -> bf16 pair + relu (384 CTAs)
        gemm_mp<0><<<dim3(Mm / TM, DFF / TN, 1), 256, GEMM_SMEM>>>(
            pxh, pxl, Dd,
            pw1h + (size_t)l * Dd * DFF, pw1l + (size_t)l * Dd * DFF, DFF,
            b1 + (size_t)l * DFF, nullptr, ph1h, ph1l, DFF, DFF, Dd, 1, 1);
        // fc2: split-K=3 (K=1024 per chunk) -> 288 CTAs
        gemm_mp<0><<<dim3(Mm / TM, Dd / TN, 3), 256, GEMM_SMEM>>>(
            ph1h, ph1l, DFF,
            pw2h + (size_t)l * DFF * Dd, pw2l + (size_t)l * DFF * Dd, Dd,
            b2 + (size_t)l * Dd, p_tmp, nullptr, nullptr, Dd, Dd, DFF / 3, 0, 0);
        addln_kernel<<<Mm / 8, 256>>>(p_tmp, ln2_g + (size_t)l * Dd,
                                      ln2_b + (size_t)l * Dd, 3,
                                      (l == Ll - 1) ? 1 : 0);
    }

    // lm_head: fp16 single-pass (A = x16 written by final addln)
    gemm_mp<2><<<dim3(Mm / TM, VP / TN, 1), 256, GEMM_SMEM>>>(
        (const __nv_bfloat16*)px16, nullptr, Dd,
        (const __nv_bfloat16*)plmh, nullptr, VP,
        lm_b, out, nullptr, nullptr, Vv, Vv, Dd, 0, 0);
}

// round 12
// speedup vs baseline: 1.8091x; 1.0312x over previous
#include <cuda_runtime.h>
#include <cuda_bf16.h>
#include <cuda_fp16.h>
#include <cstdint>
#include <math.h>
#include <stddef.h>

// Problem constants
#define Bq 2
#define Tt 1024
#define Dd 768
#define Hh 12
#define Ll 6
#define Vv 50257
#define VP 50304
#define HS 64
#define Mm (Bq*Tt)
#define DFF (4*Dd)
#define NQKV (3*Dd)

// GEMM tiling
#define TM 128
#define TN 128
#define BK 32
#define SA_STRIDE 40
#define SB_STRIDE 136
#define OFF_AH 0
#define OFF_AL 10240
#define OFF_BH 20480
#define OFF_BL 29184
#define STAGE_BYTES 37888
#define GEMM_SMEM (2*STAGE_BYTES)

// Flash attention tiling
#define FBM 64
#define FBN 64
#define FST_KH 0
#define FST_KL 9216
#define FST_VH 18432
#define FST_VL 27648
#define FSTAGE 36864
#define FLASH_SMEM (2*FSTAGE)

// ---------------- scratch --------------------------------------------------
__device__ float g_x  [Mm*Dd];
__device__ float g_tmp[(size_t)3*Mm*Dd];     // up to 3 split-K partials

__device__ __nv_bfloat16 x_h [Mm*Dd],  x_l [Mm*Dd];
__device__ __half        x16 [Mm*Dd];
__device__ __nv_bfloat16 o_h [Mm*Dd],  o_l [Mm*Dd];
__device__ __nv_bfloat16 h1_h[(size_t)Mm*DFF], h1_l[(size_t)Mm*DFF];
__device__ __nv_bfloat16 qkvp_h[(size_t)Mm*NQKV], qkvp_l[(size_t)Mm*NQKV];

__device__ __half        wqkv16_h[(size_t)Ll*Dd*NQKV], wqkv16_l[(size_t)Ll*Dd*NQKV];
__device__ __nv_bfloat16 wpr_h [(size_t)Ll*Dd*Dd],   wpr_l [(size_t)Ll*Dd*Dd];
__device__ __nv_bfloat16 w1b_h [(size_t)Ll*Dd*DFF],  w1b_l [(size_t)Ll*Dd*DFF];
__device__ __nv_bfloat16 w2b_h [(size_t)Ll*DFF*Dd],  w2b_l [(size_t)Ll*DFF*Dd];
__device__ __half        lmw16_h[(size_t)Dd*VP];

// ---------------- helpers --------------------------------------------------
__device__ __forceinline__ uint32_t s2u(const void* p) {
    uint32_t a;
    asm("{ .reg .u64 t; cvta.to.shared.u64 t, %1; cvt.u32.u64 %0, t; }" : "=r"(a) : "l"(p));
    return a;
}
__device__ __forceinline__ void cpa16(uint32_t dst, const void* src) {
    asm volatile("cp.async.cg.shared.global [%0], [%1], 16;" :: "r"(dst), "l"(src));
}
__device__ __forceinline__ void ldmx4(uint32_t* r, uint32_t addr) {
    asm volatile("ldmatrix.sync.aligned.m8n8.x4.shared.b16 {%0,%1,%2,%3},[%4];"
                 : "=r"(r[0]), "=r"(r[1]), "=r"(r[2]), "=r"(r[3]) : "r"(addr));
}
__device__ __forceinline__ void ldmx4t(uint32_t* r, uint32_t addr) {
    asm volatile("ldmatrix.sync.aligned.m8n8.x4.trans.shared.b16 {%0,%1,%2,%3},[%4];"
                 : "=r"(r[0]), "=r"(r[1]), "=r"(r[2]), "=r"(r[3]) : "r"(addr));
}
__device__ __forceinline__ void mma_bf16(float* c, const uint32_t* a,
                                         uint32_t b0, uint32_t b1) {
    asm volatile(
        "mma.sync.aligned.m16n8k16.row.col.f32.bf16.bf16.f32 "
        "{%0,%1,%2,%3},{%4,%5,%6,%7},{%8,%9},{%0,%1,%2,%3};"
        : "+f"(c[0]), "+f"(c[1]), "+f"(c[2]), "+f"(c[3])
        : "r"(a[0]), "r"(a[1]), "r"(a[2]), "r"(a[3]), "r"(b0), "r"(b1));
}
__device__ __forceinline__ void mma_f16(float* c, const uint32_t* a,
                                        uint32_t b0, uint32_t b1) {
    asm volatile(
        "mma.sync.aligned.m16n8k16.row.col.f32.f16.f16.f32 "
        "{%0,%1,%2,%3},{%4,%5,%6,%7},{%8,%9},{%0,%1,%2,%3};"
        : "+f"(c[0]), "+f"(c[1]), "+f"(c[2]), "+f"(c[3])
        : "r"(a[0]), "r"(a[1]), "r"(a[2]), "r"(a[3]), "r"(b0), "r"(b1));
}
__device__ __forceinline__ void splitv(float v, __nv_bfloat16& h, __nv_bfloat16& l) {
    h = __float2bfloat16_rn(v);
    l = __float2bfloat16_rn(v - __bfloat162float(h));
}
__device__ __forceinline__ uint32_t pk(__nv_bfloat16 a, __nv_bfloat16 b) {
    return ((uint32_t)__bfloat16_as_ushort(b) << 16) | __bfloat16_as_ushort(a);
}
__device__ __forceinline__ uint32_t pkh(__half a, __half b) {
    return ((uint32_t)__half_as_ushort(b) << 16) | __half_as_ushort(a);
}
__device__ __forceinline__ void split4(float4 v, uint2& h, uint2& l) {
    __nv_bfloat16 h0, h1, h2, h3, l0, l1, l2, l3;
    splitv(v.x, h0, l0); splitv(v.y, h1, l1);
    splitv(v.z, h2, l2); splitv(v.w, h3, l3);
    h = make_uint2(pk(h0, h1), pk(h2, h3));
    l = make_uint2(pk(l0, l1), pk(l2, l3));
}
__device__ __forceinline__ void split4h(float4 v, uint2& h, uint2& l) {
    __half h0 = __float2half_rn(v.x), h1 = __float2half_rn(v.y);
    __half h2 = __float2half_rn(v.z), h3 = __float2half_rn(v.w);
    __half l0 = __float2half_rn(v.x - __half2float(h0));
    __half l1 = __float2half_rn(v.y - __half2float(h1));
    __half l2 = __float2half_rn(v.z - __half2float(h2));
    __half l3 = __float2half_rn(v.w - __half2float(h3));
    h = make_uint2(pkh(h0, h1), pkh(h2, h3));
    l = make_uint2(pkh(l0, l1), pkh(l2, l3));
}

// ---------------- weight conversion ----------------------------------------
__global__ void split_flat(const float4* __restrict__ src,
                           uint2* __restrict__ h,
                           uint2* __restrict__ l, unsigned n4) {
    unsigned stride = gridDim.x * blockDim.x;
    for (unsigned i = blockIdx.x * blockDim.x + threadIdx.x; i < n4; i += 2 * stride) {
        unsigned j = i + stride;
        float4 a = src[i];
        float4 b;
        bool has2 = (j < n4);
        if (has2) b = src[j];
        uint2 ha, la;
        split4(a, ha, la);
        h[i] = ha; l[i] = la;
        if (has2) {
            uint2 hb, lb;
            split4(b, hb, lb);
            h[j] = hb; l[j] = lb;
        }
    }
}

__device__ __forceinline__ void qkv_one(const float* __restrict__ wq,
                                        const float* __restrict__ wk,
                                        const float* __restrict__ wv,
                                        unsigned i4) {
    unsigned e = i4 * 4u;
    unsigned l = e / (unsigned)(Dd * NQKV);
    unsigned r = e - l * (unsigned)(Dd * NQKV);
    unsigned k = r / (unsigned)NQKV;
    unsigned n = r - k * (unsigned)NQKV;
    unsigned wsel = n / (unsigned)Dd;
    unsigned r2 = n - wsel * (unsigned)Dd;
    unsigned hh = r2 >> 6, s = r2 & 63;
    const float* base = (wsel == 0) ? wq : ((wsel == 1) ? wk : wv);
    float4 v = *(const float4*)(base + ((size_t)(l * Hh + hh) * Dd + k) * HS + s);
    uint2 hp, lp;
    split4h(v, hp, lp);
    ((uint2*)wqkv16_h)[i4] = hp;
    ((uint2*)wqkv16_l)[i4] = lp;
}
__global__ void conv_qkv(const float* __restrict__ wq,
                         const float* __restrict__ wk,
                         const float* __restrict__ wv) {
    const unsigned total4 = (unsigned)Ll * Dd * NQKV / 4u;
    unsigned stride = gridDim.x * blockDim.x;
    for (unsigned i = blockIdx.x * blockDim.x + threadIdx.x; i < total4; i += 2 * stride) {
        qkv_one(wq, wk, wv, i);
        if (i + stride < total4) qkv_one(wq, wk, wv, i + stride);
    }
}

__device__ __forceinline__ void lm_one(const float* __restrict__ lm_w, unsigned i4) {
    unsigned e = i4 * 4u;
    unsigned k = e / (unsigned)VP;
    unsigned n = e - k * (unsigned)VP;
    const float* row = lm_w + (size_t)k * Vv;
    float4 v;
    v.x = (n     < Vv) ? row[n]     : 0.f;
    v.y = (n + 1 < Vv) ? row[n + 1] : 0.f;
    v.z = (n + 2 < Vv) ? row[n + 2] : 0.f;
    v.w = (n + 3 < Vv) ? row[n + 3] : 0.f;
    uint2 hp;
    hp.x = pkh(__float2half_rn(v.x), __float2half_rn(v.y));
    hp.y = pkh(__float2half_rn(v.z), __float2half_rn(v.w));
    ((uint2*)lmw16_h)[i4] = hp;
}
__global__ void conv_lm(const float* __restrict__ lm_w) {
    const unsigned total4 = (unsigned)Dd * VP / 4u;
    unsigned stride = gridDim.x * blockDim.x;
    for (unsigned i = blockIdx.x * blockDim.x + threadIdx.x; i < total4; i += 2 * stride) {
        lm_one(lm_w, i);
        if (i + stride < total4) lm_one(lm_w, i + stride);
    }
}

// ---------------- templated tensor-core GEMM (cp.async double-buffered) ----
// MODE 0: bf16 3-pass (AhBh + AhBl + AlBh).
// MODE 2: fp16 single-pass (AhBh only).
// MODE 3: fp16 2-pass (A hi only, B hi/lo: AhBh + AhBl).
// Split-K: blockIdx.z = K-chunk; partials to Cf + z*Mm*ldc, bias on chunk 0.
template<int MODE>
__global__ __launch_bounds__(256, 2) void gemm_mp(
    const __nv_bfloat16* __restrict__ Ah_g, const __nv_bfloat16* __restrict__ Al_g,
    int lda,
    const __nv_bfloat16* __restrict__ Bh_g, const __nv_bfloat16* __restrict__ Bl_g,
    int ldb,
    const float* __restrict__ bias,
    float* __restrict__ Cf,
    __nv_bfloat16* __restrict__ Ch, __nv_bfloat16* __restrict__ Cl,
    int ldc, int N, int K, int relu, int outmode)
{
    extern __shared__ char smem[];
    const uint32_t sb = s2u(smem);
    const int tid = threadIdx.x;
    const int wid = tid >> 5, lane = tid & 31;
    const int m0 = blockIdx.x * TM;
    const int n0 = blockIdx.y * TN;
    const int kz = blockIdx.z;
    const int mw = (wid & 3) * 32;
    const int nw = (wid >> 2) * 64;

    Ah_g += (size_t)kz * K;
    if (MODE == 0) Al_g += (size_t)kz * K;
    Bh_g += (size_t)kz * K * ldb;
    if (MODE == 0 || MODE == 3) Bl_g += (size_t)kz * K * ldb;
    Cf   += (size_t)kz * Mm * ldc;
    const float* biasz = (kz == 0) ? bias : nullptr;

    float acc[2][8][4];
    #pragma unroll
    for (int a = 0; a < 2; a++)
        #pragma unroll
        for (int b = 0; b < 8; b++)
            #pragma unroll
            for (int c = 0; c < 4; c++) acc[a][b][c] = 0.f;

    auto load_stage = [&](int kc, int st) {
        uint32_t base = sb + st * STAGE_BYTES;
        #pragma unroll
        for (int i = 0; i < 2; i++) {
            int c = tid + i * 256;
            int row = c >> 2, q = c & 3;
            uint32_t d = base + OFF_AH + row * 80 + q * 16;
            cpa16(d, Ah_g + (size_t)(m0 + row) * lda + kc + q * 8);
            if (MODE == 0)
                cpa16(d + (OFF_AL - OFF_AH), Al_g + (size_t)(m0 + row) * lda + kc + q * 8);
        }
        #pragma unroll
        for (int i = 0; i < 2; i++) {
            int c = tid + i * 256;
            int row = c >> 4, q = c & 15;
            uint32_t d = base + OFF_BH + row * 272 + q * 16;
            cpa16(d, Bh_g + (size_t)(kc + row) * ldb + n0 + q * 8);
            if (MODE == 0 || MODE == 3)
                cpa16(d + (OFF_BL - OFF_BH), Bl_g + (size_t)(kc + row) * ldb + n0 + q * 8);
        }
        asm volatile("cp.async.commit_group;" ::: "memory");
    };

    const int niter = K / BK;
    load_stage(0, 0);

    for (int it = 0; it < niter; it++) {
        if (it + 1 < niter) {
            load_stage((it + 1) * BK, (it + 1) & 1);
            asm volatile("cp.async.wait_group 1;" ::: "memory");
        } else {
            asm volatile("cp.async.wait_group 0;" ::: "memory");
        }
        __syncthreads();

        const uint32_t sbase = sb + (it & 1) * STAGE_BYTES;
        #pragma unroll
        for (int kk = 0; kk < BK; kk += 16) {
            uint32_t ah[2][4], al[2][4];
            int arow = mw + (lane & 15);
            int acol = kk + (lane >> 4) * 8;
            #pragma unroll
            for (int mi = 0; mi < 2; mi++) {
                uint32_t off = (uint32_t)(arow + mi * 16) * (SA_STRIDE * 2) + acol * 2;
                ldmx4(ah[mi], sbase + OFF_AH + off);
                if (MODE == 0) ldmx4(al[mi], sbase + OFF_AL + off);
            }
            int brow = kk + (lane & 15);
            int bcol = nw + (lane >> 4) * 8;
            #pragma unroll
            for (int ni = 0; ni < 4; ni++) {
                uint32_t off = (uint32_t)brow * (SB_STRIDE * 2) + (bcol + ni * 16) * 2;
                uint32_t bh[4], bl[4];
                ldmx4t(bh, sbase + OFF_BH + off);
                if (MODE == 0 || MODE == 3) ldmx4t(bl, sbase + OFF_BL + off);
                #pragma unroll
                for (int mi = 0; mi < 2; mi++) {
                    if (MODE == 0) {
                        mma_bf16(acc[mi][2 * ni],     ah[mi], bh[0], bh[1]);
                        mma_bf16(acc[mi][2 * ni],     ah[mi], bl[0], bl[1]);
                        mma_bf16(acc[mi][2 * ni],     al[mi], bh[0], bh[1]);
                        mma_bf16(acc[mi][2 * ni + 1], ah[mi], bh[2], bh[3]);
                        mma_bf16(acc[mi][2 * ni + 1], ah[mi], bl[2], bl[3]);
                        mma_bf16(acc[mi][2 * ni + 1], al[mi], bh[2], bh[3]);
                    } else if (MODE == 3) {
                        mma_f16(acc[mi][2 * ni],     ah[mi], bh[0], bh[1]);
                        mma_f16(acc[mi][2 * ni],     ah[mi], bl[0], bl[1]);
                        mma_f16(acc[mi][2 * ni + 1], ah[mi], bh[2], bh[3]);
                        mma_f16(acc[mi][2 * ni + 1], ah[mi], bl[2], bl[3]);
                    } else {
                        mma_f16(acc[mi][2 * ni],     ah[mi], bh[0], bh[1]);
                        mma_f16(acc[mi][2 * ni + 1], ah[mi], bh[2], bh[3]);
                    }
                }
            }
        }
        __syncthreads();
    }

    float* sC = (float*)smem;
    const int r0 = mw + (lane >> 2);
    const int c0 = 2 * (lane & 3);
    #pragma unroll 1
    for (int hf = 0; hf < 2; hf++) {
        if ((wid >> 2) == hf) {
            #pragma unroll
            for (int mi = 0; mi < 2; mi++)
                #pragma unroll
                for (int ni = 0; ni < 8; ni++) {
                    int rr = (r0 + mi * 16) * 68 + ni * 8 + c0;
                    sC[rr]              = acc[mi][ni][0];
                    sC[rr + 1]          = acc[mi][ni][1];
                    sC[rr + 8 * 68]     = acc[mi][ni][2];
                    sC[rr + 8 * 68 + 1] = acc[mi][ni][3];
                }
        }
        __syncthreads();
        #pragma unroll 4
        for (int it = 0; it < 32; it++) {
            int idx = tid + it * 256;
            int r = idx >> 6, c = idx & 63;
            int col = n0 + hf * 64 + c;
            if (col < N) {
                float v = sC[r * 68 + c];
                if (biasz) v += biasz[col];
                if (relu) v = fmaxf(v, 0.f);
                if (outmode == 0) {
                    Cf[(size_t)(m0 + r) * ldc + col] = v;
                } else {
                    __nv_bfloat16 hh, ll;
                    splitv(v, hh, ll);
                    Ch[(size_t)(m0 + r) * ldc + col] = hh;
                    Cl[(size_t)(m0 + r) * ldc + col] = ll;
                }
            }
        }
        __syncthreads();
    }
}

// ---------------- flash attention (bf16x3, causal, online softmax) ---------
__global__ __launch_bounds__(128) void flash_kernel() {
    extern __shared__ char smem[];
    const uint32_t sb = s2u(smem);
    const int tid = threadIdx.x, wid = tid >> 5, lane = tid & 31;
    const int bh = blockIdx.y;
    const int b = bh / Hh, h = bh % Hh;
    const int t0 = (int)(gridDim.x - 1 - blockIdx.x) * FBM;
    const int mw = wid * 16;

    const size_t rowbase = (size_t)(b * Tt) * NQKV + h * HS;

    #pragma unroll
    for (int i = 0; i < 4; i++) {
        int c = tid + i * 128;
        int row = c >> 3, q = c & 7;
        size_t g = rowbase + (size_t)(t0 + row) * NQKV + q * 8;
        cpa16(sb + row * 144 + q * 16, qkvp_h + g);
        cpa16(sb + 9216 + row * 144 + q * 16, qkvp_l + g);
    }
    asm volatile("cp.async.commit_group;" ::: "memory");
    asm volatile("cp.async.wait_group 0;" ::: "memory");
    __syncthreads();

    uint32_t qfh[4][4], qfl[4][4];
    {
        int arow = mw + (lane & 15);
        #pragma unroll
        for (int kk = 0; kk < 4; kk++) {
            int acol = kk * 16 + (lane >> 4) * 8;
            uint32_t off = (uint32_t)arow * 144 + acol * 2;
            ldmx4(qfh[kk], sb + off);
            ldmx4(qfl[kk], sb + 9216 + off);
        }
    }
    __syncthreads();

    auto kv_issue = [&](int u0, int st) {
        uint32_t base = sb + st * FSTAGE;
        #pragma unroll
        for (int i = 0; i < 4; i++) {
            int c = tid + i * 128;
            int row = c >> 3, q = c & 7;
            size_t g = rowbase + (size_t)(u0 + row) * NQKV + q * 8;
            uint32_t d = base + row * 144 + q * 16;
            cpa16(d + FST_KH, qkvp_h + g + Dd);
            cpa16(d + FST_KL, qkvp_l + g + Dd);
            cpa16(d + FST_VH, qkvp_h + g + 2 * Dd);
            cpa16(d + FST_VL, qkvp_l + g + 2 * Dd);
        }
        asm volatile("cp.async.commit_group;" ::: "memory");
    };

    float o[8][4];
    #pragma unroll
    for (int i = 0; i < 8; i++)
        #pragma unroll
        for (int j = 0; j < 4; j++) o[i][j] = 0.f;
    float mA = -1e30f, mB = -1e30f, lA = 0.f, lB = 0.f;

    const int nt = t0 / FBN + 1;
    kv_issue(0, 1);

    for (int it = 0; it < nt; it++) {
        const int u0 = it * FBN;
        if (it + 1 < nt) {
            kv_issue((it + 1) * FBN, it & 1);
            asm volatile("cp.async.wait_group 1;" ::: "memory");
        } else {
            asm volatile("cp.async.wait_group 0;" ::: "memory");
        }
        __syncthreads();
        const uint32_t kb = sb + ((it + 1) & 1) * FSTAGE;

        float s[8][4];
        #pragma unroll
        for (int i = 0; i < 8; i++)
            #pragma unroll
            for (int j = 0; j < 4; j++) s[i][j] = 0.f;

        const int bn = ((lane >> 4) << 3) + (lane & 7);
        const int bk = ((lane >> 3) & 1) * 8;
        #pragma unroll
        for (int kk = 0; kk < 4; kk++) {
            #pragma unroll
            for (int j = 0; j < 4; j++) {
                uint32_t addr = kb + (uint32_t)(j * 16 + bn) * 144 + (kk * 16 + bk) * 2;
                uint32_t kh4[4], kl4[4];
                ldmx4(kh4, addr + FST_KH);
                ldmx4(kl4, addr + FST_KL);
                mma_bf16(s[2 * j],     qfh[kk], kh4[0], kh4[1]);
                mma_bf16(s[2 * j],     qfh[kk], kl4[0], kl4[1]);
                mma_bf16(s[2 * j],     qfl[kk], kh4[0], kh4[1]);
                mma_bf16(s[2 * j + 1], qfh[kk], kh4[2], kh4[3]);
                mma_bf16(s[2 * j + 1], qfh[kk], kl4[2], kl4[3]);
                mma_bf16(s[2 * j + 1], qfl[kk], kh4[2], kh4[3]);
            }
        }

        const int rA = lane >> 2;
        const int tA = t0 + mw + rA, tB = tA + 8;
        #pragma unroll
        for (int nb = 0; nb < 8; nb++)
            #pragma unroll
            for (int j = 0; j < 4; j++) s[nb][j] *= 0.125f;
        if (u0 + FBN - 1 > t0 + mw) {
            #pragma unroll
            for (int nb = 0; nb < 8; nb++) {
                int u_lo = u0 + nb * 8 + (lane & 3) * 2;
                if (u_lo     > tA) s[nb][0] = -1e30f;
                if (u_lo + 1 > tA) s[nb][1] = -1e30f;
                if (u_lo     > tB) s[nb][2] = -1e30f;
                if (u_lo + 1 > tB) s[nb][3] = -1e30f;
            }
        }

        float rmA = -1e30f, rmB = -1e30f;
        #pragma unroll
        for (int nb = 0; nb < 8; nb++) {
            rmA = fmaxf(rmA, fmaxf(s[nb][0], s[nb][1]));
            rmB = fmaxf(rmB, fmaxf(s[nb][2], s[nb][3]));
        }
        rmA = fmaxf(rmA, __shfl_xor_sync(0xffffffffu, rmA, 1));
        rmA = fmaxf(rmA, __shfl_xor_sync(0xffffffffu, rmA, 2));
        rmB = fmaxf(rmB, __shfl_xor_sync(0xffffffffu, rmB, 1));
        rmB = fmaxf(rmB, __shfl_xor_sync(0xffffffffu, rmB, 2));
        float mAn = fmaxf(mA, rmA), mBn = fmaxf(mB, rmB);
        float scA = __expf(mA - mAn), scB = __expf(mB - mBn);
        mA = mAn; mB = mBn;

        float rsA = 0.f, rsB = 0.f;
        #pragma unroll
        for (int nb = 0; nb < 8; nb++) {
            s[nb][0] = __expf(s[nb][0] - mA); rsA += s[nb][0];
            s[nb][1] = __expf(s[nb][1] - mA); rsA += s[nb][1];
            s[nb][2] = __expf(s[nb][2] - mB); rsB += s[nb][2];
            s[nb][3] = __expf(s[nb][3] - mB); rsB += s[nb][3];
        }
        rsA += __shfl_xor_sync(0xffffffffu, rsA, 1);
        rsA += __shfl_xor_sync(0xffffffffu, rsA, 2);
        rsB += __shfl_xor_sync(0xffffffffu, rsB, 1);
        rsB += __shfl_xor_sync(0xffffffffu, rsB, 2);
        lA = lA * scA + rsA;
        lB = lB * scB + rsB;
        #pragma unroll
        for (int nb = 0; nb < 8; nb++) {
            o[nb][0] *= scA; o[nb][1] *= scA;
            o[nb][2] *= scB; o[nb][3] *= scB;
        }

        #pragma unroll
        for (int g = 0; g < 4; g++) {
            uint32_t pha[4], pla[4];
            {
                __nv_bfloat16 h0, h1, l0, l1;
                splitv(s[2 * g][0], h0, l0); splitv(s[2 * g][1], h1, l1);
                pha[0] = pk(h0, h1); pla[0] = pk(l0, l1);
                splitv(s[2 * g][2], h0, l0); splitv(s[2 * g][3], h1, l1);
                pha[1] = pk(h0, h1); pla[1] = pk(l0, l1);
                splitv(s[2 * g + 1][0], h0, l0); splitv(s[2 * g + 1][1], h1, l1);
                pha[2] = pk(h0, h1); pla[2] = pk(l0, l1);
                splitv(s[2 * g + 1][2], h0, l0); splitv(s[2 * g + 1][3], h1, l1);
                pha[3] = pk(h0, h1); pla[3] = pk(l0, l1);
            }
            const int vrow = g * 16 + (lane & 15);
            #pragma unroll
            for (int j = 0; j < 4; j++) {
                uint32_t addr = kb + (uint32_t)vrow * 144 +
                                (uint32_t)(j * 16 + (lane >> 4) * 8) * 2;
                uint32_t vh4[4], vl4[4];
                ldmx4t(vh4, addr + FST_VH);
                ldmx4t(vl4, addr + FST_VL);
                mma_bf16(o[2 * j],     pha, vh4[0], vh4[1]);
                mma_bf16(o[2 * j],     pha, vl4[0], vl4[1]);
                mma_bf16(o[2 * j],     pla, vh4[0], vh4[1]);
                mma_bf16(o[2 * j + 1], pha, vh4[2], vh4[3]);
                mma_bf16(o[2 * j + 1], pha, vl4[2], vl4[3]);
                mma_bf16(o[2 * j + 1], pla, vh4[2], vh4[3]);
            }
        }
        __syncthreads();
    }

    const float invA = 1.f / lA, invB = 1.f / lB;
    const int rA = lane >> 2;
    const int tA = t0 + mw + rA, tB = tA + 8;
    const int cbase = h * HS + (lane & 3) * 2;
    size_t baseA = (size_t)(b * Tt + tA) * Dd + cbase;
    size_t baseB = (size_t)(b * Tt + tB) * Dd + cbase;
    #pragma unroll
    for (int nb = 0; nb < 8; nb++) {
        splitv(o[nb][0] * invA, o_h[baseA + nb * 8],     o_l[baseA + nb * 8]);
        splitv(o[nb][1] * invA, o_h[baseA + nb * 8 + 1], o_l[baseA + nb * 8 + 1]);
        splitv(o[nb][2] * invB, o_h[baseB + nb * 8],     o_l[baseB + nb * 8]);
        splitv(o[nb][3] * invB, o_h[baseB + nb * 8 + 1], o_l[baseB + nb * 8 + 1]);
    }
}

// ---------------- embedding -------------------------------------------------
__global__ void embed_kernel(const int* __restrict__ idx,
                             const float* __restrict__ tok_emb,
                             const float* __restrict__ pos_emb) {
    int m = blockIdx.x;
    int t = m % Tt;
    int tok = idx[m];
    const float* te = tok_emb + (size_t)tok * Dd;
    const float* pe = pos_emb + (size_t)t * Dd;
    float* x = g_x + (size_t)m * Dd;
    for (int c = threadIdx.x; c < Dd; c += blockDim.x) {
        float v = te[c] + pe[c];
        x[c] = v;
        splitv(v, x_h[(size_t)m * Dd + c], x_l[(size_t)m * Dd + c]);
        x16[(size_t)m * Dd + c] = __float2half_rn(v);
    }
}

// ---------------- fused residual add + LayerNorm (warp per row) ------------
__global__ void addln_kernel(const float* __restrict__ tmp,
                             const float* __restrict__ gamma,
                             const float* __restrict__ beta,
                             int nparts) {
    int row = blockIdx.x * (blockDim.x >> 5) + (threadIdx.x >> 5);
    int lane = threadIdx.x & 31;
    float* x = g_x + (size_t)row * Dd;
    const float* a0 = tmp + (size_t)row * Dd;

    float v[24];
    float s = 0.f;
    #pragma unroll
    for (int i = 0; i < 24; i++) {
        int c = lane + i * 32;
        float t = x[c] + a0[c];
        if (nparts > 1) t += a0[(size_t)Mm * Dd + c];
        if (nparts > 2) t += a0[(size_t)2 * Mm * Dd + c];
        v[i] = t;
        s += t;
    }
    #pragma unroll
    for (int o = 16; o > 0; o >>= 1) s += __shfl_xor_sync(0xffffffffu, s, o);
    float mean = s * (1.f / Dd);

    float q = 0.f;
    #pragma unroll
    for (int i = 0; i < 24; i++) {
        float d = v[i] - mean;
        q += d * d;
    }
    #pragma unroll
    for (int o = 16; o > 0; o >>= 1) q += __shfl_xor_sync(0xffffffffu, q, o);
    float rstd = rsqrtf(q * (1.f / Dd) + 1e-5f);

    #pragma unroll
    for (int i = 0; i < 24; i++) {
        int c = lane + i * 32;
        float ov = (v[i] - mean) * rstd * gamma[c] + beta[c];
        x[c] = ov;
        splitv(ov, x_h[(size_t)row * Dd + c], x_l[(size_t)row * Dd + c]);
        x16[(size_t)row * Dd + c] = __float2half_rn(ov);
    }
}

// ---------------- host orchestration ----------------------------------------
extern "C" void kernel_launch(void* const* d_in, const int* in_sizes, int n_in,
                              void* d_out, int out_size) {
    const int*   idx     = (const int*)  d_in[0];
    const float* tok_emb = (const float*)d_in[1];
    const float* pos_emb = (const float*)d_in[2];
    const float* wq      = (const float*)d_in[3];
    const float* wk      = (const float*)d_in[4];
    const float* wv      = (const float*)d_in[5];
    const float* wproj   = (const float*)d_in[6];
    const float* bproj   = (const float*)d_in[7];
    const float* w1      = (const float*)d_in[8];
    const float* b1      = (const float*)d_in[9];
    const float* w2      = (const float*)d_in[10];
    const float* b2      = (const float*)d_in[11];
    const float* ln1_g   = (const float*)d_in[12];
    const float* ln1_b   = (const float*)d_in[13];
    const float* ln2_g   = (const float*)d_in[14];
    const float* ln2_b   = (const float*)d_in[15];
    const float* lm_w    = (const float*)d_in[16];
    const float* lm_b    = (const float*)d_in[17];
    float* out = (float*)d_out;

    cudaFuncSetAttribute(gemm_mp<0>, cudaFuncAttributeMaxDynamicSharedMemorySize, GEMM_SMEM);
    cudaFuncSetAttribute(gemm_mp<2>, cudaFuncAttributeMaxDynamicSharedMemorySize, GEMM_SMEM);
    cudaFuncSetAttribute(gemm_mp<3>, cudaFuncAttributeMaxDynamicSharedMemorySize, GEMM_SMEM);
    cudaFuncSetAttribute(flash_kernel, cudaFuncAttributeMaxDynamicSharedMemorySize, FLASH_SMEM);

    float *p_x, *p_tmp;
    cudaGetSymbolAddress((void**)&p_x,   g_x);
    cudaGetSymbolAddress((void**)&p_tmp, g_tmp);
    __nv_bfloat16 *pxh, *pxl, *poh, *pol, *ph1h, *ph1l, *pqh, *pql;
    cudaGetSymbolAddress((void**)&pxh, x_h);   cudaGetSymbolAddress((void**)&pxl, x_l);
    cudaGetSymbolAddress((void**)&poh, o_h);   cudaGetSymbolAddress((void**)&pol, o_l);
    cudaGetSymbolAddress((void**)&ph1h, h1_h); cudaGetSymbolAddress((void**)&ph1l, h1_l);
    cudaGetSymbolAddress((void**)&pqh, qkvp_h); cudaGetSymbolAddress((void**)&pql, qkvp_l);
    __nv_bfloat16 *pwph, *pwpl, *pw1h, *pw1l, *pw2h, *pw2l;
    cudaGetSymbolAddress((void**)&pwph, wpr_h);  cudaGetSymbolAddress((void**)&pwpl, wpr_l);
    cudaGetSymbolAddress((void**)&pw1h, w1b_h);  cudaGetSymbolAddress((void**)&pw1l, w1b_l);
    cudaGetSymbolAddress((void**)&pw2h, w2b_h);  cudaGetSymbolAddress((void**)&pw2l, w2b_l);
    __half *pwq16h, *pwq16l, *plmh, *px16;
    cudaGetSymbolAddress((void**)&pwq16h, wqkv16_h);
    cudaGetSymbolAddress((void**)&pwq16l, wqkv16_l);
    cudaGetSymbolAddress((void**)&plmh, lmw16_h);
    cudaGetSymbolAddress((void**)&px16, x16);

    conv_qkv<<<1024, 256>>>(wq, wk, wv);
    split_flat<<<512, 256>>>((const float4*)wproj, (uint2*)pwph, (uint2*)pwpl,
                             (unsigned)(Ll * Dd * Dd / 4));
    split_flat<<<1024, 256>>>((const float4*)w1, (uint2*)pw1h, (uint2*)pw1l,
                              (unsigned)(Ll * Dd * DFF / 4));
    split_flat<<<1024, 256>>>((const float4*)w2, (uint2*)pw2h, (uint2*)pw2l,
                              (unsigned)(Ll * DFF * Dd / 4));
    conv_lm<<<2048, 256>>>(lm_w);

    embed_kernel<<<Mm, 256>>>(idx, tok_emb, pos_emb);

    for (int l = 0; l < Ll; l++) {
        // QKV: fp16 2-pass (A = x16 hi, B = fp16 hi/lo) -> bf16 pair out
        gemm_mp<3><<<dim3(Mm / TM, NQKV / TN, 1), 256, GEMM_SMEM>>>(
            (const __nv_bfloat16*)px16, nullptr, Dd,
            (const __nv_bfloat16*)(pwq16h + (size_t)l * Dd * NQKV),
            (const __nv_bfloat16*)(pwq16l + (size_t)l * Dd * NQKV), NQKV,
            nullptr, nullptr, pqh, pql, NQKV, NQKV, Dd, 0, 1);
        flash_kernel<<<dim3(Tt / FBM, Bq * Hh), 128, FLASH_SMEM>>>();
        // proj: bf16x3 split-K=3
        gemm_mp<0><<<dim3(Mm / TM, Dd / TN, 3), 256, GEMM_SMEM>>>(
            poh, pol, Dd,
            pwph + (size_t)l * Dd * Dd, pwpl + (size_t)l * Dd * Dd, Dd,
            bproj + (size_t)l * Dd, p_tmp, nullptr, nullptr, Dd, Dd, Dd / 3, 0, 0);
        addln_kernel<<<Mm / 8, 256>>>(p_tmp, ln1_g + (size_t)l * Dd,
                                      ln1_b + (size_t)l * Dd, 3);
        // fc1: bf16x3 -> bf16 pair + relu
        gemm_mp<0><<<dim3(Mm / TM, DFF / TN, 1), 256, GEMM_SMEM>>>(
            pxh, pxl, Dd,
            pw1h + (size_t)l * Dd * DFF, pw1l + (size_t)l * Dd * DFF, DFF,
            b1 + (size_t)l * DFF, nullptr, ph1h, ph1l, DFF, DFF, Dd, 1, 1);
        // fc2: bf16x3 split-K=3
        gemm_mp<0><<<dim3(Mm / TM, Dd / TN, 3), 256, GEMM_SMEM>>>(
            ph1h, ph1l, DFF,
            pw2h + (size_t)l * DFF * Dd, pw2l + (size_t)l * DFF * Dd, Dd,
            b2 + (size_t)l * Dd, p_tmp, nullptr, nullptr, Dd, Dd, DFF / 3, 0, 0);
        addln_kernel<<<Mm / 8, 256>>>(p_tmp, ln2_g + (size_t)l * Dd,
                                      ln2_b + (size_t)l * Dd, 3);
    }

    // lm_head: fp16 single-pass (A = x16)
    gemm_mp<2><<<dim3(Mm / TM, VP / TN, 1), 256, GEMM_SMEM>>>(
        (const __nv_bfloat16*)px16, nullptr, Dd,
        (const __nv_bfloat16*)plmh, nullptr, VP,
        lm_b, out, nullptr, nullptr, Vv, Vv, Dd, 0, 0);
}

// round 14
// speedup vs baseline: 2.0416x; 1.1285x over previous
#include <cuda_runtime.h>
#include <cuda_bf16.h>
#include <cuda_fp16.h>
#include <cstdint>
#include <math.h>
#include <stddef.h>

// Problem constants
#define Bq 2
#define Tt 1024
#define Dd 768
#define Hh 12
#define Ll 6
#define Vv 50257
#define VP 50304
#define HS 64
#define Mm (Bq*Tt)
#define DFF (4*Dd)
#define NQKV (3*Dd)

// GEMM tiling
#define TM 128
#define TN 128
#define BK 32
#define SA_STRIDE 40
#define SB_STRIDE 136
#define OFF_AH 0
#define OFF_AL 10240
#define OFF_BH 20480
#define OFF_BL 29184
#define STAGE_BYTES 37888
#define GEMM_SMEM (2*STAGE_BYTES)

// Flash attention tiling
#define FBM 64
#define FBN 64
#define FST_KH 0
#define FST_KL 9216
#define FST_VH 18432
#define FST_VL 27648
#define FSTAGE 36864
#define FLASH_SMEM (2*FSTAGE)

// ---------------- scratch --------------------------------------------------
__device__ float g_x  [Mm*Dd];
__device__ float g_tmp[(size_t)3*Mm*Dd];     // up to 3 split-K partials

__device__ __half        x16 [Mm*Dd];
__device__ __nv_bfloat16 o_h [Mm*Dd],  o_l [Mm*Dd];
__device__ __half        h1f16[(size_t)Mm*DFF];
__device__ __nv_bfloat16 qkvp_h[(size_t)Mm*NQKV], qkvp_l[(size_t)Mm*NQKV];

__device__ __half        wqkv16_h[(size_t)Ll*Dd*NQKV], wqkv16_l[(size_t)Ll*Dd*NQKV];
__device__ __nv_bfloat16 wpr_h [(size_t)Ll*Dd*Dd],   wpr_l [(size_t)Ll*Dd*Dd];
__device__ __half        w1f16_h[(size_t)Ll*Dd*DFF], w1f16_l[(size_t)Ll*Dd*DFF];
__device__ __half        w2f16_h[(size_t)Ll*DFF*Dd], w2f16_l[(size_t)Ll*DFF*Dd];
__device__ __half        lmw16_h[(size_t)Dd*VP];

// ---------------- helpers --------------------------------------------------
__device__ __forceinline__ uint32_t s2u(const void* p) {
    uint32_t a;
    asm("{ .reg .u64 t; cvta.to.shared.u64 t, %1; cvt.u32.u64 %0, t; }" : "=r"(a) : "l"(p));
    return a;
}
__device__ __forceinline__ void cpa16(uint32_t dst, const void* src) {
    asm volatile("cp.async.cg.shared.global [%0], [%1], 16;" :: "r"(dst), "l"(src));
}
__device__ __forceinline__ void ldmx4(uint32_t* r, uint32_t addr) {
    asm volatile("ldmatrix.sync.aligned.m8n8.x4.shared.b16 {%0,%1,%2,%3},[%4];"
                 : "=r"(r[0]), "=r"(r[1]), "=r"(r[2]), "=r"(r[3]) : "r"(addr));
}
__device__ __forceinline__ void ldmx4t(uint32_t* r, uint32_t addr) {
    asm volatile("ldmatrix.sync.aligned.m8n8.x4.trans.shared.b16 {%0,%1,%2,%3},[%4];"
                 : "=r"(r[0]), "=r"(r[1]), "=r"(r[2]), "=r"(r[3]) : "r"(addr));
}
__device__ __forceinline__ void mma_bf16(float* c, const uint32_t* a,
                                         uint32_t b0, uint32_t b1) {
    asm volatile(
        "mma.sync.aligned.m16n8k16.row.col.f32.bf16.bf16.f32 "
        "{%0,%1,%2,%3},{%4,%5,%6,%7},{%8,%9},{%0,%1,%2,%3};"
        : "+f"(c[0]), "+f"(c[1]), "+f"(c[2]), "+f"(c[3])
        : "r"(a[0]), "r"(a[1]), "r"(a[2]), "r"(a[3]), "r"(b0), "r"(b1));
}
__device__ __forceinline__ void mma_f16(float* c, const uint32_t* a,
                                        uint32_t b0, uint32_t b1) {
    asm volatile(
        "mma.sync.aligned.m16n8k16.row.col.f32.f16.f16.f32 "
        "{%0,%1,%2,%3},{%4,%5,%6,%7},{%8,%9},{%0,%1,%2,%3};"
        : "+f"(c[0]), "+f"(c[1]), "+f"(c[2]), "+f"(c[3])
        : "r"(a[0]), "r"(a[1]), "r"(a[2]), "r"(a[3]), "r"(b0), "r"(b1));
}
__device__ __forceinline__ void splitv(float v, __nv_bfloat16& h, __nv_bfloat16& l) {
    h = __float2bfloat16_rn(v);
    l = __float2bfloat16_rn(v - __bfloat162float(h));
}
__device__ __forceinline__ uint32_t pk(__nv_bfloat16 a, __nv_bfloat16 b) {
    return ((uint32_t)__bfloat16_as_ushort(b) << 16) | __bfloat16_as_ushort(a);
}
__device__ __forceinline__ uint32_t pkh(__half a, __half b) {
    return ((uint32_t)__half_as_ushort(b) << 16) | __half_as_ushort(a);
}
__device__ __forceinline__ void split4(float4 v, uint2& h, uint2& l) {
    __nv_bfloat16 h0, h1, h2, h3, l0, l1, l2, l3;
    splitv(v.x, h0, l0); splitv(v.y, h1, l1);
    splitv(v.z, h2, l2); splitv(v.w, h3, l3);
    h = make_uint2(pk(h0, h1), pk(h2, h3));
    l = make_uint2(pk(l0, l1), pk(l2, l3));
}
__device__ __forceinline__ void split4h(float4 v, uint2& h, uint2& l) {
    __half h0 = __float2half_rn(v.x), h1 = __float2half_rn(v.y);
    __half h2 = __float2half_rn(v.z), h3 = __float2half_rn(v.w);
    __half l0 = __float2half_rn(v.x - __half2float(h0));
    __half l1 = __float2half_rn(v.y - __half2float(h1));
    __half l2 = __float2half_rn(v.z - __half2float(h2));
    __half l3 = __float2half_rn(v.w - __half2float(h3));
    h = make_uint2(pkh(h0, h1), pkh(h2, h3));
    l = make_uint2(pkh(l0, l1), pkh(l2, l3));
}

// ---------------- weight conversion ----------------------------------------
__global__ void split_flat(const float4* __restrict__ src,
                           uint2* __restrict__ h,
                           uint2* __restrict__ l, unsigned n4) {
    unsigned stride = gridDim.x * blockDim.x;
    for (unsigned i = blockIdx.x * blockDim.x + threadIdx.x; i < n4; i += 2 * stride) {
        unsigned j = i + stride;
        float4 a = src[i];
        float4 b;
        bool has2 = (j < n4);
        if (has2) b = src[j];
        uint2 ha, la;
        split4(a, ha, la);
        h[i] = ha; l[i] = la;
        if (has2) {
            uint2 hb, lb;
            split4(b, hb, lb);
            h[j] = hb; l[j] = lb;
        }
    }
}
__global__ void split_flat_h(const float4* __restrict__ src,
                             uint2* __restrict__ h,
                             uint2* __restrict__ l, unsigned n4) {
    unsigned stride = gridDim.x * blockDim.x;
    for (unsigned i = blockIdx.x * blockDim.x + threadIdx.x; i < n4; i += 2 * stride) {
        unsigned j = i + stride;
        float4 a = src[i];
        float4 b;
        bool has2 = (j < n4);
        if (has2) b = src[j];
        uint2 ha, la;
        split4h(a, ha, la);
        h[i] = ha; l[i] = la;
        if (has2) {
            uint2 hb, lb;
            split4h(b, hb, lb);
            h[j] = hb; l[j] = lb;
        }
    }
}

__device__ __forceinline__ void qkv_one(const float* __restrict__ wq,
                                        const float* __restrict__ wk,
                                        const float* __restrict__ wv,
                                        unsigned i4) {
    unsigned e = i4 * 4u;
    unsigned l = e / (unsigned)(Dd * NQKV);
    unsigned r = e - l * (unsigned)(Dd * NQKV);
    unsigned k = r / (unsigned)NQKV;
    unsigned n = r - k * (unsigned)NQKV;
    unsigned wsel = n / (unsigned)Dd;
    unsigned r2 = n - wsel * (unsigned)Dd;
    unsigned hh = r2 >> 6, s = r2 & 63;
    const float* base = (wsel == 0) ? wq : ((wsel == 1) ? wk : wv);
    float4 v = *(const float4*)(base + ((size_t)(l * Hh + hh) * Dd + k) * HS + s);
    uint2 hp, lp;
    split4h(v, hp, lp);
    ((uint2*)wqkv16_h)[i4] = hp;
    ((uint2*)wqkv16_l)[i4] = lp;
}
__global__ void conv_qkv(const float* __restrict__ wq,
                         const float* __restrict__ wk,
                         const float* __restrict__ wv) {
    const unsigned total4 = (unsigned)Ll * Dd * NQKV / 4u;
    unsigned stride = gridDim.x * blockDim.x;
    for (unsigned i = blockIdx.x * blockDim.x + threadIdx.x; i < total4; i += 2 * stride) {
        qkv_one(wq, wk, wv, i);
        if (i + stride < total4) qkv_one(wq, wk, wv, i + stride);
    }
}

__device__ __forceinline__ void lm_one(const float* __restrict__ lm_w, unsigned i4) {
    unsigned e = i4 * 4u;
    unsigned k = e / (unsigned)VP;
    unsigned n = e - k * (unsigned)VP;
    const float* row = lm_w + (size_t)k * Vv;
    float4 v;
    v.x = (n     < Vv) ? row[n]     : 0.f;
    v.y = (n + 1 < Vv) ? row[n + 1] : 0.f;
    v.z = (n + 2 < Vv) ? row[n + 2] : 0.f;
    v.w = (n + 3 < Vv) ? row[n + 3] : 0.f;
    uint2 hp;
    hp.x = pkh(__float2half_rn(v.x), __float2half_rn(v.y));
    hp.y = pkh(__float2half_rn(v.z), __float2half_rn(v.w));
    ((uint2*)lmw16_h)[i4] = hp;
}
__global__ void conv_lm(const float* __restrict__ lm_w) {
    const unsigned total4 = (unsigned)Dd * VP / 4u;
    unsigned stride = gridDim.x * blockDim.x;
    for (unsigned i = blockIdx.x * blockDim.x + threadIdx.x; i < total4; i += 2 * stride) {
        lm_one(lm_w, i);
        if (i + stride < total4) lm_one(lm_w, i + stride);
    }
}

// ---------------- templated tensor-core GEMM (cp.async double-buffered) ----
// MODE 0: bf16 3-pass (AhBh + AhBl + AlBh).
// MODE 2: fp16 single-pass (AhBh only).
// MODE 3: fp16 2-pass (A hi only, B hi/lo: AhBh + AhBl).
// outmode 0: fp32 C. outmode 1: bf16 hi/lo pair. outmode 2: fp16 single (Ch).
// Split-K: blockIdx.z = K-chunk; partials to Cf + z*Mm*ldc, bias on chunk 0.
template<int MODE>
__global__ __launch_bounds__(256, 2) void gemm_mp(
    const __nv_bfloat16* __restrict__ Ah_g, const __nv_bfloat16* __restrict__ Al_g,
    int lda,
    const __nv_bfloat16* __restrict__ Bh_g, const __nv_bfloat16* __restrict__ Bl_g,
    int ldb,
    const float* __restrict__ bias,
    float* __restrict__ Cf,
    __nv_bfloat16* __restrict__ Ch, __nv_bfloat16* __restrict__ Cl,
    int ldc, int N, int K, int relu, int outmode)
{
    extern __shared__ char smem[];
    const uint32_t sb = s2u(smem);
    const int tid = threadIdx.x;
    const int wid = tid >> 5, lane = tid & 31;
    const int m0 = blockIdx.x * TM;
    const int n0 = blockIdx.y * TN;
    const int kz = blockIdx.z;
    const int mw = (wid & 3) * 32;
    const int nw = (wid >> 2) * 64;

    Ah_g += (size_t)kz * K;
    if (MODE == 0) Al_g += (size_t)kz * K;
    Bh_g += (size_t)kz * K * ldb;
    if (MODE == 0 || MODE == 3) Bl_g += (size_t)kz * K * ldb;
    Cf   += (size_t)kz * Mm * ldc;
    const float* biasz = (kz == 0) ? bias : nullptr;

    float acc[2][8][4];
    #pragma unroll
    for (int a = 0; a < 2; a++)
        #pragma unroll
        for (int b = 0; b < 8; b++)
            #pragma unroll
            for (int c = 0; c < 4; c++) acc[a][b][c] = 0.f;

    auto load_stage = [&](int kc, int st) {
        uint32_t base = sb + st * STAGE_BYTES;
        #pragma unroll
        for (int i = 0; i < 2; i++) {
            int c = tid + i * 256;
            int row = c >> 2, q = c & 3;
            uint32_t d = base + OFF_AH + row * 80 + q * 16;
            cpa16(d, Ah_g + (size_t)(m0 + row) * lda + kc + q * 8);
            if (MODE == 0)
                cpa16(d + (OFF_AL - OFF_AH), Al_g + (size_t)(m0 + row) * lda + kc + q * 8);
        }
        #pragma unroll
        for (int i = 0; i < 2; i++) {
            int c = tid + i * 256;
            int row = c >> 4, q = c & 15;
            uint32_t d = base + OFF_BH + row * 272 + q * 16;
            cpa16(d, Bh_g + (size_t)(kc + row) * ldb + n0 + q * 8);
            if (MODE == 0 || MODE == 3)
                cpa16(d + (OFF_BL - OFF_BH), Bl_g + (size_t)(kc + row) * ldb + n0 + q * 8);
        }
        asm volatile("cp.async.commit_group;" ::: "memory");
    };

    const int niter = K / BK;
    load_stage(0, 0);

    for (int it = 0; it < niter; it++) {
        if (it + 1 < niter) {
            load_stage((it + 1) * BK, (it + 1) & 1);
            asm volatile("cp.async.wait_group 1;" ::: "memory");
        } else {
            asm volatile("cp.async.wait_group 0;" ::: "memory");
        }
        __syncthreads();

        const uint32_t sbase = sb + (it & 1) * STAGE_BYTES;
        #pragma unroll
        for (int kk = 0; kk < BK; kk += 16) {
            uint32_t ah[2][4], al[2][4];
            int arow = mw + (lane & 15);
            int acol = kk + (lane >> 4) * 8;
            #pragma unroll
            for (int mi = 0; mi < 2; mi++) {
                uint32_t off = (uint32_t)(arow + mi * 16) * (SA_STRIDE * 2) + acol * 2;
                ldmx4(ah[mi], sbase + OFF_AH + off);
                if (MODE == 0) ldmx4(al[mi], sbase + OFF_AL + off);
            }
            int brow = kk + (lane & 15);
            int bcol = nw + (lane >> 4) * 8;
            #pragma unroll
            for (int ni = 0; ni < 4; ni++) {
                uint32_t off = (uint32_t)brow * (SB_STRIDE * 2) + (bcol + ni * 16) * 2;
                uint32_t bh[4], bl[4];
                ldmx4t(bh, sbase + OFF_BH + off);
                if (MODE == 0 || MODE == 3) ldmx4t(bl, sbase + OFF_BL + off);
                #pragma unroll
                for (int mi = 0; mi < 2; mi++) {
                    if (MODE == 0) {
                        mma_bf16(acc[mi][2 * ni],     ah[mi], bh[0], bh[1]);
                        mma_bf16(acc[mi][2 * ni],     ah[mi], bl[0], bl[1]);
                        mma_bf16(acc[mi][2 * ni],     al[mi], bh[0], bh[1]);
                        mma_bf16(acc[mi][2 * ni + 1], ah[mi], bh[2], bh[3]);
                        mma_bf16(acc[mi][2 * ni + 1], ah[mi], bl[2], bl[3]);
                        mma_bf16(acc[mi][2 * ni + 1], al[mi], bh[2], bh[3]);
                    } else if (MODE == 3) {
                        mma_f16(acc[mi][2 * ni],     ah[mi], bh[0], bh[1]);
                        mma_f16(acc[mi][2 * ni],     ah[mi], bl[0], bl[1]);
                        mma_f16(acc[mi][2 * ni + 1], ah[mi], bh[2], bh[3]);
                        mma_f16(acc[mi][2 * ni + 1], ah[mi], bl[2], bl[3]);
                    } else {
                        mma_f16(acc[mi][2 * ni],     ah[mi], bh[0], bh[1]);
                        mma_f16(acc[mi][2 * ni + 1], ah[mi], bh[2], bh[3]);
                    }
                }
            }
        }
        __syncthreads();
    }

    float* sC = (float*)smem;
    const int r0 = mw + (lane >> 2);
    const int c0 = 2 * (lane & 3);
    #pragma unroll 1
    for (int hf = 0; hf < 2; hf++) {
        if ((wid >> 2) == hf) {
            #pragma unroll
            for (int mi = 0; mi < 2; mi++)
                #pragma unroll
                for (int ni = 0; ni < 8; ni++) {
                    int rr = (r0 + mi * 16) * 68 + ni * 8 + c0;
                    sC[rr]              = acc[mi][ni][0];
                    sC[rr + 1]          = acc[mi][ni][1];
                    sC[rr + 8 * 68]     = acc[mi][ni][2];
                    sC[rr + 8 * 68 + 1] = acc[mi][ni][3];
                }
        }
        __syncthreads();
        #pragma unroll 4
        for (int it = 0; it < 32; it++) {
            int idx = tid + it * 256;
            int r = idx >> 6, c = idx & 63;
            int col = n0 + hf * 64 + c;
            if (col < N) {
                float v = sC[r * 68 + c];
                if (biasz) v += biasz[col];
                if (relu) v = fmaxf(v, 0.f);
                if (outmode == 0) {
                    Cf[(size_t)(m0 + r) * ldc + col] = v;
                } else if (outmode == 1) {
                    __nv_bfloat16 hh, ll;
                    splitv(v, hh, ll);
                    Ch[(size_t)(m0 + r) * ldc + col] = hh;
                    Cl[(size_t)(m0 + r) * ldc + col] = ll;
                } else {
                    ((__half*)Ch)[(size_t)(m0 + r) * ldc + col] = __float2half_rn(v);
                }
            }
        }
        __syncthreads();
    }
}

// ---------------- flash attention (bf16x3, causal, online softmax) ---------
__global__ __launch_bounds__(128) void flash_kernel() {
    extern __shared__ char smem[];
    const uint32_t sb = s2u(smem);
    const int tid = threadIdx.x, wid = tid >> 5, lane = tid & 31;
    const int bh = blockIdx.y;
    const int b = bh / Hh, h = bh % Hh;
    const int t0 = (int)(gridDim.x - 1 - blockIdx.x) * FBM;
    const int mw = wid * 16;

    const size_t rowbase = (size_t)(b * Tt) * NQKV + h * HS;

    #pragma unroll
    for (int i = 0; i < 4; i++) {
        int c = tid + i * 128;
        int row = c >> 3, q = c & 7;
        size_t g = rowbase + (size_t)(t0 + row) * NQKV + q * 8;
        cpa16(sb + row * 144 + q * 16, qkvp_h + g);
        cpa16(sb + 9216 + row * 144 + q * 16, qkvp_l + g);
    }
    asm volatile("cp.async.commit_group;" ::: "memory");
    asm volatile("cp.async.wait_group 0;" ::: "memory");
    __syncthreads();

    uint32_t qfh[4][4], qfl[4][4];
    {
        int arow = mw + (lane & 15);
        #pragma unroll
        for (int kk = 0; kk < 4; kk++) {
            int acol = kk * 16 + (lane >> 4) * 8;
            uint32_t off = (uint32_t)arow * 144 + acol * 2;
            ldmx4(qfh[kk], sb + off);
            ldmx4(qfl[kk], sb + 9216 + off);
        }
    }
    __syncthreads();

    auto kv_issue = [&](int u0, int st) {
        uint32_t base = sb + st * FSTAGE;
        #pragma unroll
        for (int i = 0; i < 4; i++) {
            int c = tid + i * 128;
            int row = c >> 3, q = c & 7;
            size_t g = rowbase + (size_t)(u0 + row) * NQKV + q * 8;
            uint32_t d = base + row * 144 + q * 16;
            cpa16(d + FST_KH, qkvp_h + g + Dd);
            cpa16(d + FST_KL, qkvp_l + g + Dd);
            cpa16(d + FST_VH, qkvp_h + g + 2 * Dd);
            cpa16(d + FST_VL, qkvp_l + g + 2 * Dd);
        }
        asm volatile("cp.async.commit_group;" ::: "memory");
    };

    float o[8][4];
    #pragma unroll
    for (int i = 0; i < 8; i++)
        #pragma unroll
        for (int j = 0; j < 4; j++) o[i][j] = 0.f;
    float mA = -1e30f, mB = -1e30f, lA = 0.f, lB = 0.f;

    const int nt = t0 / FBN + 1;
    kv_issue(0, 1);

    for (int it = 0; it < nt; it++) {
        const int u0 = it * FBN;
        if (it + 1 < nt) {
            kv_issue((it + 1) * FBN, it & 1);
            asm volatile("cp.async.wait_group 1;" ::: "memory");
        } else {
            asm volatile("cp.async.wait_group 0;" ::: "memory");
        }
        __syncthreads();
        const uint32_t kb = sb + ((it + 1) & 1) * FSTAGE;

        float s[8][4];
        #pragma unroll
        for (int i = 0; i < 8; i++)
            #pragma unroll
            for (int j = 0; j < 4; j++) s[i][j] = 0.f;

        const int bn = ((lane >> 4) << 3) + (lane & 7);
        const int bk = ((lane >> 3) & 1) * 8;
        #pragma unroll
        for (int kk = 0; kk < 4; kk++) {
            #pragma unroll
            for (int j = 0; j < 4; j++) {
                uint32_t addr = kb + (uint32_t)(j * 16 + bn) * 144 + (kk * 16 + bk) * 2;
                uint32_t kh4[4], kl4[4];
                ldmx4(kh4, addr + FST_KH);
                ldmx4(kl4, addr + FST_KL);
                mma_bf16(s[2 * j],     qfh[kk], kh4[0], kh4[1]);
                mma_bf16(s[2 * j],     qfh[kk], kl4[0], kl4[1]);
                mma_bf16(s[2 * j],     qfl[kk], kh4[0], kh4[1]);
                mma_bf16(s[2 * j + 1], qfh[kk], kh4[2], kh4[3]);
                mma_bf16(s[2 * j + 1], qfh[kk], kl4[2], kl4[3]);
                mma_bf16(s[2 * j + 1], qfl[kk], kh4[2], kh4[3]);
            }
        }

        const int rA = lane >> 2;
        const int tA = t0 + mw + rA, tB = tA + 8;
        #pragma unroll
        for (int nb = 0; nb < 8; nb++)
            #pragma unroll
            for (int j = 0; j < 4; j++) s[nb][j] *= 0.125f;
        if (u0 + FBN - 1 > t0 + mw) {
            #pragma unroll
            for (int nb = 0; nb < 8; nb++) {
                int u_lo = u0 + nb * 8 + (lane & 3) * 2;
                if (u_lo     > tA) s[nb][0] = -1e30f;
                if (u_lo + 1 > tA) s[nb][1] = -1e30f;
                if (u_lo     > tB) s[nb][2] = -1e30f;
                if (u_lo + 1 > tB) s[nb][3] = -1e30f;
            }
        }

        float rmA = -1e30f, rmB = -1e30f;
        #pragma unroll
        for (int nb = 0; nb < 8; nb++) {
            rmA = fmaxf(rmA, fmaxf(s[nb][0], s[nb][1]));
            rmB = fmaxf(rmB, fmaxf(s[nb][2], s[nb][3]));
        }
        rmA = fmaxf(rmA, __shfl_xor_sync(0xffffffffu, rmA, 1));
        rmA = fmaxf(rmA, __shfl_xor_sync(0xffffffffu, rmA, 2));
        rmB = fmaxf(rmB, __shfl_xor_sync(0xffffffffu, rmB, 1));
        rmB = fmaxf(rmB, __shfl_xor_sync(0xffffffffu, rmB, 2));
        float mAn = fmaxf(mA, rmA), mBn = fmaxf(mB, rmB);
        float scA = __expf(mA - mAn), scB = __expf(mB - mBn);
        mA = mAn; mB = mBn;

        float rsA = 0.f, rsB = 0.f;
        #pragma unroll
        for (int nb = 0; nb < 8; nb++) {
            s[nb][0] = __expf(s[nb][0] - mA); rsA += s[nb][0];
            s[nb][1] = __expf(s[nb][1] - mA); rsA += s[nb][1];
            s[nb][2] = __expf(s[nb][2] - mB); rsB += s[nb][2];
            s[nb][3] = __expf(s[nb][3] - mB); rsB += s[nb][3];
        }
        rsA += __shfl_xor_sync(0xffffffffu, rsA, 1);
        rsA += __shfl_xor_sync(0xffffffffu, rsA, 2);
        rsB += __shfl_xor_sync(0xffffffffu, rsB, 1);
        rsB += __shfl_xor_sync(0xffffffffu, rsB, 2);
        lA = lA * scA + rsA;
        lB = lB * scB + rsB;
        #pragma unroll
        for (int nb = 0; nb < 8; nb++) {
            o[nb][0] *= scA; o[nb][1] *= scA;
            o[nb][2] *= scB; o[nb][3] *= scB;
        }

        #pragma unroll
        for (int g = 0; g < 4; g++) {
            uint32_t pha[4], pla[4];
            {
                __nv_bfloat16 h0, h1, l0, l1;
                splitv(s[2 * g][0], h0, l0); splitv(s[2 * g][1], h1, l1);
                pha[0] = pk(h0, h1); pla[0] = pk(l0, l1);
                splitv(s[2 * g][2], h0, l0); splitv(s[2 * g][3], h1, l1);
                pha[1] = pk(h0, h1); pla[1] = pk(l0, l1);
                splitv(s[2 * g + 1][0], h0, l0); splitv(s[2 * g + 1][1], h1, l1);
                pha[2] = pk(h0, h1); pla[2] = pk(l0, l1);
                splitv(s[2 * g + 1][2], h0, l0); splitv(s[2 * g + 1][3], h1, l1);
                pha[3] = pk(h0, h1); pla[3] = pk(l0, l1);
            }
            const int vrow = g * 16 + (lane & 15);
            #pragma unroll
            for (int j = 0; j < 4; j++) {
                uint32_t addr = kb + (uint32_t)vrow * 144 +
                                (uint32_t)(j * 16 + (lane >> 4) * 8) * 2;
                uint32_t vh4[4], vl4[4];
                ldmx4t(vh4, addr + FST_VH);
                ldmx4t(vl4, addr + FST_VL);
                mma_bf16(o[2 * j],     pha, vh4[0], vh4[1]);
                mma_bf16(o[2 * j],     pha, vl4[0], vl4[1]);
                mma_bf16(o[2 * j],     pla, vh4[0], vh4[1]);
                mma_bf16(o[2 * j + 1], pha, vh4[2], vh4[3]);
                mma_bf16(o[2 * j + 1], pha, vl4[2], vl4[3]);
                mma_bf16(o[2 * j + 1], pla, vh4[2], vh4[3]);
            }
        }
        __syncthreads();
    }

    const float invA = 1.f / lA, invB = 1.f / lB;
    const int rA = lane >> 2;
    const int tA = t0 + mw + rA, tB = tA + 8;
    const int cbase = h * HS + (lane & 3) * 2;
    size_t baseA = (size_t)(b * Tt + tA) * Dd + cbase;
    size_t baseB = (size_t)(b * Tt + tB) * Dd + cbase;
    #pragma unroll
    for (int nb = 0; nb < 8; nb++) {
        splitv(o[nb][0] * invA, o_h[baseA + nb * 8],     o_l[baseA + nb * 8]);
        splitv(o[nb][1] * invA, o_h[baseA + nb * 8 + 1], o_l[baseA + nb * 8 + 1]);
        splitv(o[nb][2] * invB, o_h[baseB + nb * 8],     o_l[baseB + nb * 8]);
        splitv(o[nb][3] * invB, o_h[baseB + nb * 8 + 1], o_l[baseB + nb * 8 + 1]);
    }
}

// ---------------- embedding -------------------------------------------------
__global__ void embed_kernel(const int* __restrict__ idx,
                             const float* __restrict__ tok_emb,
                             const float* __restrict__ pos_emb) {
    int m = blockIdx.x;
    int t = m % Tt;
    int tok = idx[m];
    const float* te = tok_emb + (size_t)tok * Dd;
    const float* pe = pos_emb + (size_t)t * Dd;
    float* x = g_x + (size_t)m * Dd;
    for (int c = threadIdx.x; c < Dd; c += blockDim.x) {
        float v = te[c] + pe[c];
        x[c] = v;
        x16[(size_t)m * Dd + c] = __float2half_rn(v);
    }
}

// ---------------- fused residual add + LayerNorm (warp per row) ------------
__global__ void addln_kernel(const float* __restrict__ tmp,
                             const float* __restrict__ gamma,
                             const float* __restrict__ beta,
                             int nparts) {
    int row = blockIdx.x * (blockDim.x >> 5) + (threadIdx.x >> 5);
    int lane = threadIdx.x & 31;
    float* x = g_x + (size_t)row * Dd;
    const float* a0 = tmp + (size_t)row * Dd;

    float v[24];
    float s = 0.f;
    #pragma unroll
    for (int i = 0; i < 24; i++) {
        int c = lane + i * 32;
        float t = x[c] + a0[c];
        if (nparts > 1) t += a0[(size_t)Mm * Dd + c];
        if (nparts > 2) t += a0[(size_t)2 * Mm * Dd + c];
        v[i] = t;
        s += t;
    }
    #pragma unroll
    for (int o = 16; o > 0; o >>= 1) s += __shfl_xor_sync(0xffffffffu, s, o);
    float mean = s * (1.f / Dd);

    float q = 0.f;
    #pragma unroll
    for (int i = 0; i < 24; i++) {
        float d = v[i] - mean;
        q += d * d;
    }
    #pragma unroll
    for (int o = 16; o > 0; o >>= 1) q += __shfl_xor_sync(0xffffffffu, q, o);
    float rstd = rsqrtf(q * (1.f / Dd) + 1e-5f);

    #pragma unroll
    for (int i = 0; i < 24; i++) {
        int c = lane + i * 32;
        float ov = (v[i] - mean) * rstd * gamma[c] + beta[c];
        x[c] = ov;
        x16[(size_t)row * Dd + c] = __float2half_rn(ov);
    }
}

// ---------------- host orchestration ----------------------------------------
extern "C" void kernel_launch(void* const* d_in, const int* in_sizes, int n_in,
                              void* d_out, int out_size) {
    const int*   idx     = (const int*)  d_in[0];
    const float* tok_emb = (const float*)d_in[1];
    const float* pos_emb = (const float*)d_in[2];
    const float* wq      = (const float*)d_in[3];
    const float* wk      = (const float*)d_in[4];
    const float* wv      = (const float*)d_in[5];
    const float* wproj   = (const float*)d_in[6];
    const float* bproj   = (const float*)d_in[7];
    const float* w1      = (const float*)d_in[8];
    const float* b1      = (const float*)d_in[9];
    const float* w2      = (const float*)d_in[10];
    const float* b2      = (const float*)d_in[11];
    const float* ln1_g   = (const float*)d_in[12];
    const float* ln1_b   = (const float*)d_in[13];
    const float* ln2_g   = (const float*)d_in[14];
    const float* ln2_b   = (const float*)d_in[15];
    const float* lm_w    = (const float*)d_in[16];
    const float* lm_b    = (const float*)d_in[17];
    float* out = (float*)d_out;

    cudaFuncSetAttribute(gemm_mp<0>, cudaFuncAttributeMaxDynamicSharedMemorySize, GEMM_SMEM);
    cudaFuncSetAttribute(gemm_mp<2>, cudaFuncAttributeMaxDynamicSharedMemorySize, GEMM_SMEM);
    cudaFuncSetAttribute(gemm_mp<3>, cudaFuncAttributeMaxDynamicSharedMemorySize, GEMM_SMEM);
    cudaFuncSetAttribute(flash_kernel, cudaFuncAttributeMaxDynamicSharedMemorySize, FLASH_SMEM);

    float *p_x, *p_tmp;
    cudaGetSymbolAddress((void**)&p_x,   g_x);
    cudaGetSymbolAddress((void**)&p_tmp, g_tmp);
    __nv_bfloat16 *poh, *pol, *pqh, *pql;
    cudaGetSymbolAddress((void**)&poh, o_h);   cudaGetSymbolAddress((void**)&pol, o_l);
    cudaGetSymbolAddress((void**)&pqh, qkvp_h); cudaGetSymbolAddress((void**)&pql, qkvp_l);
    __nv_bfloat16 *pwph, *pwpl;
    cudaGetSymbolAddress((void**)&pwph, wpr_h);  cudaGetSymbolAddress((void**)&pwpl, wpr_l);
    __half *pwq16h, *pwq16l, *pw1h, *pw1l, *pw2h, *pw2l, *plmh, *px16, *ph1;
    cudaGetSymbolAddress((void**)&pwq16h, wqkv16_h);
    cudaGetSymbolAddress((void**)&pwq16l, wqkv16_l);
    cudaGetSymbolAddress((void**)&pw1h, w1f16_h);  cudaGetSymbolAddress((void**)&pw1l, w1f16_l);
    cudaGetSymbolAddress((void**)&pw2h, w2f16_h);  cudaGetSymbolAddress((void**)&pw2l, w2f16_l);
    cudaGetSymbolAddress((void**)&plmh, lmw16_h);
    cudaGetSymbolAddress((void**)&px16, x16);
    cudaGetSymbolAddress((void**)&ph1, h1f16);

    conv_qkv<<<1024, 256>>>(wq, wk, wv);
    split_flat<<<512, 256>>>((const float4*)wproj, (uint2*)pwph, (uint2*)pwpl,
                             (unsigned)(Ll * Dd * Dd / 4));
    split_flat_h<<<1024, 256>>>((const float4*)w1, (uint2*)pw1h, (uint2*)pw1l,
                                (unsigned)(Ll * Dd * DFF / 4));
    split_flat_h<<<1024, 256>>>((const float4*)w2, (uint2*)pw2h, (uint2*)pw2l,
                                (unsigned)(Ll * DFF * Dd / 4));
    conv_lm<<<2048, 256>>>(lm_w);

    embed_kernel<<<Mm, 256>>>(idx, tok_emb, pos_emb);

    for (int l = 0; l < Ll; l++) {
        // QKV: fp16 2-pass -> bf16 pair out
        gemm_mp<3><<<dim3(Mm / TM, NQKV / TN, 1), 256, GEMM_SMEM>>>(
            (const __nv_bfloat16*)px16, nullptr, Dd,
            (const __nv_bfloat16*)(pwq16h + (size_t)l * Dd * NQKV),
            (const __nv_bfloat16*)(pwq16l + (size_t)l * Dd * NQKV), NQKV,
            nullptr, nullptr, pqh, pql, NQKV, NQKV, Dd, 0, 1);
        flash_kernel<<<dim3(Tt / FBM, Bq * Hh), 128, FLASH_SMEM>>>();
        // proj: bf16x3 split-K=3 (precision anchor)
        gemm_mp<0><<<dim3(Mm / TM, Dd / TN, 3), 256, GEMM_SMEM>>>(
            poh, pol, Dd,
            pwph + (size_t)l * Dd * Dd, pwpl + (size_t)l * Dd * Dd, Dd,
            bproj + (size_t)l * Dd, p_tmp, nullptr, nullptr, Dd, Dd, Dd / 3, 0, 0);
        addln_kernel<<<Mm / 8, 256>>>(p_tmp, ln1_g + (size_t)l * Dd,
                                      ln1_b + (size_t)l * Dd, 3);
        // fc1: fp16 2-pass + relu -> fp16 single h1
        gemm_mp<3><<<dim3(Mm / TM, DFF / TN, 1), 256, GEMM_SMEM>>>(
            (const __nv_bfloat16*)px16, nullptr, Dd,
            (const __nv_bfloat16*)(pw1h + (size_t)l * Dd * DFF),
            (const __nv_bfloat16*)(pw1l + (size_t)l * Dd * DFF), DFF,
            b1 + (size_t)l * DFF, nullptr, (__nv_bfloat16*)ph1, nullptr,
            DFF, DFF, Dd, 1, 2);
        // fc2: fp16 2-pass split-K=3 -> fp32 partials
        gemm_mp<3><<<dim3(Mm / TM, Dd / TN, 3), 256, GEMM_SMEM>>>(
            (const __nv_bfloat16*)ph1, nullptr, DFF,
            (const __nv_bfloat16*)(pw2h + (size_t)l * DFF * Dd),
            (const __nv_bfloat16*)(pw2l + (size_t)l * DFF * Dd), Dd,
            b2 + (size_t)l * Dd, p_tmp, nullptr, nullptr, Dd, Dd, DFF / 3, 0, 0);
        addln_kernel<<<Mm / 8, 256>>>(p_tmp, ln2_g + (size_t)l * Dd,
                                      ln2_b + (size_t)l * Dd, 3);
    }

    // lm_head: fp16 single-pass (A = x16)
    gemm_mp<2><<<dim3(Mm / TM, VP / TN, 1), 256, GEMM_SMEM>>>(
        (const __nv_bfloat16*)px16, nullptr, Dd,
        (const __nv_bfloat16*)plmh, nullptr, VP,
        lm_b, out, nullptr, nullptr, Vv, Vv, Dd, 0, 0);
}

// round 16
// speedup vs baseline: 2.2053x; 1.0802x over previous
#include <cuda_runtime.h>
#include <cuda_bf16.h>
#include <cuda_fp16.h>
#include <cstdint>
#include <math.h>
#include <stddef.h>

// Problem constants
#define Bq 2
#define Tt 1024
#define Dd 768
#define Hh 12
#define Ll 6
#define Vv 50257
#define VP 50304
#define HS 64
#define Mm (Bq*Tt)
#define DFF (4*Dd)
#define NQKV (3*Dd)

// GEMM tiling
#define TM 128
#define TN 128
#define BK 32
#define SA_STRIDE 40
#define SB_STRIDE 136
#define OFF_AH 0
#define OFF_AL 10240
#define OFF_BH 20480
#define OFF_BL 29184
#define STAGE_BYTES 37888
#define GEMM_SMEM (2*STAGE_BYTES)

// Flash attention tiling
#define FBM 64
#define FBN 64
#define FST_KH 0
#define FST_KL 9216
#define FST_VH 18432
#define FST_VL 27648
#define FSTAGE 36864
#define FLASH_SMEM (2*FSTAGE)

// ---------------- scratch --------------------------------------------------
__device__ float g_x  [Mm*Dd];
__device__ float g_tmp[(size_t)3*Mm*Dd];     // up to 3 split-K partials

__device__ __half        x16 [Mm*Dd];
__device__ __half        o16 [Mm*Dd];
__device__ __half        h1f16[(size_t)Mm*DFF];
__device__ __nv_bfloat16 qkvp_h[(size_t)Mm*NQKV], qkvp_l[(size_t)Mm*NQKV];

__device__ __half        wqkv16_h[(size_t)Ll*Dd*NQKV];
__device__ __half        wpr16_h[(size_t)Ll*Dd*Dd], wpr16_l[(size_t)Ll*Dd*Dd];
__device__ __half        w1f16_h[(size_t)Ll*Dd*DFF], w1f16_l[(size_t)Ll*Dd*DFF];
__device__ __half        w2f16_h[(size_t)Ll*DFF*Dd], w2f16_l[(size_t)Ll*DFF*Dd];
__device__ __half        lmw16_h[(size_t)Dd*VP];

// ---------------- helpers --------------------------------------------------
__device__ __forceinline__ uint32_t s2u(const void* p) {
    uint32_t a;
    asm("{ .reg .u64 t; cvta.to.shared.u64 t, %1; cvt.u32.u64 %0, t; }" : "=r"(a) : "l"(p));
    return a;
}
__device__ __forceinline__ void cpa16(uint32_t dst, const void* src) {
    asm volatile("cp.async.cg.shared.global [%0], [%1], 16;" :: "r"(dst), "l"(src));
}
__device__ __forceinline__ void ldmx4(uint32_t* r, uint32_t addr) {
    asm volatile("ldmatrix.sync.aligned.m8n8.x4.shared.b16 {%0,%1,%2,%3},[%4];"
                 : "=r"(r[0]), "=r"(r[1]), "=r"(r[2]), "=r"(r[3]) : "r"(addr));
}
__device__ __forceinline__ void ldmx4t(uint32_t* r, uint32_t addr) {
    asm volatile("ldmatrix.sync.aligned.m8n8.x4.trans.shared.b16 {%0,%1,%2,%3},[%4];"
                 : "=r"(r[0]), "=r"(r[1]), "=r"(r[2]), "=r"(r[3]) : "r"(addr));
}
__device__ __forceinline__ void mma_bf16(float* c, const uint32_t* a,
                                         uint32_t b0, uint32_t b1) {
    asm volatile(
        "mma.sync.aligned.m16n8k16.row.col.f32.bf16.bf16.f32 "
        "{%0,%1,%2,%3},{%4,%5,%6,%7},{%8,%9},{%0,%1,%2,%3};"
        : "+f"(c[0]), "+f"(c[1]), "+f"(c[2]), "+f"(c[3])
        : "r"(a[0]), "r"(a[1]), "r"(a[2]), "r"(a[3]), "r"(b0), "r"(b1));
}
__device__ __forceinline__ void mma_f16(float* c, const uint32_t* a,
                                        uint32_t b0, uint32_t b1) {
    asm volatile(
        "mma.sync.aligned.m16n8k16.row.col.f32.f16.f16.f32 "
        "{%0,%1,%2,%3},{%4,%5,%6,%7},{%8,%9},{%0,%1,%2,%3};"
        : "+f"(c[0]), "+f"(c[1]), "+f"(c[2]), "+f"(c[3])
        : "r"(a[0]), "r"(a[1]), "r"(a[2]), "r"(a[3]), "r"(b0), "r"(b1));
}
__device__ __forceinline__ void splitv(float v, __nv_bfloat16& h, __nv_bfloat16& l) {
    h = __float2bfloat16_rn(v);
    l = __float2bfloat16_rn(v - __bfloat162float(h));
}
__device__ __forceinline__ uint32_t pk(__nv_bfloat16 a, __nv_bfloat16 b) {
    return ((uint32_t)__bfloat16_as_ushort(b) << 16) | __bfloat16_as_ushort(a);
}
__device__ __forceinline__ uint32_t pkh(__half a, __half b) {
    return ((uint32_t)__half_as_ushort(b) << 16) | __half_as_ushort(a);
}
__device__ __forceinline__ void split4h(float4 v, uint2& h, uint2& l) {
    __half h0 = __float2half_rn(v.x), h1 = __float2half_rn(v.y);
    __half h2 = __float2half_rn(v.z), h3 = __float2half_rn(v.w);
    __half l0 = __float2half_rn(v.x - __half2float(h0));
    __half l1 = __float2half_rn(v.y - __half2float(h1));
    __half l2 = __float2half_rn(v.z - __half2float(h2));
    __half l3 = __float2half_rn(v.w - __half2float(h3));
    h = make_uint2(pkh(h0, h1), pkh(h2, h3));
    l = make_uint2(pkh(l0, l1), pkh(l2, l3));
}

// ---------------- weight conversion ----------------------------------------
__global__ void split_flat_h(const float4* __restrict__ src,
                             uint2* __restrict__ h,
                             uint2* __restrict__ l, unsigned n4) {
    unsigned stride = gridDim.x * blockDim.x;
    for (unsigned i = blockIdx.x * blockDim.x + threadIdx.x; i < n4; i += 2 * stride) {
        unsigned j = i + stride;
        float4 a = src[i];
        float4 b;
        bool has2 = (j < n4);
        if (has2) b = src[j];
        uint2 ha, la;
        split4h(a, ha, la);
        h[i] = ha; l[i] = la;
        if (has2) {
            uint2 hb, lb;
            split4h(b, hb, lb);
            h[j] = hb; l[j] = lb;
        }
    }
}

__device__ __forceinline__ void qkv_one(const float* __restrict__ wq,
                                        const float* __restrict__ wk,
                                        const float* __restrict__ wv,
                                        unsigned i4) {
    unsigned e = i4 * 4u;
    unsigned l = e / (unsigned)(Dd * NQKV);
    unsigned r = e - l * (unsigned)(Dd * NQKV);
    unsigned k = r / (unsigned)NQKV;
    unsigned n = r - k * (unsigned)NQKV;
    unsigned wsel = n / (unsigned)Dd;
    unsigned r2 = n - wsel * (unsigned)Dd;
    unsigned hh = r2 >> 6, s = r2 & 63;
    const float* base = (wsel == 0) ? wq : ((wsel == 1) ? wk : wv);
    float4 v = *(const float4*)(base + ((size_t)(l * Hh + hh) * Dd + k) * HS + s);
    uint2 hp;
    hp.x = pkh(__float2half_rn(v.x), __float2half_rn(v.y));
    hp.y = pkh(__float2half_rn(v.z), __float2half_rn(v.w));
    ((uint2*)wqkv16_h)[i4] = hp;
}
__global__ void conv_qkv(const float* __restrict__ wq,
                         const float* __restrict__ wk,
                         const float* __restrict__ wv) {
    const unsigned total4 = (unsigned)Ll * Dd * NQKV / 4u;
    unsigned stride = gridDim.x * blockDim.x;
    for (unsigned i = blockIdx.x * blockDim.x + threadIdx.x; i < total4; i += 2 * stride) {
        qkv_one(wq, wk, wv, i);
        if (i + stride < total4) qkv_one(wq, wk, wv, i + stride);
    }
}

__device__ __forceinline__ void lm_one(const float* __restrict__ lm_w, unsigned i4) {
    unsigned e = i4 * 4u;
    unsigned k = e / (unsigned)VP;
    unsigned n = e - k * (unsigned)VP;
    const float* row = lm_w + (size_t)k * Vv;
    float4 v;
    v.x = (n     < Vv) ? row[n]     : 0.f;
    v.y = (n + 1 < Vv) ? row[n + 1] : 0.f;
    v.z = (n + 2 < Vv) ? row[n + 2] : 0.f;
    v.w = (n + 3 < Vv) ? row[n + 3] : 0.f;
    uint2 hp;
    hp.x = pkh(__float2half_rn(v.x), __float2half_rn(v.y));
    hp.y = pkh(__float2half_rn(v.z), __float2half_rn(v.w));
    ((uint2*)lmw16_h)[i4] = hp;
}
__global__ void conv_lm(const float* __restrict__ lm_w) {
    const unsigned total4 = (unsigned)Dd * VP / 4u;
    unsigned stride = gridDim.x * blockDim.x;
    for (unsigned i = blockIdx.x * blockDim.x + threadIdx.x; i < total4; i += 2 * stride) {
        lm_one(lm_w, i);
        if (i + stride < total4) lm_one(lm_w, i + stride);
    }
}

// ---------------- templated tensor-core GEMM (cp.async double-buffered) ----
// MODE 2: fp16 single-pass (AhBh only).
// MODE 3: fp16 2-pass (A hi only, B hi/lo: AhBh + AhBl).
// outmode 0: fp32 C. outmode 1: bf16 hi/lo pair. outmode 2: fp16 single (Ch).
// Split-K: blockIdx.z = K-chunk; partials to Cf + z*Mm*ldc, bias on chunk 0.
template<int MODE>
__global__ __launch_bounds__(256, 2) void gemm_mp(
    const __nv_bfloat16* __restrict__ Ah_g, int lda,
    const __nv_bfloat16* __restrict__ Bh_g, const __nv_bfloat16* __restrict__ Bl_g,
    int ldb,
    const float* __restrict__ bias,
    float* __restrict__ Cf,
    __nv_bfloat16* __restrict__ Ch, __nv_bfloat16* __restrict__ Cl,
    int ldc, int N, int K, int relu, int outmode)
{
    extern __shared__ char smem[];
    const uint32_t sb = s2u(smem);
    const int tid = threadIdx.x;
    const int wid = tid >> 5, lane = tid & 31;
    const int m0 = blockIdx.x * TM;
    const int n0 = blockIdx.y * TN;
    const int kz = blockIdx.z;
    const int mw = (wid & 3) * 32;
    const int nw = (wid >> 2) * 64;

    Ah_g += (size_t)kz * K;
    Bh_g += (size_t)kz * K * ldb;
    if (MODE == 3) Bl_g += (size_t)kz * K * ldb;
    Cf   += (size_t)kz * Mm * ldc;
    const float* biasz = (kz == 0) ? bias : nullptr;

    float acc[2][8][4];
    #pragma unroll
    for (int a = 0; a < 2; a++)
        #pragma unroll
        for (int b = 0; b < 8; b++)
            #pragma unroll
            for (int c = 0; c < 4; c++) acc[a][b][c] = 0.f;

    auto load_stage = [&](int kc, int st) {
        uint32_t base = sb + st * STAGE_BYTES;
        #pragma unroll
        for (int i = 0; i < 2; i++) {
            int c = tid + i * 256;
            int row = c >> 2, q = c & 3;
            uint32_t d = base + OFF_AH + row * 80 + q * 16;
            cpa16(d, Ah_g + (size_t)(m0 + row) * lda + kc + q * 8);
        }
        #pragma unroll
        for (int i = 0; i < 2; i++) {
            int c = tid + i * 256;
            int row = c >> 4, q = c & 15;
            uint32_t d = base + OFF_BH + row * 272 + q * 16;
            cpa16(d, Bh_g + (size_t)(kc + row) * ldb + n0 + q * 8);
            if (MODE == 3)
                cpa16(d + (OFF_BL - OFF_BH), Bl_g + (size_t)(kc + row) * ldb + n0 + q * 8);
        }
        asm volatile("cp.async.commit_group;" ::: "memory");
    };

    const int niter = K / BK;
    load_stage(0, 0);

    for (int it = 0; it < niter; it++) {
        if (it + 1 < niter) {
            load_stage((it + 1) * BK, (it + 1) & 1);
            asm volatile("cp.async.wait_group 1;" ::: "memory");
        } else {
            asm volatile("cp.async.wait_group 0;" ::: "memory");
        }
        __syncthreads();

        const uint32_t sbase = sb + (it & 1) * STAGE_BYTES;
        #pragma unroll
        for (int kk = 0; kk < BK; kk += 16) {
            uint32_t ah[2][4];
            int arow = mw + (lane & 15);
            int acol = kk + (lane >> 4) * 8;
            #pragma unroll
            for (int mi = 0; mi < 2; mi++) {
                uint32_t off = (uint32_t)(arow + mi * 16) * (SA_STRIDE * 2) + acol * 2;
                ldmx4(ah[mi], sbase + OFF_AH + off);
            }
            int brow = kk + (lane & 15);
            int bcol = nw + (lane >> 4) * 8;
            #pragma unroll
            for (int ni = 0; ni < 4; ni++) {
                uint32_t off = (uint32_t)brow * (SB_STRIDE * 2) + (bcol + ni * 16) * 2;
                uint32_t bh[4], bl[4];
                ldmx4t(bh, sbase + OFF_BH + off);
                if (MODE == 3) ldmx4t(bl, sbase + OFF_BL + off);
                #pragma unroll
                for (int mi = 0; mi < 2; mi++) {
                    if (MODE == 3) {
                        mma_f16(acc[mi][2 * ni],     ah[mi], bh[0], bh[1]);
                        mma_f16(acc[mi][2 * ni],     ah[mi], bl[0], bl[1]);
                        mma_f16(acc[mi][2 * ni + 1], ah[mi], bh[2], bh[3]);
                        mma_f16(acc[mi][2 * ni + 1], ah[mi], bl[2], bl[3]);
                    } else {
                        mma_f16(acc[mi][2 * ni],     ah[mi], bh[0], bh[1]);
                        mma_f16(acc[mi][2 * ni + 1], ah[mi], bh[2], bh[3]);
                    }
                }
            }
        }
        __syncthreads();
    }

    float* sC = (float*)smem;
    const int r0 = mw + (lane >> 2);
    const int c0 = 2 * (lane & 3);
    #pragma unroll 1
    for (int hf = 0; hf < 2; hf++) {
        if ((wid >> 2) == hf) {
            #pragma unroll
            for (int mi = 0; mi < 2; mi++)
                #pragma unroll
                for (int ni = 0; ni < 8; ni++) {
                    int rr = (r0 + mi * 16) * 68 + ni * 8 + c0;
                    sC[rr]              = acc[mi][ni][0];
                    sC[rr + 1]          = acc[mi][ni][1];
                    sC[rr + 8 * 68]     = acc[mi][ni][2];
                    sC[rr + 8 * 68 + 1] = acc[mi][ni][3];
                }
        }
        __syncthreads();
        #pragma unroll 4
        for (int it = 0; it < 32; it++) {
            int idx = tid + it * 256;
            int r = idx >> 6, c = idx & 63;
            int col = n0 + hf * 64 + c;
            if (col < N) {
                float v = sC[r * 68 + c];
                if (biasz) v += biasz[col];
                if (relu) v = fmaxf(v, 0.f);
                if (outmode == 0) {
                    Cf[(size_t)(m0 + r) * ldc + col] = v;
                } else if (outmode == 1) {
                    __nv_bfloat16 hh, ll;
                    splitv(v, hh, ll);
                    Ch[(size_t)(m0 + r) * ldc + col] = hh;
                    Cl[(size_t)(m0 + r) * ldc + col] = ll;
                } else {
                    ((__half*)Ch)[(size_t)(m0 + r) * ldc + col] = __float2half_rn(v);
                }
            }
        }
        __syncthreads();
    }
}

// ---------------- flash attention (bf16x3, causal, online softmax) ---------
__global__ __launch_bounds__(128) void flash_kernel() {
    extern __shared__ char smem[];
    const uint32_t sb = s2u(smem);
    const int tid = threadIdx.x, wid = tid >> 5, lane = tid & 31;
    const int bh = blockIdx.y;
    const int b = bh / Hh, h = bh % Hh;
    const int t0 = (int)(gridDim.x - 1 - blockIdx.x) * FBM;
    const int mw = wid * 16;

    const size_t rowbase = (size_t)(b * Tt) * NQKV + h * HS;

    #pragma unroll
    for (int i = 0; i < 4; i++) {
        int c = tid + i * 128;
        int row = c >> 3, q = c & 7;
        size_t g = rowbase + (size_t)(t0 + row) * NQKV + q * 8;
        cpa16(sb + row * 144 + q * 16, qkvp_h + g);
        cpa16(sb + 9216 + row * 144 + q * 16, qkvp_l + g);
    }
    asm volatile("cp.async.commit_group;" ::: "memory");
    asm volatile("cp.async.wait_group 0;" ::: "memory");
    __syncthreads();

    uint32_t qfh[4][4], qfl[4][4];
    {
        int arow = mw + (lane & 15);
        #pragma unroll
        for (int kk = 0; kk < 4; kk++) {
            int acol = kk * 16 + (lane >> 4) * 8;
            uint32_t off = (uint32_t)arow * 144 + acol * 2;
            ldmx4(qfh[kk], sb + off);
            ldmx4(qfl[kk], sb + 9216 + off);
        }
    }
    __syncthreads();

    auto kv_issue = [&](int u0, int st) {
        uint32_t base = sb + st * FSTAGE;
        #pragma unroll
        for (int i = 0; i < 4; i++) {
            int c = tid + i * 128;
            int row = c >> 3, q = c & 7;
            size_t g = rowbase + (size_t)(u0 + row) * NQKV + q * 8;
            uint32_t d = base + row * 144 + q * 16;
            cpa16(d + FST_KH, qkvp_h + g + Dd);
            cpa16(d + FST_KL, qkvp_l + g + Dd);
            cpa16(d + FST_VH, qkvp_h + g + 2 * Dd);
            cpa16(d + FST_VL, qkvp_l + g + 2 * Dd);
        }
        asm volatile("cp.async.commit_group;" ::: "memory");
    };

    float o[8][4];
    #pragma unroll
    for (int i = 0; i < 8; i++)
        #pragma unroll
        for (int j = 0; j < 4; j++) o[i][j] = 0.f;
    float mA = -1e30f, mB = -1e30f, lA = 0.f, lB = 0.f;

    const int nt = t0 / FBN + 1;
    kv_issue(0, 1);

    for (int it = 0; it < nt; it++) {
        const int u0 = it * FBN;
        if (it + 1 < nt) {
            kv_issue((it + 1) * FBN, it & 1);
            asm volatile("cp.async.wait_group 1;" ::: "memory");
        } else {
            asm volatile("cp.async.wait_group 0;" ::: "memory");
        }
        __syncthreads();
        const uint32_t kb = sb + ((it + 1) & 1) * FSTAGE;

        float s[8][4];
        #pragma unroll
        for (int i = 0; i < 8; i++)
            #pragma unroll
            for (int j = 0; j < 4; j++) s[i][j] = 0.f;

        const int bn = ((lane >> 4) << 3) + (lane & 7);
        const int bk = ((lane >> 3) & 1) * 8;
        #pragma unroll
        for (int kk = 0; kk < 4; kk++) {
            #pragma unroll
            for (int j = 0; j < 4; j++) {
                uint32_t addr = kb + (uint32_t)(j * 16 + bn) * 144 + (kk * 16 + bk) * 2;
                uint32_t kh4[4], kl4[4];
                ldmx4(kh4, addr + FST_KH);
                ldmx4(kl4, addr + FST_KL);
                mma_bf16(s[2 * j],     qfh[kk], kh4[0], kh4[1]);
                mma_bf16(s[2 * j],     qfh[kk], kl4[0], kl4[1]);
                mma_bf16(s[2 * j],     qfl[kk], kh4[0], kh4[1]);
                mma_bf16(s[2 * j + 1], qfh[kk], kh4[2], kh4[3]);
                mma_bf16(s[2 * j + 1], qfh[kk], kl4[2], kl4[3]);
                mma_bf16(s[2 * j + 1], qfl[kk], kh4[2], kh4[3]);
            }
        }

        const int rA = lane >> 2;
        const int tA = t0 + mw + rA, tB = tA + 8;
        #pragma unroll
        for (int nb = 0; nb < 8; nb++)
            #pragma unroll
            for (int j = 0; j < 4; j++) s[nb][j] *= 0.125f;
        if (u0 + FBN - 1 > t0 + mw) {
            #pragma unroll
            for (int nb = 0; nb < 8; nb++) {
                int u_lo = u0 + nb * 8 + (lane & 3) * 2;
                if (u_lo     > tA) s[nb][0] = -1e30f;
                if (u_lo + 1 > tA) s[nb][1] = -1e30f;
                if (u_lo     > tB) s[nb][2] = -1e30f;
                if (u_lo + 1 > tB) s[nb][3] = -1e30f;
            }
        }

        float rmA = -1e30f, rmB = -1e30f;
        #pragma unroll
        for (int nb = 0; nb < 8; nb++) {
            rmA = fmaxf(rmA, fmaxf(s[nb][0], s[nb][1]));
            rmB = fmaxf(rmB, fmaxf(s[nb][2], s[nb][3]));
        }
        rmA = fmaxf(rmA, __shfl_xor_sync(0xffffffffu, rmA, 1));
        rmA = fmaxf(rmA, __shfl_xor_sync(0xffffffffu, rmA, 2));
        rmB = fmaxf(rmB, __shfl_xor_sync(0xffffffffu, rmB, 1));
        rmB = fmaxf(rmB, __shfl_xor_sync(0xffffffffu, rmB, 2));
        float mAn = fmaxf(mA, rmA), mBn = fmaxf(mB, rmB);
        float scA = __expf(mA - mAn), scB = __expf(mB - mBn);
        mA = mAn; mB = mBn;

        float rsA = 0.f, rsB = 0.f;
        #pragma unroll
        for (int nb = 0; nb < 8; nb++) {
            s[nb][0] = __expf(s[nb][0] - mA); rsA += s[nb][0];
            s[nb][1] = __expf(s[nb][1] - mA); rsA += s[nb][1];
            s[nb][2] = __expf(s[nb][2] - mB); rsB += s[nb][2];
            s[nb][3] = __expf(s[nb][3] - mB); rsB += s[nb][3];
        }
        rsA += __shfl_xor_sync(0xffffffffu, rsA, 1);
        rsA += __shfl_xor_sync(0xffffffffu, rsA, 2);
        rsB += __shfl_xor_sync(0xffffffffu, rsB, 1);
        rsB += __shfl_xor_sync(0xffffffffu, rsB, 2);
        lA = lA * scA + rsA;
        lB = lB * scB + rsB;
        #pragma unroll
        for (int nb = 0; nb < 8; nb++) {
            o[nb][0] *= scA; o[nb][1] *= scA;
            o[nb][2] *= scB; o[nb][3] *= scB;
        }

        #pragma unroll
        for (int g = 0; g < 4; g++) {
            uint32_t pha[4], pla[4];
            {
                __nv_bfloat16 h0, h1, l0, l1;
                splitv(s[2 * g][0], h0, l0); splitv(s[2 * g][1], h1, l1);
                pha[0] = pk(h0, h1); pla[0] = pk(l0, l1);
                splitv(s[2 * g][2], h0, l0); splitv(s[2 * g][3], h1, l1);
                pha[1] = pk(h0, h1); pla[1] = pk(l0, l1);
                splitv(s[2 * g + 1][0], h0, l0); splitv(s[2 * g + 1][1], h1, l1);
                pha[2] = pk(h0, h1); pla[2] = pk(l0, l1);
                splitv(s[2 * g + 1][2], h0, l0); splitv(s[2 * g + 1][3], h1, l1);
                pha[3] = pk(h0, h1); pla[3] = pk(l0, l1);
            }
            const int vrow = g * 16 + (lane & 15);
            #pragma unroll
            for (int j = 0; j < 4; j++) {
                uint32_t addr = kb + (uint32_t)vrow * 144 +
                                (uint32_t)(j * 16 + (lane >> 4) * 8) * 2;
                uint32_t vh4[4], vl4[4];
                ldmx4t(vh4, addr + FST_VH);
                ldmx4t(vl4, addr + FST_VL);
                mma_bf16(o[2 * j],     pha, vh4[0], vh4[1]);
                mma_bf16(o[2 * j],     pha, vl4[0], vl4[1]);
                mma_bf16(o[2 * j],     pla, vh4[0], vh4[1]);
                mma_bf16(o[2 * j + 1], pha, vh4[2], vh4[3]);
                mma_bf16(o[2 * j + 1], pha, vl4[2], vl4[3]);
                mma_bf16(o[2 * j + 1], pla, vh4[2], vh4[3]);
            }
        }
        __syncthreads();
    }

    const float invA = 1.f / lA, invB = 1.f / lB;
    const int rA = lane >> 2;
    const int tA = t0 + mw + rA, tB = tA + 8;
    const int cbase = h * HS + (lane & 3) * 2;
    size_t baseA = (size_t)(b * Tt + tA) * Dd + cbase;
    size_t baseB = (size_t)(b * Tt + tB) * Dd + cbase;
    #pragma unroll
    for (int nb = 0; nb < 8; nb++) {
        o16[baseA + nb * 8]     = __float2half_rn(o[nb][0] * invA);
        o16[baseA + nb * 8 + 1] = __float2half_rn(o[nb][1] * invA);
        o16[baseB + nb * 8]     = __float2half_rn(o[nb][2] * invB);
        o16[baseB + nb * 8 + 1] = __float2half_rn(o[nb][3] * invB);
    }
}

// ---------------- embedding -------------------------------------------------
__global__ void embed_kernel(const int* __restrict__ idx,
                             const float* __restrict__ tok_emb,
                             const float* __restrict__ pos_emb) {
    int m = blockIdx.x;
    int t = m % Tt;
    int tok = idx[m];
    const float* te = tok_emb + (size_t)tok * Dd;
    const float* pe = pos_emb + (size_t)t * Dd;
    float* x = g_x + (size_t)m * Dd;
    for (int c = threadIdx.x; c < Dd; c += blockDim.x) {
        float v = te[c] + pe[c];
        x[c] = v;
        x16[(size_t)m * Dd + c] = __float2half_rn(v);
    }
}

// ---------------- fused residual add + LayerNorm (warp per row) ------------
__global__ void addln_kernel(const float* __restrict__ tmp,
                             const float* __restrict__ gamma,
                             const float* __restrict__ beta,
                             int nparts) {
    int row = blockIdx.x * (blockDim.x >> 5) + (threadIdx.x >> 5);
    int lane = threadIdx.x & 31;
    float* x = g_x + (size_t)row * Dd;
    const float* a0 = tmp + (size_t)row * Dd;

    float v[24];
    float s = 0.f;
    #pragma unroll
    for (int i = 0; i < 24; i++) {
        int c = lane + i * 32;
        float t = x[c] + a0[c];
        if (nparts > 1) t += a0[(size_t)Mm * Dd + c];
        if (nparts > 2) t += a0[(size_t)2 * Mm * Dd + c];
        v[i] = t;
        s += t;
    }
    #pragma unroll
    for (int o = 16; o > 0; o >>= 1) s += __shfl_xor_sync(0xffffffffu, s, o);
    float mean = s * (1.f / Dd);

    float q = 0.f;
    #pragma unroll
    for (int i = 0; i < 24; i++) {
        float d = v[i] - mean;
        q += d * d;
    }
    #pragma unroll
    for (int o = 16; o > 0; o >>= 1) q += __shfl_xor_sync(0xffffffffu, q, o);
    float rstd = rsqrtf(q * (1.f / Dd) + 1e-5f);

    #pragma unroll
    for (int i = 0; i < 24; i++) {
        int c = lane + i * 32;
        float ov = (v[i] - mean) * rstd * gamma[c] + beta[c];
        x[c] = ov;
        x16[(size_t)row * Dd + c] = __float2half_rn(ov);
    }
}

// ---------------- host orchestration ----------------------------------------
extern "C" void kernel_launch(void* const* d_in, const int* in_sizes, int n_in,
                              void* d_out, int out_size) {
    const int*   idx     = (const int*)  d_in[0];
    const float* tok_emb = (const float*)d_in[1];
    const float* pos_emb = (const float*)d_in[2];
    const float* wq      = (const float*)d_in[3];
    const float* wk      = (const float*)d_in[4];
    const float* wv      = (const float*)d_in[5];
    const float* wproj   = (const float*)d_in[6];
    const float* bproj   = (const float*)d_in[7];
    const float* w1      = (const float*)d_in[8];
    const float* b1      = (const float*)d_in[9];
    const float* w2      = (const float*)d_in[10];
    const float* b2      = (const float*)d_in[11];
    const float* ln1_g   = (const float*)d_in[12];
    const float* ln1_b   = (const float*)d_in[13];
    const float* ln2_g   = (const float*)d_in[14];
    const float* ln2_b   = (const float*)d_in[15];
    const float* lm_w    = (const float*)d_in[16];
    const float* lm_b    = (const float*)d_in[17];
    float* out = (float*)d_out;

    cudaFuncSetAttribute(gemm_mp<2>, cudaFuncAttributeMaxDynamicSharedMemorySize, GEMM_SMEM);
    cudaFuncSetAttribute(gemm_mp<3>, cudaFuncAttributeMaxDynamicSharedMemorySize, GEMM_SMEM);
    cudaFuncSetAttribute(flash_kernel, cudaFuncAttributeMaxDynamicSharedMemorySize, FLASH_SMEM);

    float *p_x, *p_tmp;
    cudaGetSymbolAddress((void**)&p_x,   g_x);
    cudaGetSymbolAddress((void**)&p_tmp, g_tmp);
    __nv_bfloat16 *pqh, *pql;
    cudaGetSymbolAddress((void**)&pqh, qkvp_h); cudaGetSymbolAddress((void**)&pql, qkvp_l);
    __half *pwq16h, *pwph, *pwpl, *pw1h, *pw1l, *pw2h, *pw2l, *plmh, *px16, *ph1, *po16;
    cudaGetSymbolAddress((void**)&pwq16h, wqkv16_h);
    cudaGetSymbolAddress((void**)&pwph, wpr16_h);  cudaGetSymbolAddress((void**)&pwpl, wpr16_l);
    cudaGetSymbolAddress((void**)&pw1h, w1f16_h);  cudaGetSymbolAddress((void**)&pw1l, w1f16_l);
    cudaGetSymbolAddress((void**)&pw2h, w2f16_h);  cudaGetSymbolAddress((void**)&pw2l, w2f16_l);
    cudaGetSymbolAddress((void**)&plmh, lmw16_h);
    cudaGetSymbolAddress((void**)&px16, x16);
    cudaGetSymbolAddress((void**)&ph1, h1f16);
    cudaGetSymbolAddress((void**)&po16, o16);

    conv_qkv<<<1024, 256>>>(wq, wk, wv);
    split_flat_h<<<512, 256>>>((const float4*)wproj, (uint2*)pwph, (uint2*)pwpl,
                               (unsigned)(Ll * Dd * Dd / 4));
    split_flat_h<<<1024, 256>>>((const float4*)w1, (uint2*)pw1h, (uint2*)pw1l,
                                (unsigned)(Ll * Dd * DFF / 4));
    split_flat_h<<<1024, 256>>>((const float4*)w2, (uint2*)pw2h, (uint2*)pw2l,
                                (unsigned)(Ll * DFF * Dd / 4));
    conv_lm<<<2048, 256>>>(lm_w);

    embed_kernel<<<Mm, 256>>>(idx, tok_emb, pos_emb);

    for (int l = 0; l < Ll; l++) {
        // QKV: fp16 single-pass -> bf16 pair out (for flash bf16x3 internals)
        gemm_mp<2><<<dim3(Mm / TM, NQKV / TN, 1), 256, GEMM_SMEM>>>(
            (const __nv_bfloat16*)px16, Dd,
            (const __nv_bfloat16*)(pwq16h + (size_t)l * Dd * NQKV), nullptr, NQKV,
            nullptr, nullptr, pqh, pql, NQKV, NQKV, Dd, 0, 1);
        flash_kernel<<<dim3(Tt / FBM, Bq * Hh), 128, FLASH_SMEM>>>();
        // proj: fp16 2-pass split-K=3 (A = o16, B = wproj fp16 hi/lo)
        gemm_mp<3><<<dim3(Mm / TM, Dd / TN, 3), 256, GEMM_SMEM>>>(
            (const __nv_bfloat16*)po16, Dd,
            (const __nv_bfloat16*)(pwph + (size_t)l * Dd * Dd),
            (const __nv_bfloat16*)(pwpl + (size_t)l * Dd * Dd), Dd,
            bproj + (size_t)l * Dd, p_tmp, nullptr, nullptr, Dd, Dd, Dd / 3, 0, 0);
        addln_kernel<<<Mm / 8, 256>>>(p_tmp, ln1_g + (size_t)l * Dd,
                                      ln1_b + (size_t)l * Dd, 3);
        // fc1: fp16 2-pass + relu -> fp16 single h1
        gemm_mp<3><<<dim3(Mm / TM, DFF / TN, 1), 256, GEMM_SMEM>>>(
            (const __nv_bfloat16*)px16, Dd,
            (const __nv_bfloat16*)(pw1h + (size_t)l * Dd * DFF),
            (const __nv_bfloat16*)(pw1l + (size_t)l * Dd * DFF), DFF,
            b1 + (size_t)l * DFF, nullptr, (__nv_bfloat16*)ph1, nullptr,
            DFF, DFF, Dd, 1, 2);
        // fc2: fp16 2-pass split-K=3 -> fp32 partials
        gemm_mp<3><<<dim3(Mm / TM, Dd / TN, 3), 256, GEMM_SMEM>>>(
            (const __nv_bfloat16*)ph1, DFF,
            (const __nv_bfloat16*)(pw2h + (size_t)l * DFF * Dd),
            (const __nv_bfloat16*)(pw2l + (size_t)l * DFF * Dd), Dd,
            b2 + (size_t)l * Dd, p_tmp, nullptr, nullptr, Dd, Dd, DFF / 3, 0, 0);
        addln_kernel<<<Mm / 8, 256>>>(p_tmp, ln2_g + (size_t)l * Dd,
                                      ln2_b + (size_t)l * Dd, 3);
    }

    // lm_head: fp16 single-pass (A = x16)
    gemm_mp<2><<<dim3(Mm / TM, VP / TN, 1), 256, GEMM_SMEM>>>(
        (const __nv_bfloat16*)px16, Dd,
        (const __nv_bfloat16*)plmh, nullptr, VP,
        lm_b, out, nullptr, nullptr, Vv, Vv, Dd, 0, 0);
}

// round 17
// speedup vs baseline: 2.4261x; 1.1001x over previous
#include <cuda_runtime.h>
#include <cuda_bf16.h>
#include <cuda_fp16.h>
#include <cstdint>
#include <math.h>
#include <stddef.h>

// Problem constants
#define Bq 2
#define Tt 1024
#define Dd 768
#define Hh 12
#define Ll 6
#define Vv 50257
#define VP 50304
#define HS 64
#define Mm (Bq*Tt)
#define DFF (4*Dd)
#define NQKV (3*Dd)

// GEMM tiling
#define TM 128
#define TN 128
#define BK 32
#define SA_STRIDE 40
#define SB_STRIDE 136
#define OFF_AH 0
#define OFF_AL 10240
#define OFF_BH 20480
#define OFF_BL 29184
#define STAGE_BYTES 37888
#define GEMM_SMEM (2*STAGE_BYTES)

// Flash attention tiling (fp16 single-pass)
#define FBM 64
#define FBN 64
#define FST_K 0
#define FST_V 9216
#define FSTAGE 18432
#define FLASH_SMEM (2*FSTAGE)   // 36864

// ---------------- scratch --------------------------------------------------
__device__ float g_x  [Mm*Dd];
__device__ float g_tmp[(size_t)3*Mm*Dd];     // up to 3 split-K partials

__device__ __half        x16 [Mm*Dd];
__device__ __half        o16 [Mm*Dd];
__device__ __half        h1f16[(size_t)Mm*DFF];
__device__ __half        qkv16[(size_t)Mm*NQKV];

__device__ __half        wqkv16_h[(size_t)Ll*Dd*NQKV];
__device__ __half        wpr16_h[(size_t)Ll*Dd*Dd], wpr16_l[(size_t)Ll*Dd*Dd];
__device__ __half        w1f16_h[(size_t)Ll*Dd*DFF], w1f16_l[(size_t)Ll*Dd*DFF];
__device__ __half        w2f16_h[(size_t)Ll*DFF*Dd], w2f16_l[(size_t)Ll*DFF*Dd];
__device__ __half        lmw16_h[(size_t)Dd*VP];

// ---------------- helpers --------------------------------------------------
__device__ __forceinline__ uint32_t s2u(const void* p) {
    uint32_t a;
    asm("{ .reg .u64 t; cvta.to.shared.u64 t, %1; cvt.u32.u64 %0, t; }" : "=r"(a) : "l"(p));
    return a;
}
__device__ __forceinline__ void cpa16(uint32_t dst, const void* src) {
    asm volatile("cp.async.cg.shared.global [%0], [%1], 16;" :: "r"(dst), "l"(src));
}
__device__ __forceinline__ void ldmx4(uint32_t* r, uint32_t addr) {
    asm volatile("ldmatrix.sync.aligned.m8n8.x4.shared.b16 {%0,%1,%2,%3},[%4];"
                 : "=r"(r[0]), "=r"(r[1]), "=r"(r[2]), "=r"(r[3]) : "r"(addr));
}
__device__ __forceinline__ void ldmx4t(uint32_t* r, uint32_t addr) {
    asm volatile("ldmatrix.sync.aligned.m8n8.x4.trans.shared.b16 {%0,%1,%2,%3},[%4];"
                 : "=r"(r[0]), "=r"(r[1]), "=r"(r[2]), "=r"(r[3]) : "r"(addr));
}
__device__ __forceinline__ void mma_f16(float* c, const uint32_t* a,
                                        uint32_t b0, uint32_t b1) {
    asm volatile(
        "mma.sync.aligned.m16n8k16.row.col.f32.f16.f16.f32 "
        "{%0,%1,%2,%3},{%4,%5,%6,%7},{%8,%9},{%0,%1,%2,%3};"
        : "+f"(c[0]), "+f"(c[1]), "+f"(c[2]), "+f"(c[3])
        : "r"(a[0]), "r"(a[1]), "r"(a[2]), "r"(a[3]), "r"(b0), "r"(b1));
}
__device__ __forceinline__ void splitv(float v, __nv_bfloat16& h, __nv_bfloat16& l) {
    h = __float2bfloat16_rn(v);
    l = __float2bfloat16_rn(v - __bfloat162float(h));
}
__device__ __forceinline__ uint32_t pkh(__half a, __half b) {
    return ((uint32_t)__half_as_ushort(b) << 16) | __half_as_ushort(a);
}
__device__ __forceinline__ void split4h(float4 v, uint2& h, uint2& l) {
    __half h0 = __float2half_rn(v.x), h1 = __float2half_rn(v.y);
    __half h2 = __float2half_rn(v.z), h3 = __float2half_rn(v.w);
    __half l0 = __float2half_rn(v.x - __half2float(h0));
    __half l1 = __float2half_rn(v.y - __half2float(h1));
    __half l2 = __float2half_rn(v.z - __half2float(h2));
    __half l3 = __float2half_rn(v.w - __half2float(h3));
    h = make_uint2(pkh(h0, h1), pkh(h2, h3));
    l = make_uint2(pkh(l0, l1), pkh(l2, l3));
}

// ---------------- weight conversion ----------------------------------------
__global__ void split_flat_h(const float4* __restrict__ src,
                             uint2* __restrict__ h,
                             uint2* __restrict__ l, unsigned n4) {
    unsigned stride = gridDim.x * blockDim.x;
    for (unsigned i = blockIdx.x * blockDim.x + threadIdx.x; i < n4; i += 2 * stride) {
        unsigned j = i + stride;
        float4 a = src[i];
        float4 b;
        bool has2 = (j < n4);
        if (has2) b = src[j];
        uint2 ha, la;
        split4h(a, ha, la);
        h[i] = ha; l[i] = la;
        if (has2) {
            uint2 hb, lb;
            split4h(b, hb, lb);
            h[j] = hb; l[j] = lb;
        }
    }
}

__device__ __forceinline__ void qkv_one(const float* __restrict__ wq,
                                        const float* __restrict__ wk,
                                        const float* __restrict__ wv,
                                        unsigned i4) {
    unsigned e = i4 * 4u;
    unsigned l = e / (unsigned)(Dd * NQKV);
    unsigned r = e - l * (unsigned)(Dd * NQKV);
    unsigned k = r / (unsigned)NQKV;
    unsigned n = r - k * (unsigned)NQKV;
    unsigned wsel = n / (unsigned)Dd;
    unsigned r2 = n - wsel * (unsigned)Dd;
    unsigned hh = r2 >> 6, s = r2 & 63;
    const float* base = (wsel == 0) ? wq : ((wsel == 1) ? wk : wv);
    float4 v = *(const float4*)(base + ((size_t)(l * Hh + hh) * Dd + k) * HS + s);
    uint2 hp;
    hp.x = pkh(__float2half_rn(v.x), __float2half_rn(v.y));
    hp.y = pkh(__float2half_rn(v.z), __float2half_rn(v.w));
    ((uint2*)wqkv16_h)[i4] = hp;
}
__global__ void conv_qkv(const float* __restrict__ wq,
                         const float* __restrict__ wk,
                         const float* __restrict__ wv) {
    const unsigned total4 = (unsigned)Ll * Dd * NQKV / 4u;
    unsigned stride = gridDim.x * blockDim.x;
    for (unsigned i = blockIdx.x * blockDim.x + threadIdx.x; i < total4; i += 2 * stride) {
        qkv_one(wq, wk, wv, i);
        if (i + stride < total4) qkv_one(wq, wk, wv, i + stride);
    }
}

__device__ __forceinline__ void lm_one(const float* __restrict__ lm_w, unsigned i4) {
    unsigned e = i4 * 4u;
    unsigned k = e / (unsigned)VP;
    unsigned n = e - k * (unsigned)VP;
    const float* row = lm_w + (size_t)k * Vv;
    float4 v;
    v.x = (n     < Vv) ? row[n]     : 0.f;
    v.y = (n + 1 < Vv) ? row[n + 1] : 0.f;
    v.z = (n + 2 < Vv) ? row[n + 2] : 0.f;
    v.w = (n + 3 < Vv) ? row[n + 3] : 0.f;
    uint2 hp;
    hp.x = pkh(__float2half_rn(v.x), __float2half_rn(v.y));
    hp.y = pkh(__float2half_rn(v.z), __float2half_rn(v.w));
    ((uint2*)lmw16_h)[i4] = hp;
}
__global__ void conv_lm(const float* __restrict__ lm_w) {
    const unsigned total4 = (unsigned)Dd * VP / 4u;
    unsigned stride = gridDim.x * blockDim.x;
    for (unsigned i = blockIdx.x * blockDim.x + threadIdx.x; i < total4; i += 2 * stride) {
        lm_one(lm_w, i);
        if (i + stride < total4) lm_one(lm_w, i + stride);
    }
}

// ---------------- templated tensor-core GEMM (cp.async double-buffered) ----
// MODE 2: fp16 single-pass (AhBh only).
// MODE 3: fp16 2-pass (A hi only, B hi/lo: AhBh + AhBl).
// outmode 0: fp32 C. outmode 2: fp16 single (Ch as __half*).
// Split-K: blockIdx.z = K-chunk; partials to Cf + z*Mm*ldc, bias on chunk 0.
template<int MODE>
__global__ __launch_bounds__(256, 2) void gemm_mp(
    const __nv_bfloat16* __restrict__ Ah_g, int lda,
    const __nv_bfloat16* __restrict__ Bh_g, const __nv_bfloat16* __restrict__ Bl_g,
    int ldb,
    const float* __restrict__ bias,
    float* __restrict__ Cf,
    __nv_bfloat16* __restrict__ Ch,
    int ldc, int N, int K, int relu, int outmode)
{
    extern __shared__ char smem[];
    const uint32_t sb = s2u(smem);
    const int tid = threadIdx.x;
    const int wid = tid >> 5, lane = tid & 31;
    const int m0 = blockIdx.x * TM;
    const int n0 = blockIdx.y * TN;
    const int kz = blockIdx.z;
    const int mw = (wid & 3) * 32;
    const int nw = (wid >> 2) * 64;

    Ah_g += (size_t)kz * K;
    Bh_g += (size_t)kz * K * ldb;
    if (MODE == 3) Bl_g += (size_t)kz * K * ldb;
    Cf   += (size_t)kz * Mm * ldc;
    const float* biasz = (kz == 0) ? bias : nullptr;

    float acc[2][8][4];
    #pragma unroll
    for (int a = 0; a < 2; a++)
        #pragma unroll
        for (int b = 0; b < 8; b++)
            #pragma unroll
            for (int c = 0; c < 4; c++) acc[a][b][c] = 0.f;

    auto load_stage = [&](int kc, int st) {
        uint32_t base = sb + st * STAGE_BYTES;
        #pragma unroll
        for (int i = 0; i < 2; i++) {
            int c = tid + i * 256;
            int row = c >> 2, q = c & 3;
            uint32_t d = base + OFF_AH + row * 80 + q * 16;
            cpa16(d, Ah_g + (size_t)(m0 + row) * lda + kc + q * 8);
        }
        #pragma unroll
        for (int i = 0; i < 2; i++) {
            int c = tid + i * 256;
            int row = c >> 4, q = c & 15;
            uint32_t d = base + OFF_BH + row * 272 + q * 16;
            cpa16(d, Bh_g + (size_t)(kc + row) * ldb + n0 + q * 8);
            if (MODE == 3)
                cpa16(d + (OFF_BL - OFF_BH), Bl_g + (size_t)(kc + row) * ldb + n0 + q * 8);
        }
        asm volatile("cp.async.commit_group;" ::: "memory");
    };

    const int niter = K / BK;
    load_stage(0, 0);

    for (int it = 0; it < niter; it++) {
        if (it + 1 < niter) {
            load_stage((it + 1) * BK, (it + 1) & 1);
            asm volatile("cp.async.wait_group 1;" ::: "memory");
        } else {
            asm volatile("cp.async.wait_group 0;" ::: "memory");
        }
        __syncthreads();

        const uint32_t sbase = sb + (it & 1) * STAGE_BYTES;
        #pragma unroll
        for (int kk = 0; kk < BK; kk += 16) {
            uint32_t ah[2][4];
            int arow = mw + (lane & 15);
            int acol = kk + (lane >> 4) * 8;
            #pragma unroll
            for (int mi = 0; mi < 2; mi++) {
                uint32_t off = (uint32_t)(arow + mi * 16) * (SA_STRIDE * 2) + acol * 2;
                ldmx4(ah[mi], sbase + OFF_AH + off);
            }
            int brow = kk + (lane & 15);
            int bcol = nw + (lane >> 4) * 8;
            #pragma unroll
            for (int ni = 0; ni < 4; ni++) {
                uint32_t off = (uint32_t)brow * (SB_STRIDE * 2) + (bcol + ni * 16) * 2;
                uint32_t bh[4], bl[4];
                ldmx4t(bh, sbase + OFF_BH + off);
                if (MODE == 3) ldmx4t(bl, sbase + OFF_BL + off);
                #pragma unroll
                for (int mi = 0; mi < 2; mi++) {
                    if (MODE == 3) {
                        mma_f16(acc[mi][2 * ni],     ah[mi], bh[0], bh[1]);
                        mma_f16(acc[mi][2 * ni],     ah[mi], bl[0], bl[1]);
                        mma_f16(acc[mi][2 * ni + 1], ah[mi], bh[2], bh[3]);
                        mma_f16(acc[mi][2 * ni + 1], ah[mi], bl[2], bl[3]);
                    } else {
                        mma_f16(acc[mi][2 * ni],     ah[mi], bh[0], bh[1]);
                        mma_f16(acc[mi][2 * ni + 1], ah[mi], bh[2], bh[3]);
                    }
                }
            }
        }
        __syncthreads();
    }

    float* sC = (float*)smem;
    const int r0 = mw + (lane >> 2);
    const int c0 = 2 * (lane & 3);
    #pragma unroll 1
    for (int hf = 0; hf < 2; hf++) {
        if ((wid >> 2) == hf) {
            #pragma unroll
            for (int mi = 0; mi < 2; mi++)
                #pragma unroll
                for (int ni = 0; ni < 8; ni++) {
                    int rr = (r0 + mi * 16) * 68 + ni * 8 + c0;
                    sC[rr]              = acc[mi][ni][0];
                    sC[rr + 1]          = acc[mi][ni][1];
                    sC[rr + 8 * 68]     = acc[mi][ni][2];
                    sC[rr + 8 * 68 + 1] = acc[mi][ni][3];
                }
        }
        __syncthreads();
        #pragma unroll 4
        for (int it = 0; it < 32; it++) {
            int idx = tid + it * 256;
            int r = idx >> 6, c = idx & 63;
            int col = n0 + hf * 64 + c;
            if (col < N) {
                float v = sC[r * 68 + c];
                if (biasz) v += biasz[col];
                if (relu) v = fmaxf(v, 0.f);
                if (outmode == 0) {
                    Cf[(size_t)(m0 + r) * ldc + col] = v;
                } else {
                    ((__half*)Ch)[(size_t)(m0 + r) * ldc + col] = __float2half_rn(v);
                }
            }
        }
        __syncthreads();
    }
}

// ---------------- flash attention (fp16 single-pass, causal) ---------------
// grid (16 t-tiles, B*H), 128 threads (4 warps x 16 rows).
__global__ __launch_bounds__(128) void flash_kernel() {
    extern __shared__ char smem[];
    const uint32_t sb = s2u(smem);
    const int tid = threadIdx.x, wid = tid >> 5, lane = tid & 31;
    const int bh = blockIdx.y;
    const int b = bh / Hh, h = bh % Hh;
    const int t0 = (int)(gridDim.x - 1 - blockIdx.x) * FBM;
    const int mw = wid * 16;

    const size_t rowbase = (size_t)(b * Tt) * NQKV + h * HS;

    // ---- load Q tile [64][64] fp16 into stage0 region ----
    #pragma unroll
    for (int i = 0; i < 4; i++) {
        int c = tid + i * 128;
        int row = c >> 3, q = c & 7;
        size_t g = rowbase + (size_t)(t0 + row) * NQKV + q * 8;
        cpa16(sb + row * 144 + q * 16, qkv16 + g);
    }
    asm volatile("cp.async.commit_group;" ::: "memory");
    asm volatile("cp.async.wait_group 0;" ::: "memory");
    __syncthreads();

    uint32_t qf[4][4];
    {
        int arow = mw + (lane & 15);
        #pragma unroll
        for (int kk = 0; kk < 4; kk++) {
            int acol = kk * 16 + (lane >> 4) * 8;
            ldmx4(qf[kk], sb + (uint32_t)arow * 144 + acol * 2);
        }
    }
    __syncthreads();

    auto kv_issue = [&](int u0, int st) {
        uint32_t base = sb + st * FSTAGE;
        #pragma unroll
        for (int i = 0; i < 4; i++) {
            int c = tid + i * 128;
            int row = c >> 3, q = c & 7;
            size_t g = rowbase + (size_t)(u0 + row) * NQKV + q * 8;
            uint32_t d = base + row * 144 + q * 16;
            cpa16(d + FST_K, qkv16 + g + Dd);
            cpa16(d + FST_V, qkv16 + g + 2 * Dd);
        }
        asm volatile("cp.async.commit_group;" ::: "memory");
    };

    float o[8][4];
    #pragma unroll
    for (int i = 0; i < 8; i++)
        #pragma unroll
        for (int j = 0; j < 4; j++) o[i][j] = 0.f;
    float mA = -1e30f, mB = -1e30f, lA = 0.f, lB = 0.f;

    const int nt = t0 / FBN + 1;
    kv_issue(0, 1);

    for (int it = 0; it < nt; it++) {
        const int u0 = it * FBN;
        if (it + 1 < nt) {
            kv_issue((it + 1) * FBN, it & 1);
            asm volatile("cp.async.wait_group 1;" ::: "memory");
        } else {
            asm volatile("cp.async.wait_group 0;" ::: "memory");
        }
        __syncthreads();
        const uint32_t kb = sb + ((it + 1) & 1) * FSTAGE;

        // ---- S = Q K^T (single-pass fp16) ----
        float s[8][4];
        #pragma unroll
        for (int i = 0; i < 8; i++)
            #pragma unroll
            for (int j = 0; j < 4; j++) s[i][j] = 0.f;

        const int bn = ((lane >> 4) << 3) + (lane & 7);
        const int bk = ((lane >> 3) & 1) * 8;
        #pragma unroll
        for (int kk = 0; kk < 4; kk++) {
            #pragma unroll
            for (int j = 0; j < 4; j++) {
                uint32_t addr = kb + FST_K + (uint32_t)(j * 16 + bn) * 144 + (kk * 16 + bk) * 2;
                uint32_t k4[4];
                ldmx4(k4, addr);
                mma_f16(s[2 * j],     qf[kk], k4[0], k4[1]);
                mma_f16(s[2 * j + 1], qf[kk], k4[2], k4[3]);
            }
        }

        // ---- scale + causal mask ----
        const int rA = lane >> 2;
        const int tA = t0 + mw + rA, tB = tA + 8;
        #pragma unroll
        for (int nb = 0; nb < 8; nb++)
            #pragma unroll
            for (int j = 0; j < 4; j++) s[nb][j] *= 0.125f;
        if (u0 + FBN - 1 > t0 + mw) {
            #pragma unroll
            for (int nb = 0; nb < 8; nb++) {
                int u_lo = u0 + nb * 8 + (lane & 3) * 2;
                if (u_lo     > tA) s[nb][0] = -1e30f;
                if (u_lo + 1 > tA) s[nb][1] = -1e30f;
                if (u_lo     > tB) s[nb][2] = -1e30f;
                if (u_lo + 1 > tB) s[nb][3] = -1e30f;
            }
        }

        // ---- online softmax ----
        float rmA = -1e30f, rmB = -1e30f;
        #pragma unroll
        for (int nb = 0; nb < 8; nb++) {
            rmA = fmaxf(rmA, fmaxf(s[nb][0], s[nb][1]));
            rmB = fmaxf(rmB, fmaxf(s[nb][2], s[nb][3]));
        }
        rmA = fmaxf(rmA, __shfl_xor_sync(0xffffffffu, rmA, 1));
        rmA = fmaxf(rmA, __shfl_xor_sync(0xffffffffu, rmA, 2));
        rmB = fmaxf(rmB, __shfl_xor_sync(0xffffffffu, rmB, 1));
        rmB = fmaxf(rmB, __shfl_xor_sync(0xffffffffu, rmB, 2));
        float mAn = fmaxf(mA, rmA), mBn = fmaxf(mB, rmB);
        float scA = __expf(mA - mAn), scB = __expf(mB - mBn);
        mA = mAn; mB = mBn;

        float rsA = 0.f, rsB = 0.f;
        #pragma unroll
        for (int nb = 0; nb < 8; nb++) {
            s[nb][0] = __expf(s[nb][0] - mA); rsA += s[nb][0];
            s[nb][1] = __expf(s[nb][1] - mA); rsA += s[nb][1];
            s[nb][2] = __expf(s[nb][2] - mB); rsB += s[nb][2];
            s[nb][3] = __expf(s[nb][3] - mB); rsB += s[nb][3];
        }
        rsA += __shfl_xor_sync(0xffffffffu, rsA, 1);
        rsA += __shfl_xor_sync(0xffffffffu, rsA, 2);
        rsB += __shfl_xor_sync(0xffffffffu, rsB, 1);
        rsB += __shfl_xor_sync(0xffffffffu, rsB, 2);
        lA = lA * scA + rsA;
        lB = lB * scB + rsB;
        #pragma unroll
        for (int nb = 0; nb < 8; nb++) {
            o[nb][0] *= scA; o[nb][1] *= scA;
            o[nb][2] *= scB; o[nb][3] *= scB;
        }

        // ---- O += P V (single-pass fp16) ----
        #pragma unroll
        for (int g = 0; g < 4; g++) {
            uint32_t pa[4];
            pa[0] = pkh(__float2half_rn(s[2 * g][0]),     __float2half_rn(s[2 * g][1]));
            pa[1] = pkh(__float2half_rn(s[2 * g][2]),     __float2half_rn(s[2 * g][3]));
            pa[2] = pkh(__float2half_rn(s[2 * g + 1][0]), __float2half_rn(s[2 * g + 1][1]));
            pa[3] = pkh(__float2half_rn(s[2 * g + 1][2]), __float2half_rn(s[2 * g + 1][3]));
            const int vrow = g * 16 + (lane & 15);
            #pragma unroll
            for (int j = 0; j < 4; j++) {
                uint32_t addr = kb + FST_V + (uint32_t)vrow * 144 +
                                (uint32_t)(j * 16 + (lane >> 4) * 8) * 2;
                uint32_t v4[4];
                ldmx4t(v4, addr);
                mma_f16(o[2 * j],     pa, v4[0], v4[1]);
                mma_f16(o[2 * j + 1], pa, v4[2], v4[3]);
            }
        }
        __syncthreads();
    }

    const float invA = 1.f / lA, invB = 1.f / lB;
    const int rA = lane >> 2;
    const int tA = t0 + mw + rA, tB = tA + 8;
    const int cbase = h * HS + (lane & 3) * 2;
    size_t baseA = (size_t)(b * Tt + tA) * Dd + cbase;
    size_t baseB = (size_t)(b * Tt + tB) * Dd + cbase;
    #pragma unroll
    for (int nb = 0; nb < 8; nb++) {
        o16[baseA + nb * 8]     = __float2half_rn(o[nb][0] * invA);
        o16[baseA + nb * 8 + 1] = __float2half_rn(o[nb][1] * invA);
        o16[baseB + nb * 8]     = __float2half_rn(o[nb][2] * invB);
        o16[baseB + nb * 8 + 1] = __float2half_rn(o[nb][3] * invB);
    }
}

// ---------------- embedding -------------------------------------------------
__global__ void embed_kernel(const int* __restrict__ idx,
                             const float* __restrict__ tok_emb,
                             const float* __restrict__ pos_emb) {
    int m = blockIdx.x;
    int t = m % Tt;
    int tok = idx[m];
    const float* te = tok_emb + (size_t)tok * Dd;
    const float* pe = pos_emb + (size_t)t * Dd;
    float* x = g_x + (size_t)m * Dd;
    for (int c = threadIdx.x; c < Dd; c += blockDim.x) {
        float v = te[c] + pe[c];
        x[c] = v;
        x16[(size_t)m * Dd + c] = __float2half_rn(v);
    }
}

// ---------------- fused residual add + LayerNorm (warp per row) ------------
__global__ void addln_kernel(const float* __restrict__ tmp,
                             const float* __restrict__ gamma,
                             const float* __restrict__ beta,
                             int nparts) {
    int row = blockIdx.x * (blockDim.x >> 5) + (threadIdx.x >> 5);
    int lane = threadIdx.x & 31;
    float* x = g_x + (size_t)row * Dd;
    const float* a0 = tmp + (size_t)row * Dd;

    float v[24];
    float s = 0.f;
    #pragma unroll
    for (int i = 0; i < 24; i++) {
        int c = lane + i * 32;
        float t = x[c] + a0[c];
        if (nparts > 1) t += a0[(size_t)Mm * Dd + c];
        if (nparts > 2) t += a0[(size_t)2 * Mm * Dd + c];
        v[i] = t;
        s += t;
    }
    #pragma unroll
    for (int o = 16; o > 0; o >>= 1) s += __shfl_xor_sync(0xffffffffu, s, o);
    float mean = s * (1.f / Dd);

    float q = 0.f;
    #pragma unroll
    for (int i = 0; i < 24; i++) {
        float d = v[i] - mean;
        q += d * d;
    }
    #pragma unroll
    for (int o = 16; o > 0; o >>= 1) q += __shfl_xor_sync(0xffffffffu, q, o);
    float rstd = rsqrtf(q * (1.f / Dd) + 1e-5f);

    #pragma unroll
    for (int i = 0; i < 24; i++) {
        int c = lane + i * 32;
        float ov = (v[i] - mean) * rstd * gamma[c] + beta[c];
        x[c] = ov;
        x16[(size_t)row * Dd + c] = __float2half_rn(ov);
    }
}

// ---------------- host orchestration ----------------------------------------
extern "C" void kernel_launch(void* const* d_in, const int* in_sizes, int n_in,
                              void* d_out, int out_size) {
    const int*   idx     = (const int*)  d_in[0];
    const float* tok_emb = (const float*)d_in[1];
    const float* pos_emb = (const float*)d_in[2];
    const float* wq      = (const float*)d_in[3];
    const float* wk      = (const float*)d_in[4];
    const float* wv      = (const float*)d_in[5];
    const float* wproj   = (const float*)d_in[6];
    const float* bproj   = (const float*)d_in[7];
    const float* w1      = (const float*)d_in[8];
    const float* b1      = (const float*)d_in[9];
    const float* w2      = (const float*)d_in[10];
    const float* b2      = (const float*)d_in[11];
    const float* ln1_g   = (const float*)d_in[12];
    const float* ln1_b   = (const float*)d_in[13];
    const float* ln2_g   = (const float*)d_in[14];
    const float* ln2_b   = (const float*)d_in[15];
    const float* lm_w    = (const float*)d_in[16];
    const float* lm_b    = (const float*)d_in[17];
    float* out = (float*)d_out;

    cudaFuncSetAttribute(gemm_mp<2>, cudaFuncAttributeMaxDynamicSharedMemorySize, GEMM_SMEM);
    cudaFuncSetAttribute(gemm_mp<3>, cudaFuncAttributeMaxDynamicSharedMemorySize, GEMM_SMEM);
    cudaFuncSetAttribute(flash_kernel, cudaFuncAttributeMaxDynamicSharedMemorySize, FLASH_SMEM);

    float *p_x, *p_tmp;
    cudaGetSymbolAddress((void**)&p_x,   g_x);
    cudaGetSymbolAddress((void**)&p_tmp, g_tmp);
    __half *pwq16h, *pwph, *pwpl, *pw1h, *pw1l, *pw2h, *pw2l, *plmh;
    __half *px16, *ph1, *po16, *pqkv;
    cudaGetSymbolAddress((void**)&pwq16h, wqkv16_h);
    cudaGetSymbolAddress((void**)&pwph, wpr16_h);  cudaGetSymbolAddress((void**)&pwpl, wpr16_l);
    cudaGetSymbolAddress((void**)&pw1h, w1f16_h);  cudaGetSymbolAddress((void**)&pw1l, w1f16_l);
    cudaGetSymbolAddress((void**)&pw2h, w2f16_h);  cudaGetSymbolAddress((void**)&pw2l, w2f16_l);
    cudaGetSymbolAddress((void**)&plmh, lmw16_h);
    cudaGetSymbolAddress((void**)&px16, x16);
    cudaGetSymbolAddress((void**)&ph1, h1f16);
    cudaGetSymbolAddress((void**)&po16, o16);
    cudaGetSymbolAddress((void**)&pqkv, qkv16);

    conv_qkv<<<1024, 256>>>(wq, wk, wv);
    split_flat_h<<<512, 256>>>((const float4*)wproj, (uint2*)pwph, (uint2*)pwpl,
                               (unsigned)(Ll * Dd * Dd / 4));
    split_flat_h<<<1024, 256>>>((const float4*)w1, (uint2*)pw1h, (uint2*)pw1l,
                                (unsigned)(Ll * Dd * DFF / 4));
    split_flat_h<<<1024, 256>>>((const float4*)w2, (uint2*)pw2h, (uint2*)pw2l,
                                (unsigned)(Ll * DFF * Dd / 4));
    conv_lm<<<2048, 256>>>(lm_w);

    embed_kernel<<<Mm, 256>>>(idx, tok_emb, pos_emb);

    for (int l = 0; l < Ll; l++) {
        // QKV: fp16 single-pass -> fp16 single out
        gemm_mp<2><<<dim3(Mm / TM, NQKV / TN, 1), 256, GEMM_SMEM>>>(
            (const __nv_bfloat16*)px16, Dd,
            (const __nv_bfloat16*)(pwq16h + (size_t)l * Dd * NQKV), nullptr, NQKV,
            nullptr, nullptr, (__nv_bfloat16*)pqkv, NQKV, NQKV, Dd, 0, 2);
        flash_kernel<<<dim3(Tt / FBM, Bq * Hh), 128, FLASH_SMEM>>>();
        // proj: fp16 2-pass split-K=3
        gemm_mp<3><<<dim3(Mm / TM, Dd / TN, 3), 256, GEMM_SMEM>>>(
            (const __nv_bfloat16*)po16, Dd,
            (const __nv_bfloat16*)(pwph + (size_t)l * Dd * Dd),
            (const __nv_bfloat16*)(pwpl + (size_t)l * Dd * Dd), Dd,
            bproj + (size_t)l * Dd, p_tmp, nullptr, Dd, Dd, Dd / 3, 0, 0);
        addln_kernel<<<Mm / 8, 256>>>(p_tmp, ln1_g + (size_t)l * Dd,
                                      ln1_b + (size_t)l * Dd, 3);
        // fc1: fp16 2-pass + relu -> fp16 single h1
        gemm_mp<3><<<dim3(Mm / TM, DFF / TN, 1), 256, GEMM_SMEM>>>(
            (const __nv_bfloat16*)px16, Dd,
            (const __nv_bfloat16*)(pw1h + (size_t)l * Dd * DFF),
            (const __nv_bfloat16*)(pw1l + (size_t)l * Dd * DFF), DFF,
            b1 + (size_t)l * DFF, nullptr, (__nv_bfloat16*)ph1,
            DFF, DFF, Dd, 1, 2);
        // fc2: fp16 2-pass split-K=3 -> fp32 partials
        gemm_mp<3><<<dim3(Mm / TM, Dd / TN, 3), 256, GEMM_SMEM>>>(
            (const __nv_bfloat16*)ph1, DFF,
            (const __nv_bfloat16*)(pw2h + (size_t)l * DFF * Dd),
            (const __nv_bfloat16*)(pw2l + (size_t)l * DFF * Dd), Dd,
            b2 + (size_t)l * Dd, p_tmp, nullptr, Dd, Dd, DFF / 3, 0, 0);
        addln_kernel<<<Mm / 8, 256>>>(p_tmp, ln2_g + (size_t)l * Dd,
                                      ln2_b + (size_t)l * Dd, 3);
    }

    // lm_head: fp16 single-pass (A = x16)
    gemm_mp<2><<<dim3(Mm / TM, VP / TN, 1), 256, GEMM_SMEM>>>(
        (const __nv_bfloat16*)px16, Dd,
        (const __nv_bfloat16*)plmh, nullptr, VP,
        lm_b, out, nullptr, Vv, Vv, Dd, 0, 0);
}